// round 1
// baseline (speedup 1.0000x reference)
#include <cuda_runtime.h>
#include <math.h>

// Problem constants
#define B_  8
#define N_  1024
#define C_  384
#define H_  12
#define HD_ 32
#define HID_ 768
#define NH_ 32
#define M_  (B_ * N_)          // 8192 rows for all GEMMs

__device__ __forceinline__ float gelu_f(float v) {
    return 0.5f * v * (1.0f + erff(v * 0.70710678118654752f));
}

// ---------------- scratch (device globals: allocation-free) ----------------
__device__ float g_ln2[M_ * C_];
__device__ float g_h1 [M_ * HID_];
__device__ float g_h2 [M_ * HID_];
__device__ float g_x1 [M_ * C_];
__device__ float g_ln1[M_ * C_];
__device__ float g_qkv[M_ * 3 * C_];
__device__ float g_att[M_ * C_];

// ---------------- LayerNorm: one block per row of 384 ----------------
__global__ __launch_bounds__(128) void ln_kernel(
    const float* __restrict__ in, const float* __restrict__ g,
    const float* __restrict__ bta, float* __restrict__ out)
{
    const int row = blockIdx.x;
    const int t = threadIdx.x;
    const float* xr = in + (size_t)row * C_;
    float v0 = xr[t], v1 = xr[t + 128], v2 = xr[t + 256];
    float s = v0 + v1 + v2;
    __shared__ float red[4], red2[4];
    #pragma unroll
    for (int o = 16; o; o >>= 1) s += __shfl_xor_sync(0xffffffffu, s, o);
    if ((t & 31) == 0) red[t >> 5] = s;
    __syncthreads();
    const float mean = (red[0] + red[1] + red[2] + red[3]) * (1.0f / C_);
    const float d0 = v0 - mean, d1 = v1 - mean, d2 = v2 - mean;
    float q = d0 * d0 + d1 * d1 + d2 * d2;
    #pragma unroll
    for (int o = 16; o; o >>= 1) q += __shfl_xor_sync(0xffffffffu, q, o);
    if ((t & 31) == 0) red2[t >> 5] = q;
    __syncthreads();
    const float var = (red2[0] + red2[1] + red2[2] + red2[3]) * (1.0f / C_);
    const float inv = rsqrtf(var + 1e-5f);
    float* orow = out + (size_t)row * C_;
    orow[t]       = d0 * inv * g[t]       + bta[t];
    orow[t + 128] = d1 * inv * g[t + 128] + bta[t + 128];
    orow[t + 256] = d2 * inv * g[t + 256] + bta[t + 256];
}

// ---------------- SGEMM: C[M,Nd] = act(A[M,K] @ W[Nd,K]^T + bias) (+res) ----
// 128x128 tile, BK=8, 256 threads, 8x8 per thread.
template<bool GELU, bool HASB, bool RES>
__global__ __launch_bounds__(256) void sgemm_kernel(
    const float* __restrict__ A, const float* __restrict__ W,
    const float* __restrict__ bias, const float* __restrict__ res,
    float* __restrict__ C, int M, int Nd, int K)
{
    __shared__ float As[8][128];
    __shared__ float Bs[8][128];
    const int tid = threadIdx.x;
    const int bm = blockIdx.y * 128;
    const int bn = blockIdx.x * 128;
    const int ldRow = tid >> 1;
    const int ldCol = (tid & 1) << 2;
    const float* Ap = A + (size_t)(bm + ldRow) * K + ldCol;
    const float* Wp = W + (size_t)(bn + ldRow) * K + ldCol;
    const int ty = tid >> 4;
    const int tx = tid & 15;
    float acc[8][8] = {};
    for (int k0 = 0; k0 < K; k0 += 8) {
        float4 a4 = *(const float4*)(Ap + k0);
        float4 w4 = *(const float4*)(Wp + k0);
        As[ldCol + 0][ldRow] = a4.x; As[ldCol + 1][ldRow] = a4.y;
        As[ldCol + 2][ldRow] = a4.z; As[ldCol + 3][ldRow] = a4.w;
        Bs[ldCol + 0][ldRow] = w4.x; Bs[ldCol + 1][ldRow] = w4.y;
        Bs[ldCol + 2][ldRow] = w4.z; Bs[ldCol + 3][ldRow] = w4.w;
        __syncthreads();
        #pragma unroll
        for (int k = 0; k < 8; ++k) {
            float ar[8], br[8];
            *(float4*)&ar[0] = *(const float4*)&As[k][ty * 8];
            *(float4*)&ar[4] = *(const float4*)&As[k][ty * 8 + 4];
            *(float4*)&br[0] = *(const float4*)&Bs[k][tx * 8];
            *(float4*)&br[4] = *(const float4*)&Bs[k][tx * 8 + 4];
            #pragma unroll
            for (int i = 0; i < 8; i++)
                #pragma unroll
                for (int j = 0; j < 8; j++)
                    acc[i][j] += ar[i] * br[j];
        }
        __syncthreads();
    }
    #pragma unroll
    for (int i = 0; i < 8; i++) {
        const int m = bm + ty * 8 + i;
        float* Cr = C + (size_t)m * Nd + bn + tx * 8;
        const float* Rr = RES ? (res + (size_t)m * Nd + bn + tx * 8) : nullptr;
        float o[8];
        #pragma unroll
        for (int j = 0; j < 8; j++) {
            float v = acc[i][j];
            if (HASB) v += bias[bn + tx * 8 + j];
            if (GELU) v = gelu_f(v);
            if (RES)  v += Rr[j];
            o[j] = v;
        }
        *(float4*)&Cr[0] = *(float4*)&o[0];
        *(float4*)&Cr[4] = *(float4*)&o[4];
    }
}

// ---------------- depthwise 3x3 dilation-2 conv + GELU ----------------
// layout: (b, n=y*32+x, ch) channel-last -> coalesced across ch
__global__ __launch_bounds__(256) void dwconv_kernel(
    const float* __restrict__ h1, float* __restrict__ h2,
    const float* __restrict__ w, const float* __restrict__ bias)
{
    const int n = blockIdx.x;   // 0..1023
    const int b = blockIdx.y;   // 0..7
    const int y = n >> 5, x = n & 31;
    const size_t base = (size_t)b * N_ * HID_;
    for (int c = threadIdx.x; c < HID_; c += 256) {
        float acc = bias[c];
        #pragma unroll
        for (int i = 0; i < 3; i++) {
            const int yy = y + 2 * i - 2;
            if (yy < 0 || yy > 31) continue;
            #pragma unroll
            for (int j = 0; j < 3; j++) {
                const int xx = x + 2 * j - 2;
                if (xx < 0 || xx > 31) continue;
                acc += w[c * 9 + i * 3 + j] *
                       h1[base + (size_t)(yy * 32 + xx) * HID_ + c];
            }
        }
        h2[base + (size_t)n * HID_ + c] = gelu_f(acc);
    }
}

// ---------------- flash attention with fused rel-pos + global bias ----------
// grid (N/128, H, B); 128 threads; thread t owns query row q0+t.
__global__ __launch_bounds__(128) void attn_kernel(
    const float* __restrict__ qkv, float* __restrict__ att,
    const int* __restrict__ rel_index, const float* __restrict__ rel_table,
    const float* __restrict__ gb)
{
    const int q0 = blockIdx.x * 128;
    const int h  = blockIdx.y;
    const int b  = blockIdx.z;
    const int t  = threadIdx.x;
    __shared__ float Ks[32][32];
    __shared__ float Vs[32][32];
    __shared__ float Sc[128][32];   // bias->scores, bank-swizzled (j+q)&31

    const int qrow = q0 + t;
    const size_t qkvbase = (size_t)b * N_ * 1152;
    const float SCALE = 0.17677669529663687f;  // HD^-0.5

    float qr[32], o[32];
    #pragma unroll
    for (int d = 0; d < 32; d++) {
        qr[d] = qkv[qkvbase + (size_t)qrow * 1152 + h * 32 + d] * SCALE;
        o[d] = 0.0f;
    }
    float mrun = -1e30f, ssum = 0.0f;

    for (int kt = 0; kt < N_; kt += 32) {
        // K/V tiles: 32x32 each, 1024 elems -> 8 per thread, coalesced over d
        #pragma unroll
        for (int r = 0; r < 8; r++) {
            const int idx = t + r * 128;
            const int krow = idx >> 5, d = idx & 31;
            const size_t src = qkvbase + (size_t)(kt + krow) * 1152 + h * 32 + d;
            Ks[krow][d] = qkv[src + 384];
            Vs[krow][d] = qkv[src + 768];
        }
        // bias tile 128x32, coalesced over k; swizzled store
        #pragma unroll
        for (int r = 0; r < 32; r++) {
            const int idx = t + r * 128;
            const int qq = idx >> 5, kk = idx & 31;
            const int gq = q0 + qq, gk = kt + kk;
            const int ri = rel_index[(size_t)gq * N_ + gk];
            Sc[qq][(kk + qq) & 31] =
                rel_table[ri * H_ + h] + gb[(size_t)gq * 1024 + gk];
        }
        __syncthreads();

        float mt = mrun;
        #pragma unroll
        for (int j = 0; j < 32; j++) {
            float s = Sc[t][(j + t) & 31];
            #pragma unroll
            for (int d = 0; d < 32; d++) s += qr[d] * Ks[j][d];
            Sc[t][(j + t) & 31] = s;
            mt = fmaxf(mt, s);
        }
        const float corr = __expf(mrun - mt);
        ssum *= corr;
        #pragma unroll
        for (int d = 0; d < 32; d++) o[d] *= corr;
        #pragma unroll
        for (int j = 0; j < 32; j++) {
            const float p = __expf(Sc[t][(j + t) & 31] - mt);
            ssum += p;
            #pragma unroll
            for (int d = 0; d < 32; d++) o[d] += p * Vs[j][d];
        }
        mrun = mt;
        __syncthreads();
    }
    const float inv = 1.0f / ssum;
    const size_t obase = ((size_t)b * N_ + qrow) * C_ + h * HD_;
    #pragma unroll
    for (int d = 0; d < 32; d++) att[obase + d] = o[d] * inv;
}

// ---------------- launch ----------------
extern "C" void kernel_launch(void* const* d_in, const int* in_sizes, int n_in,
                              void* d_out, int out_size)
{
    // metadata may or may not materialize the two python-int scalars n_h, n_w
    const int base = (n_in >= 19) ? 2 : 0;
    const float* x         = (const float*)d_in[0];
    const int*   rel_index = (const int*)  d_in[1 + base];
    const float* ln1_g     = (const float*)d_in[2 + base];
    const float* ln1_b     = (const float*)d_in[3 + base];
    const float* w_qkv     = (const float*)d_in[4 + base];
    const float* w_proj    = (const float*)d_in[5 + base];
    const float* b_proj    = (const float*)d_in[6 + base];
    const float* rel_table = (const float*)d_in[7 + base];
    const float* gbias     = (const float*)d_in[8 + base];
    const float* ln2_g     = (const float*)d_in[9 + base];
    const float* ln2_b     = (const float*)d_in[10 + base];
    const float* w_pw1     = (const float*)d_in[11 + base];
    const float* b_pw1     = (const float*)d_in[12 + base];
    const float* w_dw      = (const float*)d_in[13 + base];
    const float* b_dw      = (const float*)d_in[14 + base];
    const float* w_pw2     = (const float*)d_in[15 + base];
    const float* b_pw2     = (const float*)d_in[16 + base];
    float* out = (float*)d_out;

    void *p_ln2, *p_h1, *p_h2, *p_x1, *p_ln1, *p_qkv, *p_att;
    cudaGetSymbolAddress(&p_ln2, g_ln2);
    cudaGetSymbolAddress(&p_h1,  g_h1);
    cudaGetSymbolAddress(&p_h2,  g_h2);
    cudaGetSymbolAddress(&p_x1,  g_x1);
    cudaGetSymbolAddress(&p_ln1, g_ln1);
    cudaGetSymbolAddress(&p_qkv, g_qkv);
    cudaGetSymbolAddress(&p_att, g_att);

    // 1) x1 = x + MLP(LN2(x))
    ln_kernel<<<M_, 128>>>(x, ln2_g, ln2_b, (float*)p_ln2);
    sgemm_kernel<true, true, false><<<dim3(HID_ / 128, M_ / 128), 256>>>(
        (const float*)p_ln2, w_pw1, b_pw1, nullptr, (float*)p_h1, M_, HID_, C_);
    dwconv_kernel<<<dim3(N_, B_), 256>>>(
        (const float*)p_h1, (float*)p_h2, w_dw, b_dw);
    sgemm_kernel<false, true, true><<<dim3(C_ / 128, M_ / 128), 256>>>(
        (const float*)p_h2, w_pw2, b_pw2, x, (float*)p_x1, M_, C_, HID_);

    // 2) out = x1 + Attn(LN1(x1))
    ln_kernel<<<M_, 128>>>((const float*)p_x1, ln1_g, ln1_b, (float*)p_ln1);
    sgemm_kernel<false, false, false><<<dim3(1152 / 128, M_ / 128), 256>>>(
        (const float*)p_ln1, w_qkv, nullptr, nullptr, (float*)p_qkv, M_, 1152, C_);
    attn_kernel<<<dim3(N_ / 128, H_, B_), 128>>>(
        (const float*)p_qkv, (float*)p_att, rel_index, rel_table, gbias);
    sgemm_kernel<false, true, true><<<dim3(C_ / 128, M_ / 128), 256>>>(
        (const float*)p_att, w_proj, b_proj, (const float*)p_x1, out, M_, C_, C_);
}

// round 2
// speedup vs baseline: 1.8039x; 1.8039x over previous
#include <cuda_runtime.h>
#include <math.h>
#include <stdint.h>

// Problem constants
#define B_  8
#define N_  1024
#define C_  384
#define H_  12
#define HD_ 32
#define HID_ 768
#define M_  (B_ * N_)          // 8192 rows for all GEMMs
#define NREL_ 3969             // (2*32-1)^2

__device__ __forceinline__ float gelu_f(float v) {
    return 0.5f * v * (1.0f + erff(v * 0.70710678118654752f));
}

__device__ __forceinline__ uint32_t f2tf(float x) {
    uint32_t r;
    asm("cvt.rna.tf32.f32 %0, %1;" : "=r"(r) : "f"(x));
    return r;
}

__device__ __forceinline__ void mma_tf32(float* c, const uint32_t* a, const uint32_t* b) {
    asm volatile(
        "mma.sync.aligned.m16n8k8.row.col.f32.tf32.tf32.f32 "
        "{%0,%1,%2,%3}, {%4,%5,%6,%7}, {%8,%9}, {%0,%1,%2,%3};"
        : "+f"(c[0]), "+f"(c[1]), "+f"(c[2]), "+f"(c[3])
        : "r"(a[0]), "r"(a[1]), "r"(a[2]), "r"(a[3]), "r"(b[0]), "r"(b[1]));
}

// ---------------- scratch (device globals: allocation-free) ----------------
__device__ float g_ln2[M_ * C_];
__device__ float g_h1 [M_ * HID_];
__device__ float g_h2 [M_ * HID_];
__device__ float g_x1 [M_ * C_];
__device__ float g_ln1[M_ * C_];
__device__ float g_qkv[M_ * 3 * C_];
__device__ float g_att[M_ * C_];
__device__ float g_bias[H_ * N_ * N_];   // 48MB precomputed rel+global bias

// ---------------- LayerNorm: one block per row of 384 ----------------
__global__ __launch_bounds__(128) void ln_kernel(
    const float* __restrict__ in, const float* __restrict__ g,
    const float* __restrict__ bta, float* __restrict__ out)
{
    const int row = blockIdx.x;
    const int t = threadIdx.x;
    const float* xr = in + (size_t)row * C_;
    float v0 = xr[t], v1 = xr[t + 128], v2 = xr[t + 256];
    float s = v0 + v1 + v2;
    __shared__ float red[4], red2[4];
    #pragma unroll
    for (int o = 16; o; o >>= 1) s += __shfl_xor_sync(0xffffffffu, s, o);
    if ((t & 31) == 0) red[t >> 5] = s;
    __syncthreads();
    const float mean = (red[0] + red[1] + red[2] + red[3]) * (1.0f / C_);
    const float d0 = v0 - mean, d1 = v1 - mean, d2 = v2 - mean;
    float q = d0 * d0 + d1 * d1 + d2 * d2;
    #pragma unroll
    for (int o = 16; o; o >>= 1) q += __shfl_xor_sync(0xffffffffu, q, o);
    if ((t & 31) == 0) red2[t >> 5] = q;
    __syncthreads();
    const float var = (red2[0] + red2[1] + red2[2] + red2[3]) * (1.0f / C_);
    const float inv = rsqrtf(var + 1e-5f);
    float* orow = out + (size_t)row * C_;
    orow[t]       = d0 * inv * g[t]       + bta[t];
    orow[t + 128] = d1 * inv * g[t + 128] + bta[t + 128];
    orow[t + 256] = d2 * inv * g[t + 256] + bta[t + 256];
}

// ---------------- tf32 tensor-core GEMM -------------------------------------
// C[M,Nd] = act(A[M,K] @ W[Nd,K]^T + bias) (+res)
// CTA tile 128x128, BK=32, 256 thr (8 warps, 2x4), warp tile 64x32.
// smem padded stride 36 floats -> conflict-free fragment LDS.
#define SMS 36
template<bool GELU, bool HASB, bool RES>
__global__ __launch_bounds__(256) void mma_gemm(
    const float* __restrict__ A, const float* __restrict__ W,
    const float* __restrict__ bias, const float* __restrict__ res,
    float* __restrict__ C, int M, int Nd, int K)
{
    __shared__ float As[128 * SMS];
    __shared__ float Bs[128 * SMS];
    const int tid  = threadIdx.x;
    const int lane = tid & 31, warp = tid >> 5;
    const int wm = warp >> 2, wn = warp & 3;            // 2 x 4 warps
    const int bm = blockIdx.y * 128, bn = blockIdx.x * 128;

    // global loader: each thread: 4 float4 per matrix per k-tile
    const int lrow = tid >> 3;    // 0..31
    const int lc4  = tid & 7;     // 0..7 (float4 col)
    const float* Ag = A + (size_t)(bm + lrow) * K + lc4 * 4;
    const float* Wg = W + (size_t)(bn + lrow) * K + lc4 * 4;

    float4 pa[4], pb[4];
    #pragma unroll
    for (int i = 0; i < 4; i++) {
        pa[i] = *(const float4*)(Ag + (size_t)(i * 32) * K);
        pb[i] = *(const float4*)(Wg + (size_t)(i * 32) * K);
    }

    float acc[4][4][4] = {};   // [mt][nt][reg]
    const int ntiles = K >> 5;

    for (int kt = 0; kt < ntiles; kt++) {
        // store prefetched tile with round-to-nearest tf32
        #pragma unroll
        for (int i = 0; i < 4; i++) {
            float* as = &As[(lrow + i * 32) * SMS + lc4 * 4];
            float* bs = &Bs[(lrow + i * 32) * SMS + lc4 * 4];
            as[0] = __uint_as_float(f2tf(pa[i].x));
            as[1] = __uint_as_float(f2tf(pa[i].y));
            as[2] = __uint_as_float(f2tf(pa[i].z));
            as[3] = __uint_as_float(f2tf(pa[i].w));
            bs[0] = __uint_as_float(f2tf(pb[i].x));
            bs[1] = __uint_as_float(f2tf(pb[i].y));
            bs[2] = __uint_as_float(f2tf(pb[i].z));
            bs[3] = __uint_as_float(f2tf(pb[i].w));
        }
        __syncthreads();
        if (kt + 1 < ntiles) {
            const float* Ag2 = Ag + (kt + 1) * 32;
            const float* Wg2 = Wg + (kt + 1) * 32;
            #pragma unroll
            for (int i = 0; i < 4; i++) {
                pa[i] = *(const float4*)(Ag2 + (size_t)(i * 32) * K);
                pb[i] = *(const float4*)(Wg2 + (size_t)(i * 32) * K);
            }
        }
        #pragma unroll
        for (int ks = 0; ks < 4; ks++) {
            uint32_t af[4][4], bf[4][2];
            const int c = ks * 8 + (lane & 3);
            #pragma unroll
            for (int mt = 0; mt < 4; mt++) {
                const int r = wm * 64 + mt * 16 + (lane >> 2);
                af[mt][0] = __float_as_uint(As[r * SMS + c]);
                af[mt][1] = __float_as_uint(As[(r + 8) * SMS + c]);
                af[mt][2] = __float_as_uint(As[r * SMS + c + 4]);
                af[mt][3] = __float_as_uint(As[(r + 8) * SMS + c + 4]);
            }
            #pragma unroll
            for (int nt = 0; nt < 4; nt++) {
                const int n = wn * 32 + nt * 8 + (lane >> 2);
                bf[nt][0] = __float_as_uint(Bs[n * SMS + c]);
                bf[nt][1] = __float_as_uint(Bs[n * SMS + c + 4]);
            }
            #pragma unroll
            for (int mt = 0; mt < 4; mt++)
                #pragma unroll
                for (int nt = 0; nt < 4; nt++)
                    mma_tf32(acc[mt][nt], af[mt], bf[nt]);
        }
        __syncthreads();
    }

    // epilogue
    #pragma unroll
    for (int mt = 0; mt < 4; mt++) {
        #pragma unroll
        for (int nt = 0; nt < 4; nt++) {
            const int row = bm + wm * 64 + mt * 16 + (lane >> 2);
            const int col = bn + wn * 32 + nt * 8 + (lane & 3) * 2;
            #pragma unroll
            for (int half = 0; half < 2; half++) {
                const int r = row + half * 8;
                float v0 = acc[mt][nt][half * 2 + 0];
                float v1 = acc[mt][nt][half * 2 + 1];
                if (HASB) { v0 += bias[col]; v1 += bias[col + 1]; }
                if (GELU) { v0 = gelu_f(v0); v1 = gelu_f(v1); }
                if (RES) {
                    const float* Rr = res + (size_t)r * Nd + col;
                    v0 += Rr[0]; v1 += Rr[1];
                }
                *(float2*)(C + (size_t)r * Nd + col) = make_float2(v0, v1);
            }
        }
    }
}

// ---------------- depthwise 3x3 dilation-2 conv + GELU ----------------
__global__ __launch_bounds__(256) void dwconv_kernel(
    const float* __restrict__ h1, float* __restrict__ h2,
    const float* __restrict__ w, const float* __restrict__ bias)
{
    const int n = blockIdx.x;   // 0..1023
    const int b = blockIdx.y;   // 0..7
    const int y = n >> 5, x = n & 31;
    const size_t base = (size_t)b * N_ * HID_;
    for (int c = threadIdx.x; c < HID_; c += 256) {
        float acc = bias[c];
        #pragma unroll
        for (int i = 0; i < 3; i++) {
            const int yy = y + 2 * i - 2;
            if (yy < 0 || yy > 31) continue;
            #pragma unroll
            for (int j = 0; j < 3; j++) {
                const int xx = x + 2 * j - 2;
                if (xx < 0 || xx > 31) continue;
                acc += w[c * 9 + i * 3 + j] *
                       h1[base + (size_t)(yy * 32 + xx) * HID_ + c];
            }
        }
        h2[base + (size_t)n * HID_ + c] = gelu_f(acc);
    }
}

// ---------------- bias precompute: g_bias[h][q][k] = table + global ---------
__global__ __launch_bounds__(256) void bias_kernel(
    const int* __restrict__ rel_index, const float* __restrict__ rel_table,
    const float* __restrict__ gb)
{
    __shared__ float tab[NREL_];
    const int h = blockIdx.y;
    const int q0 = blockIdx.x * 32;
    for (int i = threadIdx.x; i < NREL_; i += 256) tab[i] = rel_table[i * H_ + h];
    __syncthreads();
    float* out = g_bias + (size_t)h * (N_ * N_);
    for (int e = threadIdx.x; e < 32 * N_; e += 256) {
        const int q = q0 + (e >> 10), k = e & 1023;
        const size_t idx = (size_t)q * N_ + k;
        out[idx] = tab[rel_index[idx]] + gb[idx];
    }
}

// ---------------- flash attention (bias precomputed, scores in regs) --------
__global__ __launch_bounds__(128) void attn_kernel(
    const float* __restrict__ qkv, float* __restrict__ att)
{
    const int q0 = blockIdx.x * 128;
    const int h  = blockIdx.y;
    const int b  = blockIdx.z;
    const int t  = threadIdx.x;
    __shared__ float Ks[32][32];
    __shared__ float Vs[32][32];
    __shared__ float Bt[128][32];   // bias tile, bank-swizzled (k+q)&31

    const int qrow = q0 + t;
    const size_t qkvbase = (size_t)b * N_ * 1152;
    const float SCALE = 0.17677669529663687f;  // HD^-0.5
    const float* bh = g_bias + (size_t)h * (N_ * N_);

    float qr[32], o[32];
    #pragma unroll
    for (int d = 0; d < 32; d++) {
        qr[d] = qkv[qkvbase + (size_t)qrow * 1152 + h * 32 + d] * SCALE;
        o[d] = 0.0f;
    }
    float mrun = -1e30f, ssum = 0.0f;

    for (int kt = 0; kt < N_; kt += 32) {
        #pragma unroll
        for (int r = 0; r < 8; r++) {
            const int idx = t + r * 128;
            const int krow = idx >> 5, d = idx & 31;
            const size_t src = qkvbase + (size_t)(kt + krow) * 1152 + h * 32 + d;
            Ks[krow][d] = qkv[src + 384];
            Vs[krow][d] = qkv[src + 768];
        }
        #pragma unroll
        for (int r = 0; r < 32; r++) {
            const int idx = t + r * 128;
            const int qq = idx >> 5, kk = idx & 31;
            Bt[qq][(kk + qq) & 31] = bh[(size_t)(q0 + qq) * N_ + kt + kk];
        }
        __syncthreads();

        float s[32];
        float mt = mrun;
        #pragma unroll
        for (int j = 0; j < 32; j++) {
            float v = Bt[t][(j + t) & 31];
            #pragma unroll
            for (int d = 0; d < 32; d++) v += qr[d] * Ks[j][d];
            s[j] = v;
            mt = fmaxf(mt, v);
        }
        const float corr = __expf(mrun - mt);
        ssum *= corr;
        #pragma unroll
        for (int d = 0; d < 32; d++) o[d] *= corr;
        #pragma unroll
        for (int j = 0; j < 32; j++) {
            const float p = __expf(s[j] - mt);
            ssum += p;
            #pragma unroll
            for (int d = 0; d < 32; d++) o[d] += p * Vs[j][d];
        }
        mrun = mt;
        __syncthreads();
    }
    const float inv = 1.0f / ssum;
    const size_t obase = ((size_t)b * N_ + qrow) * C_ + h * HD_;
    #pragma unroll
    for (int d = 0; d < 32; d++) att[obase + d] = o[d] * inv;
}

// ---------------- launch ----------------
extern "C" void kernel_launch(void* const* d_in, const int* in_sizes, int n_in,
                              void* d_out, int out_size)
{
    const int base = (n_in >= 19) ? 2 : 0;
    const float* x         = (const float*)d_in[0];
    const int*   rel_index = (const int*)  d_in[1 + base];
    const float* ln1_g     = (const float*)d_in[2 + base];
    const float* ln1_b     = (const float*)d_in[3 + base];
    const float* w_qkv     = (const float*)d_in[4 + base];
    const float* w_proj    = (const float*)d_in[5 + base];
    const float* b_proj    = (const float*)d_in[6 + base];
    const float* rel_table = (const float*)d_in[7 + base];
    const float* gbias     = (const float*)d_in[8 + base];
    const float* ln2_g     = (const float*)d_in[9 + base];
    const float* ln2_b     = (const float*)d_in[10 + base];
    const float* w_pw1     = (const float*)d_in[11 + base];
    const float* b_pw1     = (const float*)d_in[12 + base];
    const float* w_dw      = (const float*)d_in[13 + base];
    const float* b_dw      = (const float*)d_in[14 + base];
    const float* w_pw2     = (const float*)d_in[15 + base];
    const float* b_pw2     = (const float*)d_in[16 + base];
    float* out = (float*)d_out;

    void *p_ln2, *p_h1, *p_h2, *p_x1, *p_ln1, *p_qkv, *p_att;
    cudaGetSymbolAddress(&p_ln2, g_ln2);
    cudaGetSymbolAddress(&p_h1,  g_h1);
    cudaGetSymbolAddress(&p_h2,  g_h2);
    cudaGetSymbolAddress(&p_x1,  g_x1);
    cudaGetSymbolAddress(&p_ln1, g_ln1);
    cudaGetSymbolAddress(&p_qkv, g_qkv);
    cudaGetSymbolAddress(&p_att, g_att);

    // bias precompute (independent of x) — overlaps with MLP phase
    bias_kernel<<<dim3(32, 12), 256>>>(rel_index, rel_table, gbias);

    // 1) x1 = x + MLP(LN2(x))
    ln_kernel<<<M_, 128>>>(x, ln2_g, ln2_b, (float*)p_ln2);
    mma_gemm<true, true, false><<<dim3(HID_ / 128, M_ / 128), 256>>>(
        (const float*)p_ln2, w_pw1, b_pw1, nullptr, (float*)p_h1, M_, HID_, C_);
    dwconv_kernel<<<dim3(N_, B_), 256>>>(
        (const float*)p_h1, (float*)p_h2, w_dw, b_dw);
    mma_gemm<false, true, true><<<dim3(C_ / 128, M_ / 128), 256>>>(
        (const float*)p_h2, w_pw2, b_pw2, x, (float*)p_x1, M_, C_, HID_);

    // 2) out = x1 + Attn(LN1(x1))
    ln_kernel<<<M_, 128>>>((const float*)p_x1, ln1_g, ln1_b, (float*)p_ln1);
    mma_gemm<false, false, false><<<dim3(1152 / 128, M_ / 128), 256>>>(
        (const float*)p_ln1, w_qkv, nullptr, nullptr, (float*)p_qkv, M_, 1152, C_);
    attn_kernel<<<dim3(N_ / 128, H_, B_), 128>>>(
        (const float*)p_qkv, (float*)p_att);
    mma_gemm<false, true, true><<<dim3(C_ / 128, M_ / 128), 256>>>(
        (const float*)p_att, w_proj, b_proj, (const float*)p_x1, out, M_, C_, C_);
}

// round 3
// speedup vs baseline: 2.9296x; 1.6241x over previous
#include <cuda_runtime.h>
#include <math.h>
#include <stdint.h>

// Problem constants
#define B_  8
#define N_  1024
#define C_  384
#define H_  12
#define HD_ 32
#define HID_ 768
#define M_  (B_ * N_)
#define NREL_ 3969
#define SCALE_ 0.17677669529663687f

__device__ __forceinline__ float gelu_f(float v) {
    return 0.5f * v * (1.0f + erff(v * 0.70710678118654752f));
}

__device__ __forceinline__ uint32_t f2tf(float x) {
    uint32_t r;
    asm("cvt.rna.tf32.f32 %0, %1;" : "=r"(r) : "f"(x));
    return r;
}

__device__ __forceinline__ void mma_tf32(float* c, const uint32_t* a, const uint32_t* b) {
    asm volatile(
        "mma.sync.aligned.m16n8k8.row.col.f32.tf32.tf32.f32 "
        "{%0,%1,%2,%3}, {%4,%5,%6,%7}, {%8,%9}, {%0,%1,%2,%3};"
        : "+f"(c[0]), "+f"(c[1]), "+f"(c[2]), "+f"(c[3])
        : "r"(a[0]), "r"(a[1]), "r"(a[2]), "r"(a[3]), "r"(b[0]), "r"(b[1]));
}

// ---------------- scratch ----------------
__device__ float g_ln2[M_ * C_];
__device__ float g_h1 [M_ * HID_];
__device__ float g_h2 [M_ * HID_];
__device__ float g_x1 [M_ * C_];
__device__ float g_ln1[M_ * C_];
__device__ float g_qkv[M_ * 3 * C_];
__device__ float g_att[M_ * C_];
__device__ float g_bias[H_ * N_ * N_];   // 48MB precomputed rel+global bias

// ---------------- LayerNorm ----------------
__global__ __launch_bounds__(128) void ln_kernel(
    const float* __restrict__ in, const float* __restrict__ g,
    const float* __restrict__ bta, float* __restrict__ out)
{
    const int row = blockIdx.x;
    const int t = threadIdx.x;
    const float* xr = in + (size_t)row * C_;
    float v0 = xr[t], v1 = xr[t + 128], v2 = xr[t + 256];
    float s = v0 + v1 + v2;
    __shared__ float red[4], red2[4];
    #pragma unroll
    for (int o = 16; o; o >>= 1) s += __shfl_xor_sync(0xffffffffu, s, o);
    if ((t & 31) == 0) red[t >> 5] = s;
    __syncthreads();
    const float mean = (red[0] + red[1] + red[2] + red[3]) * (1.0f / C_);
    const float d0 = v0 - mean, d1 = v1 - mean, d2 = v2 - mean;
    float q = d0 * d0 + d1 * d1 + d2 * d2;
    #pragma unroll
    for (int o = 16; o; o >>= 1) q += __shfl_xor_sync(0xffffffffu, q, o);
    if ((t & 31) == 0) red2[t >> 5] = q;
    __syncthreads();
    const float var = (red2[0] + red2[1] + red2[2] + red2[3]) * (1.0f / C_);
    const float inv = rsqrtf(var + 1e-5f);
    float* orow = out + (size_t)row * C_;
    orow[t]       = d0 * inv * g[t]       + bta[t];
    orow[t + 128] = d1 * inv * g[t + 128] + bta[t + 128];
    orow[t + 256] = d2 * inv * g[t + 256] + bta[t + 256];
}

// ---------------- tf32 tensor-core GEMM (128x128 tile) ----------------
#define SMS 36
template<bool GELU, bool HASB, bool RES>
__global__ __launch_bounds__(256) void mma_gemm(
    const float* __restrict__ A, const float* __restrict__ W,
    const float* __restrict__ bias, const float* __restrict__ res,
    float* __restrict__ C, int M, int Nd, int K)
{
    __shared__ float As[128 * SMS];
    __shared__ float Bs[128 * SMS];
    const int tid  = threadIdx.x;
    const int lane = tid & 31, warp = tid >> 5;
    const int wm = warp >> 2, wn = warp & 3;
    const int bm = blockIdx.y * 128, bn = blockIdx.x * 128;

    const int lrow = tid >> 3;
    const int lc4  = tid & 7;
    const float* Ag = A + (size_t)(bm + lrow) * K + lc4 * 4;
    const float* Wg = W + (size_t)(bn + lrow) * K + lc4 * 4;

    float4 pa[4], pb[4];
    #pragma unroll
    for (int i = 0; i < 4; i++) {
        pa[i] = *(const float4*)(Ag + (size_t)(i * 32) * K);
        pb[i] = *(const float4*)(Wg + (size_t)(i * 32) * K);
    }

    float acc[4][4][4] = {};
    const int ntiles = K >> 5;

    for (int kt = 0; kt < ntiles; kt++) {
        #pragma unroll
        for (int i = 0; i < 4; i++) {
            float* as = &As[(lrow + i * 32) * SMS + lc4 * 4];
            float* bs = &Bs[(lrow + i * 32) * SMS + lc4 * 4];
            as[0] = __uint_as_float(f2tf(pa[i].x));
            as[1] = __uint_as_float(f2tf(pa[i].y));
            as[2] = __uint_as_float(f2tf(pa[i].z));
            as[3] = __uint_as_float(f2tf(pa[i].w));
            bs[0] = __uint_as_float(f2tf(pb[i].x));
            bs[1] = __uint_as_float(f2tf(pb[i].y));
            bs[2] = __uint_as_float(f2tf(pb[i].z));
            bs[3] = __uint_as_float(f2tf(pb[i].w));
        }
        __syncthreads();
        if (kt + 1 < ntiles) {
            const float* Ag2 = Ag + (kt + 1) * 32;
            const float* Wg2 = Wg + (kt + 1) * 32;
            #pragma unroll
            for (int i = 0; i < 4; i++) {
                pa[i] = *(const float4*)(Ag2 + (size_t)(i * 32) * K);
                pb[i] = *(const float4*)(Wg2 + (size_t)(i * 32) * K);
            }
        }
        #pragma unroll
        for (int ks = 0; ks < 4; ks++) {
            uint32_t af[4][4], bf[4][2];
            const int c = ks * 8 + (lane & 3);
            #pragma unroll
            for (int mt = 0; mt < 4; mt++) {
                const int r = wm * 64 + mt * 16 + (lane >> 2);
                af[mt][0] = __float_as_uint(As[r * SMS + c]);
                af[mt][1] = __float_as_uint(As[(r + 8) * SMS + c]);
                af[mt][2] = __float_as_uint(As[r * SMS + c + 4]);
                af[mt][3] = __float_as_uint(As[(r + 8) * SMS + c + 4]);
            }
            #pragma unroll
            for (int nt = 0; nt < 4; nt++) {
                const int n = wn * 32 + nt * 8 + (lane >> 2);
                bf[nt][0] = __float_as_uint(Bs[n * SMS + c]);
                bf[nt][1] = __float_as_uint(Bs[n * SMS + c + 4]);
            }
            #pragma unroll
            for (int mt = 0; mt < 4; mt++)
                #pragma unroll
                for (int nt = 0; nt < 4; nt++)
                    mma_tf32(acc[mt][nt], af[mt], bf[nt]);
        }
        __syncthreads();
    }

    #pragma unroll
    for (int mt = 0; mt < 4; mt++) {
        #pragma unroll
        for (int nt = 0; nt < 4; nt++) {
            const int row = bm + wm * 64 + mt * 16 + (lane >> 2);
            const int col = bn + wn * 32 + nt * 8 + (lane & 3) * 2;
            #pragma unroll
            for (int half = 0; half < 2; half++) {
                const int r = row + half * 8;
                float v0 = acc[mt][nt][half * 2 + 0];
                float v1 = acc[mt][nt][half * 2 + 1];
                if (HASB) { v0 += bias[col]; v1 += bias[col + 1]; }
                if (GELU) { v0 = gelu_f(v0); v1 = gelu_f(v1); }
                if (RES) {
                    const float* Rr = res + (size_t)r * Nd + col;
                    v0 += Rr[0]; v1 += Rr[1];
                }
                *(float2*)(C + (size_t)r * Nd + col) = make_float2(v0, v1);
            }
        }
    }
}

// ---------------- depthwise 3x3 dilation-2 conv + GELU ----------------
__global__ __launch_bounds__(256) void dwconv_kernel(
    const float* __restrict__ h1, float* __restrict__ h2,
    const float* __restrict__ w, const float* __restrict__ bias)
{
    const int n = blockIdx.x;
    const int b = blockIdx.y;
    const int y = n >> 5, x = n & 31;
    const size_t base = (size_t)b * N_ * HID_;
    for (int c = threadIdx.x; c < HID_; c += 256) {
        float acc = bias[c];
        #pragma unroll
        for (int i = 0; i < 3; i++) {
            const int yy = y + 2 * i - 2;
            if (yy < 0 || yy > 31) continue;
            #pragma unroll
            for (int j = 0; j < 3; j++) {
                const int xx = x + 2 * j - 2;
                if (xx < 0 || xx > 31) continue;
                acc += w[c * 9 + i * 3 + j] *
                       h1[base + (size_t)(yy * 32 + xx) * HID_ + c];
            }
        }
        h2[base + (size_t)n * HID_ + c] = gelu_f(acc);
    }
}

// ---------------- bias precompute ----------------
__global__ __launch_bounds__(256) void bias_kernel(
    const int* __restrict__ rel_index, const float* __restrict__ rel_table,
    const float* __restrict__ gb)
{
    __shared__ float tab[NREL_];
    const int h = blockIdx.y;
    const int q0 = blockIdx.x * 32;
    for (int i = threadIdx.x; i < NREL_; i += 256) tab[i] = rel_table[i * H_ + h];
    __syncthreads();
    float* out = g_bias + (size_t)h * (N_ * N_);
    for (int e = threadIdx.x; e < 32 * N_; e += 256) {
        const int q = q0 + (e >> 10), k = e & 1023;
        const size_t idx = (size_t)q * N_ + k;
        out[idx] = tab[rel_index[idx]] + gb[idx];
    }
}

// ---------------- tensor-core flash attention -------------------------------
// grid (8, 12, 8), 256 thr (8 warps). Warp w owns queries q0+w*16..+15.
// Key tiles of 64. S = Q Kt via mma; P staged in per-warp smem; PV via mma.
__global__ __launch_bounds__(256) void attn_mma_kernel(
    const float* __restrict__ qkv, float* __restrict__ att)
{
    const int q0 = blockIdx.x * 128;
    const int h  = blockIdx.y;
    const int b  = blockIdx.z;
    const int tid = threadIdx.x;
    const int lane = tid & 31, w = tid >> 5;
    const int lq = lane >> 2;      // quad row 0..7
    const int lr = lane & 3;       // quad lane 0..3

    __shared__ float Ks[64][40];        // [key][d]
    __shared__ float Vs[64][40];        // [key][d]
    __shared__ float Ps[8][16][68];     // per-warp P tile

    const size_t qbase = (size_t)b * N_ * 1152;

    // Q A-fragments, scaled + tf32, cached in regs (4 k-steps)
    uint32_t qa[4][4];
    {
        const int qr = q0 + w * 16 + lq;
        const float* qp  = qkv + qbase + (size_t)qr * 1152 + h * 32;
        const float* qp8 = qp + 8 * 1152;
        #pragma unroll
        for (int ks = 0; ks < 4; ks++) {
            const int d0 = ks * 8 + lr;
            qa[ks][0] = f2tf(qp [d0]     * SCALE_);
            qa[ks][1] = f2tf(qp8[d0]     * SCALE_);
            qa[ks][2] = f2tf(qp [d0 + 4] * SCALE_);
            qa[ks][3] = f2tf(qp8[d0 + 4] * SCALE_);
        }
    }

    float o[4][4] = {};            // O accumulator: 16 rows x 32 dims
    float m0 = -1e30f, m1 = -1e30f, l0 = 0.0f, l1 = 0.0f;
    const float* bh = g_bias + (size_t)h * N_ * N_;
    const int br0 = q0 + w * 16 + lq;

    for (int kt = 0; kt < 16; kt++) {
        const int k0 = kt * 64;
        // load K/V tile (tf32) — coalesced float4 reads
        #pragma unroll
        for (int i = 0; i < 2; i++) {
            const int idx = tid + i * 256;
            const int kl = idx >> 3, d4 = idx & 7;
            const float* srcb = qkv + qbase + (size_t)(k0 + kl) * 1152 + h * 32 + d4 * 4;
            const float4 kv = *(const float4*)(srcb + 384);
            const float4 vv = *(const float4*)(srcb + 768);
            float4 kc, vc;
            kc.x = __uint_as_float(f2tf(kv.x)); kc.y = __uint_as_float(f2tf(kv.y));
            kc.z = __uint_as_float(f2tf(kv.z)); kc.w = __uint_as_float(f2tf(kv.w));
            vc.x = __uint_as_float(f2tf(vv.x)); vc.y = __uint_as_float(f2tf(vv.y));
            vc.z = __uint_as_float(f2tf(vv.z)); vc.w = __uint_as_float(f2tf(vv.w));
            *(float4*)&Ks[kl][d4 * 4] = kc;
            *(float4*)&Vs[kl][d4 * 4] = vc;
        }
        __syncthreads();

        // S = Q @ K^T : 8 n-frags (64 keys)
        float s[8][4];
        #pragma unroll
        for (int nf = 0; nf < 8; nf++)
            #pragma unroll
            for (int i = 0; i < 4; i++) s[nf][i] = 0.0f;
        #pragma unroll
        for (int nf = 0; nf < 8; nf++) {
            #pragma unroll
            for (int ks = 0; ks < 4; ks++) {
                uint32_t bf[2];
                bf[0] = __float_as_uint(Ks[nf * 8 + lq][ks * 8 + lr]);
                bf[1] = __float_as_uint(Ks[nf * 8 + lq][ks * 8 + lr + 4]);
                mma_tf32(s[nf], qa[ks], bf);
            }
        }

        // + bias, row max
        float nm0 = m0, nm1 = m1;
        #pragma unroll
        for (int nf = 0; nf < 8; nf++) {
            const int col = k0 + nf * 8 + lr * 2;
            const float2 b0v = *(const float2*)(bh + (size_t)br0 * N_ + col);
            const float2 b1v = *(const float2*)(bh + (size_t)(br0 + 8) * N_ + col);
            s[nf][0] += b0v.x; s[nf][1] += b0v.y;
            s[nf][2] += b1v.x; s[nf][3] += b1v.y;
            nm0 = fmaxf(nm0, fmaxf(s[nf][0], s[nf][1]));
            nm1 = fmaxf(nm1, fmaxf(s[nf][2], s[nf][3]));
        }
        nm0 = fmaxf(nm0, __shfl_xor_sync(0xffffffffu, nm0, 1));
        nm0 = fmaxf(nm0, __shfl_xor_sync(0xffffffffu, nm0, 2));
        nm1 = fmaxf(nm1, __shfl_xor_sync(0xffffffffu, nm1, 1));
        nm1 = fmaxf(nm1, __shfl_xor_sync(0xffffffffu, nm1, 2));

        const float c0 = __expf(m0 - nm0), c1 = __expf(m1 - nm1);
        m0 = nm0; m1 = nm1; l0 *= c0; l1 *= c1;
        #pragma unroll
        for (int nf = 0; nf < 4; nf++) {
            o[nf][0] *= c0; o[nf][1] *= c0;
            o[nf][2] *= c1; o[nf][3] *= c1;
        }

        // exp -> P (tf32 to per-warp smem), row sums
        float a0 = 0.0f, a1 = 0.0f;
        #pragma unroll
        for (int nf = 0; nf < 8; nf++) {
            const float p0 = __expf(s[nf][0] - nm0);
            const float p1 = __expf(s[nf][1] - nm0);
            const float p2 = __expf(s[nf][2] - nm1);
            const float p3 = __expf(s[nf][3] - nm1);
            a0 += p0 + p1; a1 += p2 + p3;
            const int col = nf * 8 + lr * 2;
            Ps[w][lq][col]         = __uint_as_float(f2tf(p0));
            Ps[w][lq][col + 1]     = __uint_as_float(f2tf(p1));
            Ps[w][lq + 8][col]     = __uint_as_float(f2tf(p2));
            Ps[w][lq + 8][col + 1] = __uint_as_float(f2tf(p3));
        }
        a0 += __shfl_xor_sync(0xffffffffu, a0, 1);
        a0 += __shfl_xor_sync(0xffffffffu, a0, 2);
        a1 += __shfl_xor_sync(0xffffffffu, a1, 1);
        a1 += __shfl_xor_sync(0xffffffffu, a1, 2);
        l0 += a0; l1 += a1;
        __syncwarp();

        // O += P @ V : 8 k-steps, 4 n-frags (32 dims)
        #pragma unroll
        for (int kf = 0; kf < 8; kf++) {
            uint32_t pa[4];
            pa[0] = __float_as_uint(Ps[w][lq][kf * 8 + lr]);
            pa[1] = __float_as_uint(Ps[w][lq + 8][kf * 8 + lr]);
            pa[2] = __float_as_uint(Ps[w][lq][kf * 8 + lr + 4]);
            pa[3] = __float_as_uint(Ps[w][lq + 8][kf * 8 + lr + 4]);
            #pragma unroll
            for (int nf = 0; nf < 4; nf++) {
                uint32_t bf[2];
                bf[0] = __float_as_uint(Vs[kf * 8 + lr][nf * 8 + lq]);
                bf[1] = __float_as_uint(Vs[kf * 8 + lr + 4][nf * 8 + lq]);
                mma_tf32(o[nf], pa, bf);
            }
        }
        __syncthreads();
    }

    // normalize + store
    const float inv0 = 1.0f / l0, inv1 = 1.0f / l1;
    #pragma unroll
    for (int nf = 0; nf < 4; nf++) {
        const int col = h * 32 + nf * 8 + lr * 2;
        float* o0 = att + ((size_t)b * N_ + br0) * C_ + col;
        float* o1 = att + ((size_t)b * N_ + br0 + 8) * C_ + col;
        *(float2*)o0 = make_float2(o[nf][0] * inv0, o[nf][1] * inv0);
        *(float2*)o1 = make_float2(o[nf][2] * inv1, o[nf][3] * inv1);
    }
}

// ---------------- launch ----------------
extern "C" void kernel_launch(void* const* d_in, const int* in_sizes, int n_in,
                              void* d_out, int out_size)
{
    const int base = (n_in >= 19) ? 2 : 0;
    const float* x         = (const float*)d_in[0];
    const int*   rel_index = (const int*)  d_in[1 + base];
    const float* ln1_g     = (const float*)d_in[2 + base];
    const float* ln1_b     = (const float*)d_in[3 + base];
    const float* w_qkv     = (const float*)d_in[4 + base];
    const float* w_proj    = (const float*)d_in[5 + base];
    const float* b_proj    = (const float*)d_in[6 + base];
    const float* rel_table = (const float*)d_in[7 + base];
    const float* gbias     = (const float*)d_in[8 + base];
    const float* ln2_g     = (const float*)d_in[9 + base];
    const float* ln2_b     = (const float*)d_in[10 + base];
    const float* w_pw1     = (const float*)d_in[11 + base];
    const float* b_pw1     = (const float*)d_in[12 + base];
    const float* w_dw      = (const float*)d_in[13 + base];
    const float* b_dw      = (const float*)d_in[14 + base];
    const float* w_pw2     = (const float*)d_in[15 + base];
    const float* b_pw2     = (const float*)d_in[16 + base];
    float* out = (float*)d_out;

    void *p_ln2, *p_h1, *p_h2, *p_x1, *p_ln1, *p_qkv, *p_att;
    cudaGetSymbolAddress(&p_ln2, g_ln2);
    cudaGetSymbolAddress(&p_h1,  g_h1);
    cudaGetSymbolAddress(&p_h2,  g_h2);
    cudaGetSymbolAddress(&p_x1,  g_x1);
    cudaGetSymbolAddress(&p_ln1, g_ln1);
    cudaGetSymbolAddress(&p_qkv, g_qkv);
    cudaGetSymbolAddress(&p_att, g_att);

    // bias precompute (independent of x)
    bias_kernel<<<dim3(32, 12), 256>>>(rel_index, rel_table, gbias);

    // 1) x1 = x + MLP(LN2(x))
    ln_kernel<<<M_, 128>>>(x, ln2_g, ln2_b, (float*)p_ln2);
    mma_gemm<true, true, false><<<dim3(HID_ / 128, M_ / 128), 256>>>(
        (const float*)p_ln2, w_pw1, b_pw1, nullptr, (float*)p_h1, M_, HID_, C_);
    dwconv_kernel<<<dim3(N_, B_), 256>>>(
        (const float*)p_h1, (float*)p_h2, w_dw, b_dw);
    mma_gemm<false, true, true><<<dim3(C_ / 128, M_ / 128), 256>>>(
        (const float*)p_h2, w_pw2, b_pw2, x, (float*)p_x1, M_, C_, HID_);

    // 2) out = x1 + Attn(LN1(x1))
    ln_kernel<<<M_, 128>>>((const float*)p_x1, ln1_g, ln1_b, (float*)p_ln1);
    mma_gemm<false, false, false><<<dim3(1152 / 128, M_ / 128), 256>>>(
        (const float*)p_ln1, w_qkv, nullptr, nullptr, (float*)p_qkv, M_, 1152, C_);
    attn_mma_kernel<<<dim3(N_ / 128, H_, B_), 256>>>(
        (const float*)p_qkv, (float*)p_att);
    mma_gemm<false, true, true><<<dim3(C_ / 128, M_ / 128), 256>>>(
        (const float*)p_att, w_proj, b_proj, (const float*)p_x1, out, M_, C_, C_);
}

// round 4
// speedup vs baseline: 4.2495x; 1.4506x over previous
#include <cuda_runtime.h>
#include <cuda_fp16.h>
#include <math.h>
#include <stdint.h>

// Problem constants
#define B_  8
#define N_  1024
#define C_  384
#define H_  12
#define HD_ 32
#define HID_ 768
#define M_  (B_ * N_)
#define NREL_ 3969
#define SCALE_ 0.17677669529663687f

__device__ __forceinline__ float gelu_f(float v) {
    return 0.5f * v * (1.0f + erff(v * 0.70710678118654752f));
}

__device__ __forceinline__ void mma_f16(float* c, const uint32_t* a, const uint32_t* b) {
    asm volatile(
        "mma.sync.aligned.m16n8k16.row.col.f32.f16.f16.f32 "
        "{%0,%1,%2,%3}, {%4,%5,%6,%7}, {%8,%9}, {%0,%1,%2,%3};"
        : "+f"(c[0]), "+f"(c[1]), "+f"(c[2]), "+f"(c[3])
        : "r"(a[0]), "r"(a[1]), "r"(a[2]), "r"(a[3]), "r"(b[0]), "r"(b[1]));
}

__device__ __forceinline__ void ldsm_x2_t(uint32_t& r0, uint32_t& r1, const __half* p) {
    uint32_t addr = (uint32_t)__cvta_generic_to_shared(p);
    asm volatile("ldmatrix.sync.aligned.m8n8.x2.trans.shared.b16 {%0,%1}, [%2];"
                 : "=r"(r0), "=r"(r1) : "r"(addr));
}

// ---------------- scratch ----------------
__device__ float g_ln2[M_ * C_];
__device__ float g_h1 [M_ * HID_];
__device__ float g_h2 [M_ * HID_];
__device__ float g_x1 [M_ * C_];
__device__ float g_ln1[M_ * C_];
__device__ __align__(16) __half g_qkvh[M_ * 3 * C_];
__device__ float g_att[M_ * C_];
__device__ __align__(16) __half g_biash[H_ * N_ * N_];   // 25MB half bias

// ---------------- LayerNorm ----------------
__global__ __launch_bounds__(128) void ln_kernel(
    const float* __restrict__ in, const float* __restrict__ g,
    const float* __restrict__ bta, float* __restrict__ out)
{
    const int row = blockIdx.x;
    const int t = threadIdx.x;
    const float* xr = in + (size_t)row * C_;
    float v0 = xr[t], v1 = xr[t + 128], v2 = xr[t + 256];
    float s = v0 + v1 + v2;
    __shared__ float red[4], red2[4];
    #pragma unroll
    for (int o = 16; o; o >>= 1) s += __shfl_xor_sync(0xffffffffu, s, o);
    if ((t & 31) == 0) red[t >> 5] = s;
    __syncthreads();
    const float mean = (red[0] + red[1] + red[2] + red[3]) * (1.0f / C_);
    const float d0 = v0 - mean, d1 = v1 - mean, d2 = v2 - mean;
    float q = d0 * d0 + d1 * d1 + d2 * d2;
    #pragma unroll
    for (int o = 16; o; o >>= 1) q += __shfl_xor_sync(0xffffffffu, q, o);
    if ((t & 31) == 0) red2[t >> 5] = q;
    __syncthreads();
    const float var = (red2[0] + red2[1] + red2[2] + red2[3]) * (1.0f / C_);
    const float inv = rsqrtf(var + 1e-5f);
    float* orow = out + (size_t)row * C_;
    orow[t]       = d0 * inv * g[t]       + bta[t];
    orow[t + 128] = d1 * inv * g[t + 128] + bta[t + 128];
    orow[t + 256] = d2 * inv * g[t + 256] + bta[t + 256];
}

// ---------------- fp16 tensor-core GEMM (128x128 tile, BK=32) ---------------
// C = act(A[M,K] @ W[Nd,K]^T + bias) (+res). Optional half output with
// q-scale applied to cols < 384 (for the fused qkv projection).
#define SMSH 40
template<bool GELU, bool HASB, bool RES, bool OUTH, bool QSC>
__global__ __launch_bounds__(256) void mma_gemm(
    const float* __restrict__ A, const float* __restrict__ W,
    const float* __restrict__ bias, const float* __restrict__ res,
    void* __restrict__ Cv, int M, int Nd, int K)
{
    __shared__ __half As[128 * SMSH];
    __shared__ __half Bs[128 * SMSH];
    const int tid  = threadIdx.x;
    const int lane = tid & 31, warp = tid >> 5;
    const int wm = warp >> 2, wn = warp & 3;
    const int lq = lane >> 2, lr = lane & 3;
    const int bm = blockIdx.y * 128, bn = blockIdx.x * 128;

    const int lrow = tid >> 3;
    const int lc4  = tid & 7;
    const float* Ag = A + (size_t)(bm + lrow) * K + lc4 * 4;
    const float* Wg = W + (size_t)(bn + lrow) * K + lc4 * 4;

    float4 pa[4], pb[4];
    #pragma unroll
    for (int i = 0; i < 4; i++) {
        pa[i] = *(const float4*)(Ag + (size_t)(i * 32) * K);
        pb[i] = *(const float4*)(Wg + (size_t)(i * 32) * K);
    }

    float acc[4][4][4] = {};
    const int ntiles = K >> 5;

    for (int kt = 0; kt < ntiles; kt++) {
        #pragma unroll
        for (int i = 0; i < 4; i++) {
            const int off = (lrow + i * 32) * SMSH + lc4 * 4;
            __half2 a01 = __floats2half2_rn(pa[i].x, pa[i].y);
            __half2 a23 = __floats2half2_rn(pa[i].z, pa[i].w);
            __half2 b01 = __floats2half2_rn(pb[i].x, pb[i].y);
            __half2 b23 = __floats2half2_rn(pb[i].z, pb[i].w);
            uint2 ua, ub;
            ua.x = *(uint32_t*)&a01; ua.y = *(uint32_t*)&a23;
            ub.x = *(uint32_t*)&b01; ub.y = *(uint32_t*)&b23;
            *(uint2*)&As[off] = ua;
            *(uint2*)&Bs[off] = ub;
        }
        __syncthreads();
        if (kt + 1 < ntiles) {
            const float* Ag2 = Ag + (kt + 1) * 32;
            const float* Wg2 = Wg + (kt + 1) * 32;
            #pragma unroll
            for (int i = 0; i < 4; i++) {
                pa[i] = *(const float4*)(Ag2 + (size_t)(i * 32) * K);
                pb[i] = *(const float4*)(Wg2 + (size_t)(i * 32) * K);
            }
        }
        #pragma unroll
        for (int ks = 0; ks < 2; ks++) {
            uint32_t af[4][4], bf[4][2];
            const int c = ks * 16 + 2 * lr;
            #pragma unroll
            for (int mt = 0; mt < 4; mt++) {
                const int r = wm * 64 + mt * 16 + lq;
                af[mt][0] = *(const uint32_t*)&As[r * SMSH + c];
                af[mt][1] = *(const uint32_t*)&As[(r + 8) * SMSH + c];
                af[mt][2] = *(const uint32_t*)&As[r * SMSH + c + 8];
                af[mt][3] = *(const uint32_t*)&As[(r + 8) * SMSH + c + 8];
            }
            #pragma unroll
            for (int nt = 0; nt < 4; nt++) {
                const int n = wn * 32 + nt * 8 + lq;
                bf[nt][0] = *(const uint32_t*)&Bs[n * SMSH + c];
                bf[nt][1] = *(const uint32_t*)&Bs[n * SMSH + c + 8];
            }
            #pragma unroll
            for (int mt = 0; mt < 4; mt++)
                #pragma unroll
                for (int nt = 0; nt < 4; nt++)
                    mma_f16(acc[mt][nt], af[mt], bf[nt]);
        }
        __syncthreads();
    }

    #pragma unroll
    for (int mt = 0; mt < 4; mt++) {
        #pragma unroll
        for (int nt = 0; nt < 4; nt++) {
            const int row = bm + wm * 64 + mt * 16 + lq;
            const int col = bn + wn * 32 + nt * 8 + lr * 2;
            #pragma unroll
            for (int half = 0; half < 2; half++) {
                const int r = row + half * 8;
                float v0 = acc[mt][nt][half * 2 + 0];
                float v1 = acc[mt][nt][half * 2 + 1];
                if (HASB) { v0 += bias[col]; v1 += bias[col + 1]; }
                if (GELU) { v0 = gelu_f(v0); v1 = gelu_f(v1); }
                if (RES) {
                    const float* Rr = res + (size_t)r * Nd + col;
                    v0 += Rr[0]; v1 += Rr[1];
                }
                if (OUTH) {
                    if (QSC && col < 384) { v0 *= SCALE_; v1 *= SCALE_; }
                    __half2 hv = __floats2half2_rn(v0, v1);
                    *(__half2*)((__half*)Cv + (size_t)r * Nd + col) = hv;
                } else {
                    *(float2*)((float*)Cv + (size_t)r * Nd + col) = make_float2(v0, v1);
                }
            }
        }
    }
}

// ---------------- depthwise 3x3 dilation-2 conv + GELU ----------------
__global__ __launch_bounds__(256) void dwconv_kernel(
    const float* __restrict__ h1, float* __restrict__ h2,
    const float* __restrict__ w, const float* __restrict__ bias)
{
    const int n = blockIdx.x;
    const int b = blockIdx.y;
    const int y = n >> 5, x = n & 31;
    const size_t base = (size_t)b * N_ * HID_;
    for (int c = threadIdx.x; c < HID_; c += 256) {
        float acc = bias[c];
        #pragma unroll
        for (int i = 0; i < 3; i++) {
            const int yy = y + 2 * i - 2;
            if (yy < 0 || yy > 31) continue;
            #pragma unroll
            for (int j = 0; j < 3; j++) {
                const int xx = x + 2 * j - 2;
                if (xx < 0 || xx > 31) continue;
                acc += w[c * 9 + i * 3 + j] *
                       h1[base + (size_t)(yy * 32 + xx) * HID_ + c];
            }
        }
        h2[base + (size_t)n * HID_ + c] = gelu_f(acc);
    }
}

// ---------------- bias precompute (half output) ----------------
__global__ __launch_bounds__(256) void bias_kernel(
    const int* __restrict__ rel_index, const float* __restrict__ rel_table,
    const float* __restrict__ gb)
{
    __shared__ float tab[NREL_];
    const int h = blockIdx.y;
    const int q0 = blockIdx.x * 32;
    for (int i = threadIdx.x; i < NREL_; i += 256) tab[i] = rel_table[i * H_ + h];
    __syncthreads();
    __half* out = g_biash + (size_t)h * (N_ * N_);
    for (int e = threadIdx.x; e < 32 * 512; e += 256) {
        const int q = q0 + (e >> 9);
        const int k = (e & 511) * 2;
        const size_t idx = (size_t)q * N_ + k;
        const __half2 v = __floats2half2_rn(
            tab[rel_index[idx]] + gb[idx],
            tab[rel_index[idx + 1]] + gb[idx + 1]);
        *(__half2*)&out[idx] = v;
    }
}

// ---------------- fp16 tensor-core flash attention --------------------------
// grid (8, 12, 8), 256 thr (8 warps). Warp w: queries q0+w*16..+15.
// qkv is half with Q pre-scaled. Bias is half.
__global__ __launch_bounds__(256) void attn_mma_kernel(
    const __half* __restrict__ qkv, float* __restrict__ att)
{
    const int q0 = blockIdx.x * 128;
    const int h  = blockIdx.y;
    const int b  = blockIdx.z;
    const int tid = threadIdx.x;
    const int lane = tid & 31, w = tid >> 5;
    const int lq = lane >> 2;
    const int lr = lane & 3;

    __shared__ __half Ks[64][SMSH];
    __shared__ __half Vs[64][SMSH];
    __shared__ __half Ps[8][16][72];

    const size_t qbase = (size_t)b * N_ * 1152;

    // Q A-fragments (pre-scaled half), 2 k-steps of 16
    uint32_t qa[2][4];
    const int br0 = q0 + w * 16 + lq;
    {
        const __half* qp  = qkv + qbase + (size_t)br0 * 1152 + h * 32;
        const __half* qp8 = qp + 8 * 1152;
        #pragma unroll
        for (int ks = 0; ks < 2; ks++) {
            const int c = ks * 16 + 2 * lr;
            qa[ks][0] = *(const uint32_t*)(qp  + c);
            qa[ks][1] = *(const uint32_t*)(qp8 + c);
            qa[ks][2] = *(const uint32_t*)(qp  + c + 8);
            qa[ks][3] = *(const uint32_t*)(qp8 + c + 8);
        }
    }

    float o[4][4] = {};
    float m0 = -1e30f, m1 = -1e30f, l0 = 0.0f, l1 = 0.0f;
    const __half* bh = g_biash + (size_t)h * N_ * N_;

    for (int kt = 0; kt < 16; kt++) {
        const int k0 = kt * 64;
        // K/V tile: one uint4 (8 halves) per thread per matrix
        {
            const int kl = tid >> 2, d8 = (tid & 3) * 8;
            const __half* src = qkv + qbase + (size_t)(k0 + kl) * 1152 + h * 32 + d8;
            *(uint4*)&Ks[kl][d8] = *(const uint4*)(src + 384);
            *(uint4*)&Vs[kl][d8] = *(const uint4*)(src + 768);
        }
        __syncthreads();

        // S = Q @ K^T
        float s[8][4];
        #pragma unroll
        for (int nf = 0; nf < 8; nf++) {
            s[nf][0] = s[nf][1] = s[nf][2] = s[nf][3] = 0.0f;
            #pragma unroll
            for (int ks = 0; ks < 2; ks++) {
                uint32_t bf[2];
                const int c = ks * 16 + 2 * lr;
                bf[0] = *(const uint32_t*)&Ks[nf * 8 + lq][c];
                bf[1] = *(const uint32_t*)&Ks[nf * 8 + lq][c + 8];
                mma_f16(s[nf], qa[ks], bf);
            }
        }

        // + bias (half2), row max
        float nm0 = m0, nm1 = m1;
        #pragma unroll
        for (int nf = 0; nf < 8; nf++) {
            const int col = k0 + nf * 8 + lr * 2;
            const float2 b0v = __half22float2(*(const __half2*)(bh + (size_t)br0 * N_ + col));
            const float2 b1v = __half22float2(*(const __half2*)(bh + (size_t)(br0 + 8) * N_ + col));
            s[nf][0] += b0v.x; s[nf][1] += b0v.y;
            s[nf][2] += b1v.x; s[nf][3] += b1v.y;
            nm0 = fmaxf(nm0, fmaxf(s[nf][0], s[nf][1]));
            nm1 = fmaxf(nm1, fmaxf(s[nf][2], s[nf][3]));
        }
        nm0 = fmaxf(nm0, __shfl_xor_sync(0xffffffffu, nm0, 1));
        nm0 = fmaxf(nm0, __shfl_xor_sync(0xffffffffu, nm0, 2));
        nm1 = fmaxf(nm1, __shfl_xor_sync(0xffffffffu, nm1, 1));
        nm1 = fmaxf(nm1, __shfl_xor_sync(0xffffffffu, nm1, 2));

        const float c0 = __expf(m0 - nm0), c1 = __expf(m1 - nm1);
        m0 = nm0; m1 = nm1; l0 *= c0; l1 *= c1;
        #pragma unroll
        for (int nf = 0; nf < 4; nf++) {
            o[nf][0] *= c0; o[nf][1] *= c0;
            o[nf][2] *= c1; o[nf][3] *= c1;
        }

        // exp -> P (half), row sums
        float a0 = 0.0f, a1 = 0.0f;
        #pragma unroll
        for (int nf = 0; nf < 8; nf++) {
            const float p0 = __expf(s[nf][0] - nm0);
            const float p1 = __expf(s[nf][1] - nm0);
            const float p2 = __expf(s[nf][2] - nm1);
            const float p3 = __expf(s[nf][3] - nm1);
            a0 += p0 + p1; a1 += p2 + p3;
            const int col = nf * 8 + lr * 2;
            *(__half2*)&Ps[w][lq][col]     = __floats2half2_rn(p0, p1);
            *(__half2*)&Ps[w][lq + 8][col] = __floats2half2_rn(p2, p3);
        }
        a0 += __shfl_xor_sync(0xffffffffu, a0, 1);
        a0 += __shfl_xor_sync(0xffffffffu, a0, 2);
        a1 += __shfl_xor_sync(0xffffffffu, a1, 1);
        a1 += __shfl_xor_sync(0xffffffffu, a1, 2);
        l0 += a0; l1 += a1;
        __syncwarp();

        // O += P @ V : 4 k-steps of 16 keys; V B-frags via ldmatrix.trans
        #pragma unroll
        for (int kf = 0; kf < 4; kf++) {
            uint32_t pa[4];
            const int c = kf * 16 + 2 * lr;
            pa[0] = *(const uint32_t*)&Ps[w][lq][c];
            pa[1] = *(const uint32_t*)&Ps[w][lq + 8][c];
            pa[2] = *(const uint32_t*)&Ps[w][lq][c + 8];
            pa[3] = *(const uint32_t*)&Ps[w][lq + 8][c + 8];
            #pragma unroll
            for (int nf = 0; nf < 4; nf++) {
                uint32_t b0r, b1r;
                ldsm_x2_t(b0r, b1r, &Vs[kf * 16 + (lane & 15)][nf * 8]);
                uint32_t bfr[2] = { b0r, b1r };
                mma_f16(o[nf], pa, bfr);
            }
        }
        __syncthreads();
    }

    const float inv0 = 1.0f / l0, inv1 = 1.0f / l1;
    #pragma unroll
    for (int nf = 0; nf < 4; nf++) {
        const int col = h * 32 + nf * 8 + lr * 2;
        float* o0 = att + ((size_t)b * N_ + br0) * C_ + col;
        float* o1 = att + ((size_t)b * N_ + br0 + 8) * C_ + col;
        *(float2*)o0 = make_float2(o[nf][0] * inv0, o[nf][1] * inv0);
        *(float2*)o1 = make_float2(o[nf][2] * inv1, o[nf][3] * inv1);
    }
}

// ---------------- launch ----------------
extern "C" void kernel_launch(void* const* d_in, const int* in_sizes, int n_in,
                              void* d_out, int out_size)
{
    const int base = (n_in >= 19) ? 2 : 0;
    const float* x         = (const float*)d_in[0];
    const int*   rel_index = (const int*)  d_in[1 + base];
    const float* ln1_g     = (const float*)d_in[2 + base];
    const float* ln1_b     = (const float*)d_in[3 + base];
    const float* w_qkv     = (const float*)d_in[4 + base];
    const float* w_proj    = (const float*)d_in[5 + base];
    const float* b_proj    = (const float*)d_in[6 + base];
    const float* rel_table = (const float*)d_in[7 + base];
    const float* gbias     = (const float*)d_in[8 + base];
    const float* ln2_g     = (const float*)d_in[9 + base];
    const float* ln2_b     = (const float*)d_in[10 + base];
    const float* w_pw1     = (const float*)d_in[11 + base];
    const float* b_pw1     = (const float*)d_in[12 + base];
    const float* w_dw      = (const float*)d_in[13 + base];
    const float* b_dw      = (const float*)d_in[14 + base];
    const float* w_pw2     = (const float*)d_in[15 + base];
    const float* b_pw2     = (const float*)d_in[16 + base];
    float* out = (float*)d_out;

    void *p_ln2, *p_h1, *p_h2, *p_x1, *p_ln1, *p_qkvh, *p_att;
    cudaGetSymbolAddress(&p_ln2, g_ln2);
    cudaGetSymbolAddress(&p_h1,  g_h1);
    cudaGetSymbolAddress(&p_h2,  g_h2);
    cudaGetSymbolAddress(&p_x1,  g_x1);
    cudaGetSymbolAddress(&p_ln1, g_ln1);
    cudaGetSymbolAddress(&p_qkvh, g_qkvh);
    cudaGetSymbolAddress(&p_att, g_att);

    // bias precompute (independent of x)
    bias_kernel<<<dim3(32, 12), 256>>>(rel_index, rel_table, gbias);

    // 1) x1 = x + MLP(LN2(x))
    ln_kernel<<<M_, 128>>>(x, ln2_g, ln2_b, (float*)p_ln2);
    mma_gemm<true, true, false, false, false><<<dim3(HID_ / 128, M_ / 128), 256>>>(
        (const float*)p_ln2, w_pw1, b_pw1, nullptr, p_h1, M_, HID_, C_);
    dwconv_kernel<<<dim3(N_, B_), 256>>>(
        (const float*)p_h1, (float*)p_h2, w_dw, b_dw);
    mma_gemm<false, true, true, false, false><<<dim3(C_ / 128, M_ / 128), 256>>>(
        (const float*)p_h2, w_pw2, b_pw2, x, p_x1, M_, C_, HID_);

    // 2) out = x1 + Attn(LN1(x1))
    ln_kernel<<<M_, 128>>>((const float*)p_x1, ln1_g, ln1_b, (float*)p_ln1);
    mma_gemm<false, false, false, true, true><<<dim3(1152 / 128, M_ / 128), 256>>>(
        (const float*)p_ln1, w_qkv, nullptr, nullptr, p_qkvh, M_, 1152, C_);
    attn_mma_kernel<<<dim3(N_ / 128, H_, B_), 256>>>(
        (const __half*)p_qkvh, (float*)p_att);
    mma_gemm<false, true, true, false, false><<<dim3(C_ / 128, M_ / 128), 256>>>(
        (const float*)p_att, w_proj, b_proj, (const float*)p_x1, out, M_, C_, C_);
}

// round 5
// speedup vs baseline: 4.4655x; 1.0508x over previous
#include <cuda_runtime.h>
#include <cuda_fp16.h>
#include <math.h>
#include <stdint.h>

// Problem constants
#define B_  8
#define N_  1024
#define C_  384
#define H_  12
#define HD_ 32
#define HID_ 768
#define M_  (B_ * N_)
#define NREL_ 3969
#define SCALE_ 0.17677669529663687f

__device__ __forceinline__ float gelu_f(float v) {
    return 0.5f * v * (1.0f + erff(v * 0.70710678118654752f));
}

__device__ __forceinline__ void mma_f16(float* c, const uint32_t* a, const uint32_t* b) {
    asm volatile(
        "mma.sync.aligned.m16n8k16.row.col.f32.f16.f16.f32 "
        "{%0,%1,%2,%3}, {%4,%5,%6,%7}, {%8,%9}, {%0,%1,%2,%3};"
        : "+f"(c[0]), "+f"(c[1]), "+f"(c[2]), "+f"(c[3])
        : "r"(a[0]), "r"(a[1]), "r"(a[2]), "r"(a[3]), "r"(b[0]), "r"(b[1]));
}

__device__ __forceinline__ void ldsm_x2_t(uint32_t& r0, uint32_t& r1, const __half* p) {
    uint32_t addr = (uint32_t)__cvta_generic_to_shared(p);
    asm volatile("ldmatrix.sync.aligned.m8n8.x2.trans.shared.b16 {%0,%1}, [%2];"
                 : "=r"(r0), "=r"(r1) : "r"(addr));
}

// ---------------- scratch ----------------
__device__ __align__(16) __half g_ln2[M_ * C_];
__device__ __align__(16) __half g_h1 [M_ * HID_];
__device__ __align__(16) __half g_h2 [M_ * HID_];
__device__ float g_x1 [M_ * C_];
__device__ __align__(16) __half g_ln1[M_ * C_];
__device__ __align__(16) __half g_qkvh[M_ * 3 * C_];
__device__ __align__(16) __half g_atth[M_ * C_];
__device__ __align__(16) __half g_biash[H_ * N_ * N_];
__device__ __align__(16) __half g_wh[1179648];   // qkv|pw1|pw2|proj halves
#define OFF_QKV  0
#define OFF_PW1  442368
#define OFF_PW2  737280
#define OFF_PROJ 1032192

// ---------------- weight fp32 -> fp16 ----------------
__global__ __launch_bounds__(256) void w2h_kernel(
    const float* __restrict__ src, __half* __restrict__ dst, int n4)
{
    const int i = blockIdx.x * 256 + threadIdx.x;
    if (i < n4) {
        const float4 v = *(const float4*)(src + i * 4);
        __half2 h0 = __floats2half2_rn(v.x, v.y);
        __half2 h1 = __floats2half2_rn(v.z, v.w);
        uint2 u; u.x = *(uint32_t*)&h0; u.y = *(uint32_t*)&h1;
        *(uint2*)(dst + i * 4) = u;
    }
}

// ---------------- LayerNorm (half output) ----------------
__global__ __launch_bounds__(128) void ln_kernel(
    const float* __restrict__ in, const float* __restrict__ g,
    const float* __restrict__ bta, __half* __restrict__ out)
{
    const int row = blockIdx.x;
    const int t = threadIdx.x;
    const float* xr = in + (size_t)row * C_;
    float v0 = xr[t], v1 = xr[t + 128], v2 = xr[t + 256];
    float s = v0 + v1 + v2;
    __shared__ float red[4], red2[4];
    #pragma unroll
    for (int o = 16; o; o >>= 1) s += __shfl_xor_sync(0xffffffffu, s, o);
    if ((t & 31) == 0) red[t >> 5] = s;
    __syncthreads();
    const float mean = (red[0] + red[1] + red[2] + red[3]) * (1.0f / C_);
    const float d0 = v0 - mean, d1 = v1 - mean, d2 = v2 - mean;
    float q = d0 * d0 + d1 * d1 + d2 * d2;
    #pragma unroll
    for (int o = 16; o; o >>= 1) q += __shfl_xor_sync(0xffffffffu, q, o);
    if ((t & 31) == 0) red2[t >> 5] = q;
    __syncthreads();
    const float var = (red2[0] + red2[1] + red2[2] + red2[3]) * (1.0f / C_);
    const float inv = rsqrtf(var + 1e-5f);
    __half* orow = out + (size_t)row * C_;
    orow[t]       = __float2half_rn(d0 * inv * g[t]       + bta[t]);
    orow[t + 128] = __float2half_rn(d1 * inv * g[t + 128] + bta[t + 128]);
    orow[t + 256] = __float2half_rn(d2 * inv * g[t + 256] + bta[t + 256]);
}

// ---------------- fp16 GEMM: half A/W, cp.async 2-stage ---------------------
// C = act(A[M,K] @ W[Nd,K]^T + bias) (+res fp32). OUTH: half out; QSC: scale
// cols<384 by SCALE_ (fused qkv).  OUTF: fp32 out.
#define SMSH 40
template<bool GELU, bool HASB, bool RES, bool OUTH, bool QSC>
__global__ __launch_bounds__(256) void mma_gemm_h(
    const __half* __restrict__ A, const __half* __restrict__ W,
    const float* __restrict__ bias, const float* __restrict__ res,
    void* __restrict__ Cv, int M, int Nd, int K)
{
    __shared__ __half As[2][128 * SMSH];
    __shared__ __half Bs[2][128 * SMSH];
    const int tid  = threadIdx.x;
    const int lane = tid & 31, warp = tid >> 5;
    const int wm = warp >> 2, wn = warp & 3;
    const int lq = lane >> 2, lr = lane & 3;
    const int bm = blockIdx.y * 128, bn = blockIdx.x * 128;
    const int ntiles = K >> 5;

    // loader: 2 x 16B per matrix per thread
    const int lrow0 = tid >> 2, lc8 = (tid & 3) * 8;
    const int lrow1 = (tid + 256) >> 2;

    #define ISSUE(kt, buf)                                                       \
    {                                                                            \
        const __half* ag0 = A + (size_t)(bm + lrow0) * K + (kt) * 32 + lc8;      \
        const __half* wg0 = W + (size_t)(bn + lrow0) * K + (kt) * 32 + lc8;      \
        const __half* ag1 = A + (size_t)(bm + lrow1) * K + (kt) * 32 + lc8;      \
        const __half* wg1 = W + (size_t)(bn + lrow1) * K + (kt) * 32 + lc8;      \
        uint32_t sa0 = (uint32_t)__cvta_generic_to_shared(&As[buf][lrow0 * SMSH + lc8]); \
        uint32_t sb0 = (uint32_t)__cvta_generic_to_shared(&Bs[buf][lrow0 * SMSH + lc8]); \
        uint32_t sa1 = (uint32_t)__cvta_generic_to_shared(&As[buf][lrow1 * SMSH + lc8]); \
        uint32_t sb1 = (uint32_t)__cvta_generic_to_shared(&Bs[buf][lrow1 * SMSH + lc8]); \
        asm volatile("cp.async.cg.shared.global [%0], [%1], 16;" :: "r"(sa0), "l"(ag0)); \
        asm volatile("cp.async.cg.shared.global [%0], [%1], 16;" :: "r"(sb0), "l"(wg0)); \
        asm volatile("cp.async.cg.shared.global [%0], [%1], 16;" :: "r"(sa1), "l"(ag1)); \
        asm volatile("cp.async.cg.shared.global [%0], [%1], 16;" :: "r"(sb1), "l"(wg1)); \
        asm volatile("cp.async.commit_group;");                                  \
    }

    float acc[4][4][4] = {};
    ISSUE(0, 0);
    for (int kt = 0; kt < ntiles; kt++) {
        if (kt + 1 < ntiles) {
            ISSUE(kt + 1, (kt + 1) & 1);
            asm volatile("cp.async.wait_group 1;");
        } else {
            asm volatile("cp.async.wait_group 0;");
        }
        __syncthreads();
        const __half* as = As[kt & 1];
        const __half* bs = Bs[kt & 1];
        #pragma unroll
        for (int ks = 0; ks < 2; ks++) {
            uint32_t af[4][4], bf[4][2];
            const int c = ks * 16 + 2 * lr;
            #pragma unroll
            for (int mt = 0; mt < 4; mt++) {
                const int r = wm * 64 + mt * 16 + lq;
                af[mt][0] = *(const uint32_t*)&as[r * SMSH + c];
                af[mt][1] = *(const uint32_t*)&as[(r + 8) * SMSH + c];
                af[mt][2] = *(const uint32_t*)&as[r * SMSH + c + 8];
                af[mt][3] = *(const uint32_t*)&as[(r + 8) * SMSH + c + 8];
            }
            #pragma unroll
            for (int nt = 0; nt < 4; nt++) {
                const int n = wn * 32 + nt * 8 + lq;
                bf[nt][0] = *(const uint32_t*)&bs[n * SMSH + c];
                bf[nt][1] = *(const uint32_t*)&bs[n * SMSH + c + 8];
            }
            #pragma unroll
            for (int mt = 0; mt < 4; mt++)
                #pragma unroll
                for (int nt = 0; nt < 4; nt++)
                    mma_f16(acc[mt][nt], af[mt], bf[nt]);
        }
        __syncthreads();
    }
    #undef ISSUE

    #pragma unroll
    for (int mt = 0; mt < 4; mt++) {
        #pragma unroll
        for (int nt = 0; nt < 4; nt++) {
            const int row = bm + wm * 64 + mt * 16 + lq;
            const int col = bn + wn * 32 + nt * 8 + lr * 2;
            #pragma unroll
            for (int half = 0; half < 2; half++) {
                const int r = row + half * 8;
                float v0 = acc[mt][nt][half * 2 + 0];
                float v1 = acc[mt][nt][half * 2 + 1];
                if (HASB) { v0 += bias[col]; v1 += bias[col + 1]; }
                if (GELU) { v0 = gelu_f(v0); v1 = gelu_f(v1); }
                if (RES) {
                    const float* Rr = res + (size_t)r * Nd + col;
                    v0 += Rr[0]; v1 += Rr[1];
                }
                if (OUTH) {
                    if (QSC && col < 384) { v0 *= SCALE_; v1 *= SCALE_; }
                    __half2 hv = __floats2half2_rn(v0, v1);
                    *(__half2*)((__half*)Cv + (size_t)r * Nd + col) = hv;
                } else {
                    *(float2*)((float*)Cv + (size_t)r * Nd + col) = make_float2(v0, v1);
                }
            }
        }
    }
}

// ---------------- depthwise 3x3 dilation-2 conv + GELU (half io) ------------
__global__ __launch_bounds__(256) void dwconv_kernel(
    const __half* __restrict__ h1, __half* __restrict__ h2,
    const float* __restrict__ w, const float* __restrict__ bias)
{
    const int n = blockIdx.x;
    const int b = blockIdx.y;
    const int y = n >> 5, x = n & 31;
    const size_t base = (size_t)b * N_ * HID_;
    for (int c = threadIdx.x; c < HID_; c += 256) {
        float acc = bias[c];
        #pragma unroll
        for (int i = 0; i < 3; i++) {
            const int yy = y + 2 * i - 2;
            if (yy < 0 || yy > 31) continue;
            #pragma unroll
            for (int j = 0; j < 3; j++) {
                const int xx = x + 2 * j - 2;
                if (xx < 0 || xx > 31) continue;
                acc += w[c * 9 + i * 3 + j] *
                       __half2float(h1[base + (size_t)(yy * 32 + xx) * HID_ + c]);
            }
        }
        h2[base + (size_t)n * HID_ + c] = __float2half_rn(gelu_f(acc));
    }
}

// ---------------- bias precompute (half output) ----------------
__global__ __launch_bounds__(256) void bias_kernel(
    const int* __restrict__ rel_index, const float* __restrict__ rel_table,
    const float* __restrict__ gb)
{
    __shared__ float tab[NREL_];
    const int h = blockIdx.y;
    const int q0 = blockIdx.x * 32;
    for (int i = threadIdx.x; i < NREL_; i += 256) tab[i] = rel_table[i * H_ + h];
    __syncthreads();
    __half* out = g_biash + (size_t)h * (N_ * N_);
    for (int e = threadIdx.x; e < 32 * 512; e += 256) {
        const int q = q0 + (e >> 9);
        const int k = (e & 511) * 2;
        const size_t idx = (size_t)q * N_ + k;
        const __half2 v = __floats2half2_rn(
            tab[rel_index[idx]] + gb[idx],
            tab[rel_index[idx + 1]] + gb[idx + 1]);
        *(__half2*)&out[idx] = v;
    }
}

// ---------------- fp16 tensor-core flash attention --------------------------
__global__ __launch_bounds__(256) void attn_mma_kernel(
    const __half* __restrict__ qkv, __half* __restrict__ att)
{
    const int q0 = blockIdx.x * 128;
    const int h  = blockIdx.y;
    const int b  = blockIdx.z;
    const int tid = threadIdx.x;
    const int lane = tid & 31, w = tid >> 5;
    const int lq = lane >> 2;
    const int lr = lane & 3;

    __shared__ __half Ks[64][SMSH];
    __shared__ __half Vs[64][SMSH];
    __shared__ __half Ps[8][16][72];

    const size_t qbase = (size_t)b * N_ * 1152;

    uint32_t qa[2][4];
    const int br0 = q0 + w * 16 + lq;
    {
        const __half* qp  = qkv + qbase + (size_t)br0 * 1152 + h * 32;
        const __half* qp8 = qp + 8 * 1152;
        #pragma unroll
        for (int ks = 0; ks < 2; ks++) {
            const int c = ks * 16 + 2 * lr;
            qa[ks][0] = *(const uint32_t*)(qp  + c);
            qa[ks][1] = *(const uint32_t*)(qp8 + c);
            qa[ks][2] = *(const uint32_t*)(qp  + c + 8);
            qa[ks][3] = *(const uint32_t*)(qp8 + c + 8);
        }
    }

    float o[4][4] = {};
    float m0 = -1e30f, m1 = -1e30f, l0 = 0.0f, l1 = 0.0f;
    const __half* bh = g_biash + (size_t)h * N_ * N_;

    for (int kt = 0; kt < 16; kt++) {
        const int k0 = kt * 64;
        {
            const int kl = tid >> 2, d8 = (tid & 3) * 8;
            const __half* src = qkv + qbase + (size_t)(k0 + kl) * 1152 + h * 32 + d8;
            *(uint4*)&Ks[kl][d8] = *(const uint4*)(src + 384);
            *(uint4*)&Vs[kl][d8] = *(const uint4*)(src + 768);
        }
        __syncthreads();

        float s[8][4];
        #pragma unroll
        for (int nf = 0; nf < 8; nf++) {
            s[nf][0] = s[nf][1] = s[nf][2] = s[nf][3] = 0.0f;
            #pragma unroll
            for (int ks = 0; ks < 2; ks++) {
                uint32_t bf[2];
                const int c = ks * 16 + 2 * lr;
                bf[0] = *(const uint32_t*)&Ks[nf * 8 + lq][c];
                bf[1] = *(const uint32_t*)&Ks[nf * 8 + lq][c + 8];
                mma_f16(s[nf], qa[ks], bf);
            }
        }

        float nm0 = m0, nm1 = m1;
        #pragma unroll
        for (int nf = 0; nf < 8; nf++) {
            const int col = k0 + nf * 8 + lr * 2;
            const float2 b0v = __half22float2(*(const __half2*)(bh + (size_t)br0 * N_ + col));
            const float2 b1v = __half22float2(*(const __half2*)(bh + (size_t)(br0 + 8) * N_ + col));
            s[nf][0] += b0v.x; s[nf][1] += b0v.y;
            s[nf][2] += b1v.x; s[nf][3] += b1v.y;
            nm0 = fmaxf(nm0, fmaxf(s[nf][0], s[nf][1]));
            nm1 = fmaxf(nm1, fmaxf(s[nf][2], s[nf][3]));
        }
        nm0 = fmaxf(nm0, __shfl_xor_sync(0xffffffffu, nm0, 1));
        nm0 = fmaxf(nm0, __shfl_xor_sync(0xffffffffu, nm0, 2));
        nm1 = fmaxf(nm1, __shfl_xor_sync(0xffffffffu, nm1, 1));
        nm1 = fmaxf(nm1, __shfl_xor_sync(0xffffffffu, nm1, 2));

        const float c0 = __expf(m0 - nm0), c1 = __expf(m1 - nm1);
        m0 = nm0; m1 = nm1; l0 *= c0; l1 *= c1;
        #pragma unroll
        for (int nf = 0; nf < 4; nf++) {
            o[nf][0] *= c0; o[nf][1] *= c0;
            o[nf][2] *= c1; o[nf][3] *= c1;
        }

        float a0 = 0.0f, a1 = 0.0f;
        #pragma unroll
        for (int nf = 0; nf < 8; nf++) {
            const float p0 = __expf(s[nf][0] - nm0);
            const float p1 = __expf(s[nf][1] - nm0);
            const float p2 = __expf(s[nf][2] - nm1);
            const float p3 = __expf(s[nf][3] - nm1);
            a0 += p0 + p1; a1 += p2 + p3;
            const int col = nf * 8 + lr * 2;
            *(__half2*)&Ps[w][lq][col]     = __floats2half2_rn(p0, p1);
            *(__half2*)&Ps[w][lq + 8][col] = __floats2half2_rn(p2, p3);
        }
        a0 += __shfl_xor_sync(0xffffffffu, a0, 1);
        a0 += __shfl_xor_sync(0xffffffffu, a0, 2);
        a1 += __shfl_xor_sync(0xffffffffu, a1, 1);
        a1 += __shfl_xor_sync(0xffffffffu, a1, 2);
        l0 += a0; l1 += a1;
        __syncwarp();

        #pragma unroll
        for (int kf = 0; kf < 4; kf++) {
            uint32_t pa[4];
            const int c = kf * 16 + 2 * lr;
            pa[0] = *(const uint32_t*)&Ps[w][lq][c];
            pa[1] = *(const uint32_t*)&Ps[w][lq + 8][c];
            pa[2] = *(const uint32_t*)&Ps[w][lq][c + 8];
            pa[3] = *(const uint32_t*)&Ps[w][lq + 8][c + 8];
            #pragma unroll
            for (int nf = 0; nf < 4; nf++) {
                uint32_t b0r, b1r;
                ldsm_x2_t(b0r, b1r, &Vs[kf * 16 + (lane & 15)][nf * 8]);
                uint32_t bfr[2] = { b0r, b1r };
                mma_f16(o[nf], pa, bfr);
            }
        }
        __syncthreads();
    }

    const float inv0 = 1.0f / l0, inv1 = 1.0f / l1;
    #pragma unroll
    for (int nf = 0; nf < 4; nf++) {
        const int col = h * 32 + nf * 8 + lr * 2;
        __half* o0 = att + ((size_t)b * N_ + br0) * C_ + col;
        __half* o1 = att + ((size_t)b * N_ + br0 + 8) * C_ + col;
        *(__half2*)o0 = __floats2half2_rn(o[nf][0] * inv0, o[nf][1] * inv0);
        *(__half2*)o1 = __floats2half2_rn(o[nf][2] * inv1, o[nf][3] * inv1);
    }
}

// ---------------- launch ----------------
extern "C" void kernel_launch(void* const* d_in, const int* in_sizes, int n_in,
                              void* d_out, int out_size)
{
    const int base = (n_in >= 19) ? 2 : 0;
    const float* x         = (const float*)d_in[0];
    const int*   rel_index = (const int*)  d_in[1 + base];
    const float* ln1_g     = (const float*)d_in[2 + base];
    const float* ln1_b     = (const float*)d_in[3 + base];
    const float* w_qkv     = (const float*)d_in[4 + base];
    const float* w_proj    = (const float*)d_in[5 + base];
    const float* b_proj    = (const float*)d_in[6 + base];
    const float* rel_table = (const float*)d_in[7 + base];
    const float* gbias     = (const float*)d_in[8 + base];
    const float* ln2_g     = (const float*)d_in[9 + base];
    const float* ln2_b     = (const float*)d_in[10 + base];
    const float* w_pw1     = (const float*)d_in[11 + base];
    const float* b_pw1     = (const float*)d_in[12 + base];
    const float* w_dw      = (const float*)d_in[13 + base];
    const float* b_dw      = (const float*)d_in[14 + base];
    const float* w_pw2     = (const float*)d_in[15 + base];
    const float* b_pw2     = (const float*)d_in[16 + base];
    float* out = (float*)d_out;

    void *p_ln2, *p_h1, *p_h2, *p_x1, *p_ln1, *p_qkvh, *p_atth, *p_wh;
    cudaGetSymbolAddress(&p_ln2, g_ln2);
    cudaGetSymbolAddress(&p_h1,  g_h1);
    cudaGetSymbolAddress(&p_h2,  g_h2);
    cudaGetSymbolAddress(&p_x1,  g_x1);
    cudaGetSymbolAddress(&p_ln1, g_ln1);
    cudaGetSymbolAddress(&p_qkvh, g_qkvh);
    cudaGetSymbolAddress(&p_atth, g_atth);
    cudaGetSymbolAddress(&p_wh,  g_wh);
    __half* wh = (__half*)p_wh;

    // weight conversions + bias precompute (independent of x)
    w2h_kernel<<<(442368/4 + 255)/256, 256>>>(w_qkv,  wh + OFF_QKV,  442368/4);
    w2h_kernel<<<(294912/4 + 255)/256, 256>>>(w_pw1,  wh + OFF_PW1,  294912/4);
    w2h_kernel<<<(294912/4 + 255)/256, 256>>>(w_pw2,  wh + OFF_PW2,  294912/4);
    w2h_kernel<<<(147456/4 + 255)/256, 256>>>(w_proj, wh + OFF_PROJ, 147456/4);
    bias_kernel<<<dim3(32, 12), 256>>>(rel_index, rel_table, gbias);

    // 1) x1 = x + MLP(LN2(x))
    ln_kernel<<<M_, 128>>>(x, ln2_g, ln2_b, (__half*)p_ln2);
    mma_gemm_h<true, true, false, true, false><<<dim3(HID_ / 128, M_ / 128), 256>>>(
        (const __half*)p_ln2, wh + OFF_PW1, b_pw1, nullptr, p_h1, M_, HID_, C_);
    dwconv_kernel<<<dim3(N_, B_), 256>>>(
        (const __half*)p_h1, (__half*)p_h2, w_dw, b_dw);
    mma_gemm_h<false, true, true, false, false><<<dim3(C_ / 128, M_ / 128), 256>>>(
        (const __half*)p_h2, wh + OFF_PW2, b_pw2, x, p_x1, M_, C_, HID_);

    // 2) out = x1 + Attn(LN1(x1))
    ln_kernel<<<M_, 128>>>((const float*)p_x1, ln1_g, ln1_b, (__half*)p_ln1);
    mma_gemm_h<false, false, false, true, true><<<dim3(1152 / 128, M_ / 128), 256>>>(
        (const __half*)p_ln1, wh + OFF_QKV, nullptr, nullptr, p_qkvh, M_, 1152, C_);
    attn_mma_kernel<<<dim3(N_ / 128, H_, B_), 256>>>(
        (const __half*)p_qkvh, (__half*)p_atth);
    mma_gemm_h<false, true, true, false, false><<<dim3(C_ / 128, M_ / 128), 256>>>(
        (const __half*)p_atth, wh + OFF_PROJ, b_proj, (const float*)p_x1, out, M_, C_, C_);
}

// round 6
// speedup vs baseline: 4.7258x; 1.0583x over previous
#include <cuda_runtime.h>
#include <cuda_fp16.h>
#include <math.h>
#include <stdint.h>

// Problem constants
#define B_  8
#define N_  1024
#define C_  384
#define H_  12
#define HD_ 32
#define HID_ 768
#define M_  (B_ * N_)
#define NREL_ 3969
#define SCALE_ 0.17677669529663687f

__device__ __forceinline__ float gelu_f(float v) {
    return 0.5f * v * (1.0f + erff(v * 0.70710678118654752f));
}

__device__ __forceinline__ void mma_f16(float* c, const uint32_t* a, const uint32_t* b) {
    asm volatile(
        "mma.sync.aligned.m16n8k16.row.col.f32.f16.f16.f32 "
        "{%0,%1,%2,%3}, {%4,%5,%6,%7}, {%8,%9}, {%0,%1,%2,%3};"
        : "+f"(c[0]), "+f"(c[1]), "+f"(c[2]), "+f"(c[3])
        : "r"(a[0]), "r"(a[1]), "r"(a[2]), "r"(a[3]), "r"(b[0]), "r"(b[1]));
}

__device__ __forceinline__ void ldsm_x4(uint32_t* r, const __half* p) {
    uint32_t addr = (uint32_t)__cvta_generic_to_shared(p);
    asm volatile("ldmatrix.sync.aligned.m8n8.x4.shared.b16 {%0,%1,%2,%3}, [%4];"
                 : "=r"(r[0]), "=r"(r[1]), "=r"(r[2]), "=r"(r[3]) : "r"(addr));
}

__device__ __forceinline__ void ldsm_x2_t(uint32_t& r0, uint32_t& r1, const __half* p) {
    uint32_t addr = (uint32_t)__cvta_generic_to_shared(p);
    asm volatile("ldmatrix.sync.aligned.m8n8.x2.trans.shared.b16 {%0,%1}, [%2];"
                 : "=r"(r0), "=r"(r1) : "r"(addr));
}

// ---------------- scratch ----------------
__device__ __align__(16) __half g_ln2[M_ * C_];
__device__ __align__(16) __half g_h1 [M_ * HID_];
__device__ __align__(16) __half g_h2 [M_ * HID_];
__device__ float g_x1 [M_ * C_];
__device__ __align__(16) __half g_ln1[M_ * C_];
__device__ __align__(16) __half g_qkvh[M_ * 3 * C_];
__device__ __align__(16) __half g_atth[M_ * C_];
__device__ __align__(16) __half g_biash[H_ * N_ * N_];
__device__ __align__(16) __half g_wh[1179648];
#define OFF_QKV  0
#define OFF_PW1  442368
#define OFF_PW2  737280
#define OFF_PROJ 1032192

// ---------------- weight fp32 -> fp16 ----------------
__global__ __launch_bounds__(256) void w2h_kernel(
    const float* __restrict__ src, __half* __restrict__ dst, int n4)
{
    const int i = blockIdx.x * 256 + threadIdx.x;
    if (i < n4) {
        const float4 v = *(const float4*)(src + i * 4);
        __half2 h0 = __floats2half2_rn(v.x, v.y);
        __half2 h1 = __floats2half2_rn(v.z, v.w);
        uint2 u; u.x = *(uint32_t*)&h0; u.y = *(uint32_t*)&h1;
        *(uint2*)(dst + i * 4) = u;
    }
}

// ---------------- LayerNorm (half output) ----------------
__global__ __launch_bounds__(128) void ln_kernel(
    const float* __restrict__ in, const float* __restrict__ g,
    const float* __restrict__ bta, __half* __restrict__ out)
{
    const int row = blockIdx.x;
    const int t = threadIdx.x;
    const float* xr = in + (size_t)row * C_;
    float v0 = xr[t], v1 = xr[t + 128], v2 = xr[t + 256];
    float s = v0 + v1 + v2;
    __shared__ float red[4], red2[4];
    #pragma unroll
    for (int o = 16; o; o >>= 1) s += __shfl_xor_sync(0xffffffffu, s, o);
    if ((t & 31) == 0) red[t >> 5] = s;
    __syncthreads();
    const float mean = (red[0] + red[1] + red[2] + red[3]) * (1.0f / C_);
    const float d0 = v0 - mean, d1 = v1 - mean, d2 = v2 - mean;
    float q = d0 * d0 + d1 * d1 + d2 * d2;
    #pragma unroll
    for (int o = 16; o; o >>= 1) q += __shfl_xor_sync(0xffffffffu, q, o);
    if ((t & 31) == 0) red2[t >> 5] = q;
    __syncthreads();
    const float var = (red2[0] + red2[1] + red2[2] + red2[3]) * (1.0f / C_);
    const float inv = rsqrtf(var + 1e-5f);
    __half* orow = out + (size_t)row * C_;
    orow[t]       = __float2half_rn(d0 * inv * g[t]       + bta[t]);
    orow[t + 128] = __float2half_rn(d1 * inv * g[t + 128] + bta[t + 128]);
    orow[t + 256] = __float2half_rn(d2 * inv * g[t + 256] + bta[t + 256]);
}

// ---------------- fp16 GEMM: ldmatrix fragments, cp.async 2-stage -----------
#define SMSH 40
template<bool GELU, bool HASB, bool RES, bool OUTH, bool QSC>
__global__ __launch_bounds__(256, 2) void mma_gemm_h(
    const __half* __restrict__ A, const __half* __restrict__ W,
    const float* __restrict__ bias, const float* __restrict__ res,
    void* __restrict__ Cv, int M, int Nd, int K)
{
    __shared__ __half As[2][128 * SMSH];
    __shared__ __half Bs[2][128 * SMSH];
    const int tid  = threadIdx.x;
    const int lane = tid & 31, warp = tid >> 5;
    const int wm = warp >> 2, wn = warp & 3;
    const int lq = lane >> 2, lr = lane & 3;
    const int bm = blockIdx.y * 128, bn = blockIdx.x * 128;
    const int ntiles = K >> 5;

    const int lrow0 = tid >> 2, lc8 = (tid & 3) * 8;
    const int lrow1 = (tid + 256) >> 2;

    // ldmatrix lane addressing offsets
    const int arow = ((lane >> 3) & 1) * 8 + (lane & 7);  // A/x4: row offset
    const int acol = (lane >> 4) * 8;                     // A/x4: col offset
    const int brow = ((lane >> 4) << 3) + (lane & 7);     // B-pair/x4: row offset
    const int bcol = ((lane >> 3) & 1) * 8;               // B-pair/x4: col offset

    #define ISSUE(kt, buf)                                                       \
    {                                                                            \
        const __half* ag0 = A + (size_t)(bm + lrow0) * K + (kt) * 32 + lc8;      \
        const __half* wg0 = W + (size_t)(bn + lrow0) * K + (kt) * 32 + lc8;      \
        const __half* ag1 = A + (size_t)(bm + lrow1) * K + (kt) * 32 + lc8;      \
        const __half* wg1 = W + (size_t)(bn + lrow1) * K + (kt) * 32 + lc8;      \
        uint32_t sa0 = (uint32_t)__cvta_generic_to_shared(&As[buf][lrow0 * SMSH + lc8]); \
        uint32_t sb0 = (uint32_t)__cvta_generic_to_shared(&Bs[buf][lrow0 * SMSH + lc8]); \
        uint32_t sa1 = (uint32_t)__cvta_generic_to_shared(&As[buf][lrow1 * SMSH + lc8]); \
        uint32_t sb1 = (uint32_t)__cvta_generic_to_shared(&Bs[buf][lrow1 * SMSH + lc8]); \
        asm volatile("cp.async.cg.shared.global [%0], [%1], 16;" :: "r"(sa0), "l"(ag0)); \
        asm volatile("cp.async.cg.shared.global [%0], [%1], 16;" :: "r"(sb0), "l"(wg0)); \
        asm volatile("cp.async.cg.shared.global [%0], [%1], 16;" :: "r"(sa1), "l"(ag1)); \
        asm volatile("cp.async.cg.shared.global [%0], [%1], 16;" :: "r"(sb1), "l"(wg1)); \
        asm volatile("cp.async.commit_group;");                                  \
    }

    float acc[4][4][4] = {};
    ISSUE(0, 0);
    for (int kt = 0; kt < ntiles; kt++) {
        if (kt + 1 < ntiles) {
            ISSUE(kt + 1, (kt + 1) & 1);
            asm volatile("cp.async.wait_group 1;");
        } else {
            asm volatile("cp.async.wait_group 0;");
        }
        __syncthreads();
        const __half* as = As[kt & 1];
        const __half* bs = Bs[kt & 1];
        #pragma unroll
        for (int ks = 0; ks < 2; ks++) {
            const int c = ks * 16;
            uint32_t af[4][4], bf[4][2];
            #pragma unroll
            for (int mt = 0; mt < 4; mt++)
                ldsm_x4(af[mt], &as[(wm * 64 + mt * 16 + arow) * SMSH + c + acol]);
            #pragma unroll
            for (int np = 0; np < 2; np++) {
                uint32_t tmp[4];
                ldsm_x4(tmp, &bs[(wn * 32 + np * 16 + brow) * SMSH + c + bcol]);
                bf[np * 2][0] = tmp[0]; bf[np * 2][1] = tmp[1];
                bf[np * 2 + 1][0] = tmp[2]; bf[np * 2 + 1][1] = tmp[3];
            }
            #pragma unroll
            for (int mt = 0; mt < 4; mt++)
                #pragma unroll
                for (int nt = 0; nt < 4; nt++)
                    mma_f16(acc[mt][nt], af[mt], bf[nt]);
        }
        __syncthreads();
    }
    #undef ISSUE

    #pragma unroll
    for (int mt = 0; mt < 4; mt++) {
        #pragma unroll
        for (int nt = 0; nt < 4; nt++) {
            const int row = bm + wm * 64 + mt * 16 + lq;
            const int col = bn + wn * 32 + nt * 8 + lr * 2;
            #pragma unroll
            for (int half = 0; half < 2; half++) {
                const int r = row + half * 8;
                float v0 = acc[mt][nt][half * 2 + 0];
                float v1 = acc[mt][nt][half * 2 + 1];
                if (HASB) { v0 += bias[col]; v1 += bias[col + 1]; }
                if (GELU) { v0 = gelu_f(v0); v1 = gelu_f(v1); }
                if (RES) {
                    const float* Rr = res + (size_t)r * Nd + col;
                    v0 += Rr[0]; v1 += Rr[1];
                }
                if (OUTH) {
                    if (QSC && col < 384) { v0 *= SCALE_; v1 *= SCALE_; }
                    __half2 hv = __floats2half2_rn(v0, v1);
                    *(__half2*)((__half*)Cv + (size_t)r * Nd + col) = hv;
                } else {
                    *(float2*)((float*)Cv + (size_t)r * Nd + col) = make_float2(v0, v1);
                }
            }
        }
    }
}

// ---------------- depthwise 3x3 dilation-2 conv + GELU (half io) ------------
__global__ __launch_bounds__(256) void dwconv_kernel(
    const __half* __restrict__ h1, __half* __restrict__ h2,
    const float* __restrict__ w, const float* __restrict__ bias)
{
    const int n = blockIdx.x;
    const int b = blockIdx.y;
    const int y = n >> 5, x = n & 31;
    const size_t base = (size_t)b * N_ * HID_;
    for (int c = threadIdx.x; c < HID_; c += 256) {
        float acc = bias[c];
        #pragma unroll
        for (int i = 0; i < 3; i++) {
            const int yy = y + 2 * i - 2;
            if (yy < 0 || yy > 31) continue;
            #pragma unroll
            for (int j = 0; j < 3; j++) {
                const int xx = x + 2 * j - 2;
                if (xx < 0 || xx > 31) continue;
                acc += w[c * 9 + i * 3 + j] *
                       __half2float(h1[base + (size_t)(yy * 32 + xx) * HID_ + c]);
            }
        }
        h2[base + (size_t)n * HID_ + c] = __float2half_rn(gelu_f(acc));
    }
}

// ---------------- bias precompute (half output) ----------------
__global__ __launch_bounds__(256) void bias_kernel(
    const int* __restrict__ rel_index, const float* __restrict__ rel_table,
    const float* __restrict__ gb)
{
    __shared__ float tab[NREL_];
    const int h = blockIdx.y;
    const int q0 = blockIdx.x * 32;
    for (int i = threadIdx.x; i < NREL_; i += 256) tab[i] = rel_table[i * H_ + h];
    __syncthreads();
    __half* out = g_biash + (size_t)h * (N_ * N_);
    for (int e = threadIdx.x; e < 32 * 512; e += 256) {
        const int q = q0 + (e >> 9);
        const int k = (e & 511) * 2;
        const size_t idx = (size_t)q * N_ + k;
        const __half2 v = __floats2half2_rn(
            tab[rel_index[idx]] + gb[idx],
            tab[rel_index[idx + 1]] + gb[idx + 1]);
        *(__half2*)&out[idx] = v;
    }
}

// ---------------- fp16 tensor-core flash attention --------------------------
__global__ __launch_bounds__(256) void attn_mma_kernel(
    const __half* __restrict__ qkv, __half* __restrict__ att)
{
    const int q0 = blockIdx.x * 128;
    const int h  = blockIdx.y;
    const int b  = blockIdx.z;
    const int tid = threadIdx.x;
    const int lane = tid & 31, w = tid >> 5;
    const int lq = lane >> 2;
    const int lr = lane & 3;

    __shared__ __half Ks[64][SMSH];
    __shared__ __half Vs[64][SMSH];
    __shared__ __half Ps[8][16][72];

    const size_t qbase = (size_t)b * N_ * 1152;

    // ldmatrix lane offsets
    const int arow = ((lane >> 3) & 1) * 8 + (lane & 7);
    const int acol = (lane >> 4) * 8;
    const int brow = ((lane >> 4) << 3) + (lane & 7);
    const int bcol = ((lane >> 3) & 1) * 8;

    uint32_t qa[2][4];
    const int br0 = q0 + w * 16 + lq;
    {
        const __half* qp  = qkv + qbase + (size_t)br0 * 1152 + h * 32;
        const __half* qp8 = qp + 8 * 1152;
        #pragma unroll
        for (int ks = 0; ks < 2; ks++) {
            const int c = ks * 16 + 2 * lr;
            qa[ks][0] = *(const uint32_t*)(qp  + c);
            qa[ks][1] = *(const uint32_t*)(qp8 + c);
            qa[ks][2] = *(const uint32_t*)(qp  + c + 8);
            qa[ks][3] = *(const uint32_t*)(qp8 + c + 8);
        }
    }

    float o[4][4] = {};
    float m0 = -1e30f, m1 = -1e30f, l0 = 0.0f, l1 = 0.0f;
    const __half* bh = g_biash + (size_t)h * N_ * N_;

    for (int kt = 0; kt < 16; kt++) {
        const int k0 = kt * 64;
        {
            const int kl = tid >> 2, d8 = (tid & 3) * 8;
            const __half* src = qkv + qbase + (size_t)(k0 + kl) * 1152 + h * 32 + d8;
            *(uint4*)&Ks[kl][d8] = *(const uint4*)(src + 384);
            *(uint4*)&Vs[kl][d8] = *(const uint4*)(src + 768);
        }
        __syncthreads();

        // S = Q @ K^T : K fragments via ldmatrix.x4 (pairs of nf)
        float s[8][4];
        #pragma unroll
        for (int nf = 0; nf < 8; nf++)
            s[nf][0] = s[nf][1] = s[nf][2] = s[nf][3] = 0.0f;
        #pragma unroll
        for (int ks = 0; ks < 2; ks++) {
            const int c = ks * 16;
            uint32_t kf[8][2];
            #pragma unroll
            for (int np = 0; np < 4; np++) {
                uint32_t tmp[4];
                ldsm_x4(tmp, &Ks[np * 16 + brow][c + bcol]);
                kf[np * 2][0] = tmp[0]; kf[np * 2][1] = tmp[1];
                kf[np * 2 + 1][0] = tmp[2]; kf[np * 2 + 1][1] = tmp[3];
            }
            #pragma unroll
            for (int nf = 0; nf < 8; nf++)
                mma_f16(s[nf], qa[ks], kf[nf]);
        }

        float nm0 = m0, nm1 = m1;
        #pragma unroll
        for (int nf = 0; nf < 8; nf++) {
            const int col = k0 + nf * 8 + lr * 2;
            const float2 b0v = __half22float2(*(const __half2*)(bh + (size_t)br0 * N_ + col));
            const float2 b1v = __half22float2(*(const __half2*)(bh + (size_t)(br0 + 8) * N_ + col));
            s[nf][0] += b0v.x; s[nf][1] += b0v.y;
            s[nf][2] += b1v.x; s[nf][3] += b1v.y;
            nm0 = fmaxf(nm0, fmaxf(s[nf][0], s[nf][1]));
            nm1 = fmaxf(nm1, fmaxf(s[nf][2], s[nf][3]));
        }
        nm0 = fmaxf(nm0, __shfl_xor_sync(0xffffffffu, nm0, 1));
        nm0 = fmaxf(nm0, __shfl_xor_sync(0xffffffffu, nm0, 2));
        nm1 = fmaxf(nm1, __shfl_xor_sync(0xffffffffu, nm1, 1));
        nm1 = fmaxf(nm1, __shfl_xor_sync(0xffffffffu, nm1, 2));

        const float c0 = __expf(m0 - nm0), c1 = __expf(m1 - nm1);
        m0 = nm0; m1 = nm1; l0 *= c0; l1 *= c1;
        #pragma unroll
        for (int nf = 0; nf < 4; nf++) {
            o[nf][0] *= c0; o[nf][1] *= c0;
            o[nf][2] *= c1; o[nf][3] *= c1;
        }

        float a0 = 0.0f, a1 = 0.0f;
        #pragma unroll
        for (int nf = 0; nf < 8; nf++) {
            const float p0 = __expf(s[nf][0] - nm0);
            const float p1 = __expf(s[nf][1] - nm0);
            const float p2 = __expf(s[nf][2] - nm1);
            const float p3 = __expf(s[nf][3] - nm1);
            a0 += p0 + p1; a1 += p2 + p3;
            const int col = nf * 8 + lr * 2;
            *(__half2*)&Ps[w][lq][col]     = __floats2half2_rn(p0, p1);
            *(__half2*)&Ps[w][lq + 8][col] = __floats2half2_rn(p2, p3);
        }
        a0 += __shfl_xor_sync(0xffffffffu, a0, 1);
        a0 += __shfl_xor_sync(0xffffffffu, a0, 2);
        a1 += __shfl_xor_sync(0xffffffffu, a1, 1);
        a1 += __shfl_xor_sync(0xffffffffu, a1, 2);
        l0 += a0; l1 += a1;
        __syncwarp();

        // O += P @ V : P via ldmatrix.x4, V via ldmatrix.x2.trans
        #pragma unroll
        for (int kf2 = 0; kf2 < 4; kf2++) {
            uint32_t pa[4];
            ldsm_x4(pa, &Ps[w][arow][kf2 * 16 + acol]);
            #pragma unroll
            for (int nf = 0; nf < 4; nf++) {
                uint32_t b0r, b1r;
                ldsm_x2_t(b0r, b1r, &Vs[kf2 * 16 + (lane & 15)][nf * 8]);
                uint32_t bfr[2] = { b0r, b1r };
                mma_f16(o[nf], pa, bfr);
            }
        }
        __syncthreads();
    }

    const float inv0 = 1.0f / l0, inv1 = 1.0f / l1;
    #pragma unroll
    for (int nf = 0; nf < 4; nf++) {
        const int col = h * 32 + nf * 8 + lr * 2;
        __half* o0 = att + ((size_t)b * N_ + br0) * C_ + col;
        __half* o1 = att + ((size_t)b * N_ + br0 + 8) * C_ + col;
        *(__half2*)o0 = __floats2half2_rn(o[nf][0] * inv0, o[nf][1] * inv0);
        *(__half2*)o1 = __floats2half2_rn(o[nf][2] * inv1, o[nf][3] * inv1);
    }
}

// ---------------- launch ----------------
extern "C" void kernel_launch(void* const* d_in, const int* in_sizes, int n_in,
                              void* d_out, int out_size)
{
    const int base = (n_in >= 19) ? 2 : 0;
    const float* x         = (const float*)d_in[0];
    const int*   rel_index = (const int*)  d_in[1 + base];
    const float* ln1_g     = (const float*)d_in[2 + base];
    const float* ln1_b     = (const float*)d_in[3 + base];
    const float* w_qkv     = (const float*)d_in[4 + base];
    const float* w_proj    = (const float*)d_in[5 + base];
    const float* b_proj    = (const float*)d_in[6 + base];
    const float* rel_table = (const float*)d_in[7 + base];
    const float* gbias     = (const float*)d_in[8 + base];
    const float* ln2_g     = (const float*)d_in[9 + base];
    const float* ln2_b     = (const float*)d_in[10 + base];
    const float* w_pw1     = (const float*)d_in[11 + base];
    const float* b_pw1     = (const float*)d_in[12 + base];
    const float* w_dw      = (const float*)d_in[13 + base];
    const float* b_dw      = (const float*)d_in[14 + base];
    const float* w_pw2     = (const float*)d_in[15 + base];
    const float* b_pw2     = (const float*)d_in[16 + base];
    float* out = (float*)d_out;

    void *p_ln2, *p_h1, *p_h2, *p_x1, *p_ln1, *p_qkvh, *p_atth, *p_wh;
    cudaGetSymbolAddress(&p_ln2, g_ln2);
    cudaGetSymbolAddress(&p_h1,  g_h1);
    cudaGetSymbolAddress(&p_h2,  g_h2);
    cudaGetSymbolAddress(&p_x1,  g_x1);
    cudaGetSymbolAddress(&p_ln1, g_ln1);
    cudaGetSymbolAddress(&p_qkvh, g_qkvh);
    cudaGetSymbolAddress(&p_atth, g_atth);
    cudaGetSymbolAddress(&p_wh,  g_wh);
    __half* wh = (__half*)p_wh;

    w2h_kernel<<<(442368/4 + 255)/256, 256>>>(w_qkv,  wh + OFF_QKV,  442368/4);
    w2h_kernel<<<(294912/4 + 255)/256, 256>>>(w_pw1,  wh + OFF_PW1,  294912/4);
    w2h_kernel<<<(294912/4 + 255)/256, 256>>>(w_pw2,  wh + OFF_PW2,  294912/4);
    w2h_kernel<<<(147456/4 + 255)/256, 256>>>(w_proj, wh + OFF_PROJ, 147456/4);
    bias_kernel<<<dim3(32, 12), 256>>>(rel_index, rel_table, gbias);

    // 1) x1 = x + MLP(LN2(x))
    ln_kernel<<<M_, 128>>>(x, ln2_g, ln2_b, (__half*)p_ln2);
    mma_gemm_h<true, true, false, true, false><<<dim3(HID_ / 128, M_ / 128), 256>>>(
        (const __half*)p_ln2, wh + OFF_PW1, b_pw1, nullptr, p_h1, M_, HID_, C_);
    dwconv_kernel<<<dim3(N_, B_), 256>>>(
        (const __half*)p_h1, (__half*)p_h2, w_dw, b_dw);
    mma_gemm_h<false, true, true, false, false><<<dim3(C_ / 128, M_ / 128), 256>>>(
        (const __half*)p_h2, wh + OFF_PW2, b_pw2, x, p_x1, M_, C_, HID_);

    // 2) out = x1 + Attn(LN1(x1))
    ln_kernel<<<M_, 128>>>((const float*)p_x1, ln1_g, ln1_b, (__half*)p_ln1);
    mma_gemm_h<false, false, false, true, true><<<dim3(1152 / 128, M_ / 128), 256>>>(
        (const __half*)p_ln1, wh + OFF_QKV, nullptr, nullptr, p_qkvh, M_, 1152, C_);
    attn_mma_kernel<<<dim3(N_ / 128, H_, B_), 256>>>(
        (const __half*)p_qkvh, (__half*)p_atth);
    mma_gemm_h<false, true, true, false, false><<<dim3(C_ / 128, M_ / 128), 256>>>(
        (const __half*)p_atth, wh + OFF_PROJ, b_proj, (const float*)p_x1, out, M_, C_, C_);
}

// round 7
// speedup vs baseline: 5.2180x; 1.1042x over previous
#include <cuda_runtime.h>
#include <cuda_fp16.h>
#include <math.h>
#include <stdint.h>

// Problem constants
#define B_  8
#define N_  1024
#define C_  384
#define H_  12
#define HD_ 32
#define HID_ 768
#define M_  (B_ * N_)
#define NREL_ 3969
#define SCALE_ 0.17677669529663687f

__device__ __forceinline__ float gelu_f(float v) {
    return 0.5f * v * (1.0f + erff(v * 0.70710678118654752f));
}

__device__ __forceinline__ void mma_f16(float* c, const uint32_t* a, const uint32_t* b) {
    asm volatile(
        "mma.sync.aligned.m16n8k16.row.col.f32.f16.f16.f32 "
        "{%0,%1,%2,%3}, {%4,%5,%6,%7}, {%8,%9}, {%0,%1,%2,%3};"
        : "+f"(c[0]), "+f"(c[1]), "+f"(c[2]), "+f"(c[3])
        : "r"(a[0]), "r"(a[1]), "r"(a[2]), "r"(a[3]), "r"(b[0]), "r"(b[1]));
}

__device__ __forceinline__ void ldsm_x4(uint32_t* r, const __half* p) {
    uint32_t addr = (uint32_t)__cvta_generic_to_shared(p);
    asm volatile("ldmatrix.sync.aligned.m8n8.x4.shared.b16 {%0,%1,%2,%3}, [%4];"
                 : "=r"(r[0]), "=r"(r[1]), "=r"(r[2]), "=r"(r[3]) : "r"(addr));
}

__device__ __forceinline__ void ldsm_x2_t(uint32_t& r0, uint32_t& r1, const __half* p) {
    uint32_t addr = (uint32_t)__cvta_generic_to_shared(p);
    asm volatile("ldmatrix.sync.aligned.m8n8.x2.trans.shared.b16 {%0,%1}, [%2];"
                 : "=r"(r0), "=r"(r1) : "r"(addr));
}

// ---------------- scratch ----------------
__device__ __align__(16) __half g_ln2[M_ * C_];
__device__ __align__(16) __half g_h1 [M_ * HID_];
__device__ __align__(16) __half g_h2 [M_ * HID_];
__device__ float g_x1 [M_ * C_];
__device__ __align__(16) __half g_ln1[M_ * C_];
__device__ __align__(16) __half g_qkvh[M_ * 3 * C_];
__device__ __align__(16) __half g_atth[M_ * C_];
__device__ __align__(16) __half g_biash[H_ * N_ * N_];
__device__ __align__(16) __half g_wh[1179648];
#define OFF_QKV  0
#define OFF_PW1  442368
#define OFF_PW2  737280
#define OFF_PROJ 1032192
// segment boundaries in float4 quads
#define Q_QKV  110592
#define Q_PW1  184320
#define Q_PW2  258048
#define Q_END  294912

// ---------------- merged weight fp32 -> fp16 ----------------
__global__ __launch_bounds__(256) void w2h_all_kernel(
    const float* __restrict__ s_qkv, const float* __restrict__ s_pw1,
    const float* __restrict__ s_pw2, const float* __restrict__ s_proj,
    __half* __restrict__ dst)
{
    const int i = blockIdx.x * 256 + threadIdx.x;
    if (i >= Q_END) return;
    const float* src; int local;
    if (i < Q_QKV)      { src = s_qkv;  local = i; }
    else if (i < Q_PW1) { src = s_pw1;  local = i - Q_QKV; }
    else if (i < Q_PW2) { src = s_pw2;  local = i - Q_PW1; }
    else                { src = s_proj; local = i - Q_PW2; }
    const float4 v = ((const float4*)src)[local];
    __half2 h0 = __floats2half2_rn(v.x, v.y);
    __half2 h1 = __floats2half2_rn(v.z, v.w);
    uint2 u; u.x = *(uint32_t*)&h0; u.y = *(uint32_t*)&h1;
    *(uint2*)(dst + (size_t)i * 4) = u;
}

// ---------------- LayerNorm (half output) ----------------
__global__ __launch_bounds__(128) void ln_kernel(
    const float* __restrict__ in, const float* __restrict__ g,
    const float* __restrict__ bta, __half* __restrict__ out)
{
    const int row = blockIdx.x;
    const int t = threadIdx.x;
    const float* xr = in + (size_t)row * C_;
    float v0 = xr[t], v1 = xr[t + 128], v2 = xr[t + 256];
    float s = v0 + v1 + v2;
    __shared__ float red[4], red2[4];
    #pragma unroll
    for (int o = 16; o; o >>= 1) s += __shfl_xor_sync(0xffffffffu, s, o);
    if ((t & 31) == 0) red[t >> 5] = s;
    __syncthreads();
    const float mean = (red[0] + red[1] + red[2] + red[3]) * (1.0f / C_);
    const float d0 = v0 - mean, d1 = v1 - mean, d2 = v2 - mean;
    float q = d0 * d0 + d1 * d1 + d2 * d2;
    #pragma unroll
    for (int o = 16; o; o >>= 1) q += __shfl_xor_sync(0xffffffffu, q, o);
    if ((t & 31) == 0) red2[t >> 5] = q;
    __syncthreads();
    const float var = (red2[0] + red2[1] + red2[2] + red2[3]) * (1.0f / C_);
    const float inv = rsqrtf(var + 1e-5f);
    __half* orow = out + (size_t)row * C_;
    orow[t]       = __float2half_rn(d0 * inv * g[t]       + bta[t]);
    orow[t + 128] = __float2half_rn(d1 * inv * g[t + 128] + bta[t + 128]);
    orow[t + 256] = __float2half_rn(d2 * inv * g[t + 256] + bta[t + 256]);
}

// ---------------- fp16 GEMM: 3-stage cp.async, 1 barrier/iter ---------------
#define SMSH 40
#define GEMM_SMEM (3 * 128 * SMSH * 2 * 2)   // 61440 bytes
template<bool GELU, bool HASB, bool RES, bool OUTH, bool QSC>
__global__ __launch_bounds__(256, 2) void mma_gemm_h(
    const __half* __restrict__ A, const __half* __restrict__ W,
    const float* __restrict__ bias, const float* __restrict__ res,
    void* __restrict__ Cv, int M, int Nd, int K)
{
    extern __shared__ __half dsm[];
    __half* Asb = dsm;
    __half* Bsb = dsm + 3 * 128 * SMSH;
    const int tid  = threadIdx.x;
    const int lane = tid & 31, warp = tid >> 5;
    const int wm = warp >> 2, wn = warp & 3;
    const int lq = lane >> 2, lr = lane & 3;
    const int bm = blockIdx.y * 128, bn = blockIdx.x * 128;
    const int ntiles = K >> 5;

    const int lrow0 = tid >> 2, lc8 = (tid & 3) * 8;
    const int lrow1 = (tid + 256) >> 2;

    const int arow = ((lane >> 3) & 1) * 8 + (lane & 7);
    const int acol = (lane >> 4) * 8;
    const int brow = ((lane >> 4) << 3) + (lane & 7);
    const int bcol = ((lane >> 3) & 1) * 8;

    #define ISSUE(kt, buf)                                                       \
    {                                                                            \
        __half* asb = Asb + (buf) * 128 * SMSH;                                  \
        __half* bsb = Bsb + (buf) * 128 * SMSH;                                  \
        const __half* ag0 = A + (size_t)(bm + lrow0) * K + (kt) * 32 + lc8;      \
        const __half* wg0 = W + (size_t)(bn + lrow0) * K + (kt) * 32 + lc8;      \
        const __half* ag1 = A + (size_t)(bm + lrow1) * K + (kt) * 32 + lc8;      \
        const __half* wg1 = W + (size_t)(bn + lrow1) * K + (kt) * 32 + lc8;      \
        uint32_t sa0 = (uint32_t)__cvta_generic_to_shared(&asb[lrow0 * SMSH + lc8]); \
        uint32_t sb0 = (uint32_t)__cvta_generic_to_shared(&bsb[lrow0 * SMSH + lc8]); \
        uint32_t sa1 = (uint32_t)__cvta_generic_to_shared(&asb[lrow1 * SMSH + lc8]); \
        uint32_t sb1 = (uint32_t)__cvta_generic_to_shared(&bsb[lrow1 * SMSH + lc8]); \
        asm volatile("cp.async.cg.shared.global [%0], [%1], 16;" :: "r"(sa0), "l"(ag0)); \
        asm volatile("cp.async.cg.shared.global [%0], [%1], 16;" :: "r"(sb0), "l"(wg0)); \
        asm volatile("cp.async.cg.shared.global [%0], [%1], 16;" :: "r"(sa1), "l"(ag1)); \
        asm volatile("cp.async.cg.shared.global [%0], [%1], 16;" :: "r"(sb1), "l"(wg1)); \
        asm volatile("cp.async.commit_group;");                                  \
    }

    float acc[4][4][4] = {};
    ISSUE(0, 0);
    if (ntiles > 1) ISSUE(1, 1);

    for (int kt = 0; kt < ntiles; kt++) {
        if (kt + 1 < ntiles) asm volatile("cp.async.wait_group 1;");
        else                 asm volatile("cp.async.wait_group 0;");
        __syncthreads();
        if (kt + 2 < ntiles) ISSUE(kt + 2, (kt + 2) % 3);

        const __half* as = Asb + (kt % 3) * 128 * SMSH;
        const __half* bs = Bsb + (kt % 3) * 128 * SMSH;
        #pragma unroll
        for (int ks = 0; ks < 2; ks++) {
            const int c = ks * 16;
            uint32_t af[4][4], bf[4][2];
            #pragma unroll
            for (int mt = 0; mt < 4; mt++)
                ldsm_x4(af[mt], &as[(wm * 64 + mt * 16 + arow) * SMSH + c + acol]);
            #pragma unroll
            for (int np = 0; np < 2; np++) {
                uint32_t tmp[4];
                ldsm_x4(tmp, &bs[(wn * 32 + np * 16 + brow) * SMSH + c + bcol]);
                bf[np * 2][0] = tmp[0]; bf[np * 2][1] = tmp[1];
                bf[np * 2 + 1][0] = tmp[2]; bf[np * 2 + 1][1] = tmp[3];
            }
            #pragma unroll
            for (int mt = 0; mt < 4; mt++)
                #pragma unroll
                for (int nt = 0; nt < 4; nt++)
                    mma_f16(acc[mt][nt], af[mt], bf[nt]);
        }
    }
    #undef ISSUE

    #pragma unroll
    for (int mt = 0; mt < 4; mt++) {
        #pragma unroll
        for (int nt = 0; nt < 4; nt++) {
            const int row = bm + wm * 64 + mt * 16 + lq;
            const int col = bn + wn * 32 + nt * 8 + lr * 2;
            #pragma unroll
            for (int half = 0; half < 2; half++) {
                const int r = row + half * 8;
                float v0 = acc[mt][nt][half * 2 + 0];
                float v1 = acc[mt][nt][half * 2 + 1];
                if (HASB) { v0 += bias[col]; v1 += bias[col + 1]; }
                if (GELU) { v0 = gelu_f(v0); v1 = gelu_f(v1); }
                if (RES) {
                    const float* Rr = res + (size_t)r * Nd + col;
                    v0 += Rr[0]; v1 += Rr[1];
                }
                if (OUTH) {
                    if (QSC && col < 384) { v0 *= SCALE_; v1 *= SCALE_; }
                    __half2 hv = __floats2half2_rn(v0, v1);
                    *(__half2*)((__half*)Cv + (size_t)r * Nd + col) = hv;
                } else {
                    *(float2*)((float*)Cv + (size_t)r * Nd + col) = make_float2(v0, v1);
                }
            }
        }
    }
}

// ---------------- depthwise 3x3 dil-2 conv + GELU: half2, hoisted bounds ----
__global__ __launch_bounds__(384) void dwconv_kernel(
    const __half* __restrict__ h1, __half* __restrict__ h2,
    const float* __restrict__ w, const float* __restrict__ bias)
{
    const int n = blockIdx.x;
    const int b = blockIdx.y;
    const int y = n >> 5, x = n & 31;
    const size_t base = (size_t)b * N_ * HID_;
    const int c0 = threadIdx.x * 2;

    float2 acc = make_float2(bias[c0], bias[c0 + 1]);
    const float* w0 = w + c0 * 9;
    const float* w1 = w + (c0 + 1) * 9;

    #pragma unroll
    for (int i = 0; i < 3; i++) {
        const int yy = y + 2 * i - 2;
        if (yy < 0 || yy > 31) continue;
        #pragma unroll
        for (int j = 0; j < 3; j++) {
            const int xx = x + 2 * j - 2;
            if (xx < 0 || xx > 31) continue;
            const float2 v = __half22float2(
                *(const __half2*)(h1 + base + (size_t)(yy * 32 + xx) * HID_ + c0));
            acc.x += w0[i * 3 + j] * v.x;
            acc.y += w1[i * 3 + j] * v.y;
        }
    }
    *(__half2*)(h2 + base + (size_t)n * HID_ + c0) =
        __floats2half2_rn(gelu_f(acc.x), gelu_f(acc.y));
}

// ---------------- bias precompute (half output) ----------------
__global__ __launch_bounds__(256) void bias_kernel(
    const int* __restrict__ rel_index, const float* __restrict__ rel_table,
    const float* __restrict__ gb)
{
    __shared__ float tab[NREL_];
    const int h = blockIdx.y;
    const int q0 = blockIdx.x * 32;
    for (int i = threadIdx.x; i < NREL_; i += 256) tab[i] = rel_table[i * H_ + h];
    __syncthreads();
    __half* out = g_biash + (size_t)h * (N_ * N_);
    for (int e = threadIdx.x; e < 32 * 512; e += 256) {
        const int q = q0 + (e >> 9);
        const int k = (e & 511) * 2;
        const size_t idx = (size_t)q * N_ + k;
        const __half2 v = __floats2half2_rn(
            tab[rel_index[idx]] + gb[idx],
            tab[rel_index[idx + 1]] + gb[idx + 1]);
        *(__half2*)&out[idx] = v;
    }
}

// ---------------- fp16 flash attention: double-buffered K/V -----------------
__global__ __launch_bounds__(256) void attn_mma_kernel(
    const __half* __restrict__ qkv, __half* __restrict__ att)
{
    const int q0 = blockIdx.x * 128;
    const int h  = blockIdx.y;
    const int b  = blockIdx.z;
    const int tid = threadIdx.x;
    const int lane = tid & 31, w = tid >> 5;
    const int lq = lane >> 2;
    const int lr = lane & 3;

    __shared__ __half Ks[2][64][SMSH];
    __shared__ __half Vs[2][64][SMSH];
    __shared__ __half Ps[8][16][72];

    const size_t qbase = (size_t)b * N_ * 1152;
    const int kl = tid >> 2, d8 = (tid & 3) * 8;

    #define AISSUE(kt, buf)                                                      \
    {                                                                            \
        const __half* src = qkv + qbase + (size_t)((kt) * 64 + kl) * 1152 + h * 32 + d8; \
        uint32_t sk = (uint32_t)__cvta_generic_to_shared(&Ks[buf][kl][d8]);      \
        uint32_t sv = (uint32_t)__cvta_generic_to_shared(&Vs[buf][kl][d8]);      \
        asm volatile("cp.async.cg.shared.global [%0], [%1], 16;" :: "r"(sk), "l"(src + 384)); \
        asm volatile("cp.async.cg.shared.global [%0], [%1], 16;" :: "r"(sv), "l"(src + 768)); \
        asm volatile("cp.async.commit_group;");                                  \
    }

    const int arow = ((lane >> 3) & 1) * 8 + (lane & 7);
    const int acol = (lane >> 4) * 8;
    const int brow = ((lane >> 4) << 3) + (lane & 7);
    const int bcol = ((lane >> 3) & 1) * 8;

    uint32_t qa[2][4];
    const int br0 = q0 + w * 16 + lq;
    {
        const __half* qp  = qkv + qbase + (size_t)br0 * 1152 + h * 32;
        const __half* qp8 = qp + 8 * 1152;
        #pragma unroll
        for (int ks = 0; ks < 2; ks++) {
            const int c = ks * 16 + 2 * lr;
            qa[ks][0] = *(const uint32_t*)(qp  + c);
            qa[ks][1] = *(const uint32_t*)(qp8 + c);
            qa[ks][2] = *(const uint32_t*)(qp  + c + 8);
            qa[ks][3] = *(const uint32_t*)(qp8 + c + 8);
        }
    }

    float o[4][4] = {};
    float m0 = -1e30f, m1 = -1e30f, l0 = 0.0f, l1 = 0.0f;
    const __half* bh0 = g_biash + (size_t)h * N_ * N_ + (size_t)br0 * N_;
    const __half* bh1 = bh0 + (size_t)8 * N_;

    AISSUE(0, 0);
    for (int kt = 0; kt < 16; kt++) {
        asm volatile("cp.async.wait_group 0;");
        __syncthreads();
        if (kt < 15) AISSUE(kt + 1, (kt + 1) & 1);

        const int buf = kt & 1;
        const int k0 = kt * 64;

        // S = Q @ K^T
        float s[8][4];
        #pragma unroll
        for (int nf = 0; nf < 8; nf++)
            s[nf][0] = s[nf][1] = s[nf][2] = s[nf][3] = 0.0f;
        #pragma unroll
        for (int ks = 0; ks < 2; ks++) {
            const int c = ks * 16;
            uint32_t kf[8][2];
            #pragma unroll
            for (int np = 0; np < 4; np++) {
                uint32_t tmp[4];
                ldsm_x4(tmp, &Ks[buf][np * 16 + brow][c + bcol]);
                kf[np * 2][0] = tmp[0]; kf[np * 2][1] = tmp[1];
                kf[np * 2 + 1][0] = tmp[2]; kf[np * 2 + 1][1] = tmp[3];
            }
            #pragma unroll
            for (int nf = 0; nf < 8; nf++)
                mma_f16(s[nf], qa[ks], kf[nf]);
        }

        float nm0 = m0, nm1 = m1;
        #pragma unroll
        for (int nf = 0; nf < 8; nf++) {
            const int col = k0 + nf * 8 + lr * 2;
            const float2 b0v = __half22float2(*(const __half2*)(bh0 + col));
            const float2 b1v = __half22float2(*(const __half2*)(bh1 + col));
            s[nf][0] += b0v.x; s[nf][1] += b0v.y;
            s[nf][2] += b1v.x; s[nf][3] += b1v.y;
            nm0 = fmaxf(nm0, fmaxf(s[nf][0], s[nf][1]));
            nm1 = fmaxf(nm1, fmaxf(s[nf][2], s[nf][3]));
        }
        nm0 = fmaxf(nm0, __shfl_xor_sync(0xffffffffu, nm0, 1));
        nm0 = fmaxf(nm0, __shfl_xor_sync(0xffffffffu, nm0, 2));
        nm1 = fmaxf(nm1, __shfl_xor_sync(0xffffffffu, nm1, 1));
        nm1 = fmaxf(nm1, __shfl_xor_sync(0xffffffffu, nm1, 2));

        const float c0 = __expf(m0 - nm0), c1 = __expf(m1 - nm1);
        m0 = nm0; m1 = nm1; l0 *= c0; l1 *= c1;
        #pragma unroll
        for (int nf = 0; nf < 4; nf++) {
            o[nf][0] *= c0; o[nf][1] *= c0;
            o[nf][2] *= c1; o[nf][3] *= c1;
        }

        float a0 = 0.0f, a1 = 0.0f;
        #pragma unroll
        for (int nf = 0; nf < 8; nf++) {
            const float p0 = __expf(s[nf][0] - nm0);
            const float p1 = __expf(s[nf][1] - nm0);
            const float p2 = __expf(s[nf][2] - nm1);
            const float p3 = __expf(s[nf][3] - nm1);
            a0 += p0 + p1; a1 += p2 + p3;
            const int col = nf * 8 + lr * 2;
            *(__half2*)&Ps[w][lq][col]     = __floats2half2_rn(p0, p1);
            *(__half2*)&Ps[w][lq + 8][col] = __floats2half2_rn(p2, p3);
        }
        a0 += __shfl_xor_sync(0xffffffffu, a0, 1);
        a0 += __shfl_xor_sync(0xffffffffu, a0, 2);
        a1 += __shfl_xor_sync(0xffffffffu, a1, 1);
        a1 += __shfl_xor_sync(0xffffffffu, a1, 2);
        l0 += a0; l1 += a1;
        __syncwarp();

        #pragma unroll
        for (int kf2 = 0; kf2 < 4; kf2++) {
            uint32_t pa[4];
            ldsm_x4(pa, &Ps[w][arow][kf2 * 16 + acol]);
            #pragma unroll
            for (int nf = 0; nf < 4; nf++) {
                uint32_t b0r, b1r;
                ldsm_x2_t(b0r, b1r, &Vs[buf][kf2 * 16 + (lane & 15)][nf * 8]);
                uint32_t bfr[2] = { b0r, b1r };
                mma_f16(o[nf], pa, bfr);
            }
        }
    }
    #undef AISSUE

    const float inv0 = 1.0f / l0, inv1 = 1.0f / l1;
    #pragma unroll
    for (int nf = 0; nf < 4; nf++) {
        const int col = h * 32 + nf * 8 + lr * 2;
        __half* o0 = att + ((size_t)b * N_ + br0) * C_ + col;
        __half* o1 = att + ((size_t)b * N_ + br0 + 8) * C_ + col;
        *(__half2*)o0 = __floats2half2_rn(o[nf][0] * inv0, o[nf][1] * inv0);
        *(__half2*)o1 = __floats2half2_rn(o[nf][2] * inv1, o[nf][3] * inv1);
    }
}

// ---------------- launch ----------------
extern "C" void kernel_launch(void* const* d_in, const int* in_sizes, int n_in,
                              void* d_out, int out_size)
{
    const int base = (n_in >= 19) ? 2 : 0;
    const float* x         = (const float*)d_in[0];
    const int*   rel_index = (const int*)  d_in[1 + base];
    const float* ln1_g     = (const float*)d_in[2 + base];
    const float* ln1_b     = (const float*)d_in[3 + base];
    const float* w_qkv     = (const float*)d_in[4 + base];
    const float* w_proj    = (const float*)d_in[5 + base];
    const float* b_proj    = (const float*)d_in[6 + base];
    const float* rel_table = (const float*)d_in[7 + base];
    const float* gbias     = (const float*)d_in[8 + base];
    const float* ln2_g     = (const float*)d_in[9 + base];
    const float* ln2_b     = (const float*)d_in[10 + base];
    const float* w_pw1     = (const float*)d_in[11 + base];
    const float* b_pw1     = (const float*)d_in[12 + base];
    const float* w_dw      = (const float*)d_in[13 + base];
    const float* b_dw      = (const float*)d_in[14 + base];
    const float* w_pw2     = (const float*)d_in[15 + base];
    const float* b_pw2     = (const float*)d_in[16 + base];
    float* out = (float*)d_out;

    void *p_ln2, *p_h1, *p_h2, *p_x1, *p_ln1, *p_qkvh, *p_atth, *p_wh;
    cudaGetSymbolAddress(&p_ln2, g_ln2);
    cudaGetSymbolAddress(&p_h1,  g_h1);
    cudaGetSymbolAddress(&p_h2,  g_h2);
    cudaGetSymbolAddress(&p_x1,  g_x1);
    cudaGetSymbolAddress(&p_ln1, g_ln1);
    cudaGetSymbolAddress(&p_qkvh, g_qkvh);
    cudaGetSymbolAddress(&p_atth, g_atth);
    cudaGetSymbolAddress(&p_wh,  g_wh);
    __half* wh = (__half*)p_wh;

    // allow 60KB dynamic smem on all GEMM instantiations (host-side, capture-safe)
    static bool attr_done = false;
    if (!attr_done) {
        cudaFuncSetAttribute(mma_gemm_h<true, true, false, true, false>,
                             cudaFuncAttributeMaxDynamicSharedMemorySize, GEMM_SMEM);
        cudaFuncSetAttribute(mma_gemm_h<false, true, true, false, false>,
                             cudaFuncAttributeMaxDynamicSharedMemorySize, GEMM_SMEM);
        cudaFuncSetAttribute(mma_gemm_h<false, false, false, true, true>,
                             cudaFuncAttributeMaxDynamicSharedMemorySize, GEMM_SMEM);
        attr_done = true;
    }

    w2h_all_kernel<<<(Q_END + 255) / 256, 256>>>(w_qkv, w_pw1, w_pw2, w_proj, wh);
    bias_kernel<<<dim3(32, 12), 256>>>(rel_index, rel_table, gbias);

    // 1) x1 = x + MLP(LN2(x))
    ln_kernel<<<M_, 128>>>(x, ln2_g, ln2_b, (__half*)p_ln2);
    mma_gemm_h<true, true, false, true, false><<<dim3(HID_ / 128, M_ / 128), 256, GEMM_SMEM>>>(
        (const __half*)p_ln2, wh + OFF_PW1, b_pw1, nullptr, p_h1, M_, HID_, C_);
    dwconv_kernel<<<dim3(N_, B_), 384>>>(
        (const __half*)p_h1, (__half*)p_h2, w_dw, b_dw);
    mma_gemm_h<false, true, true, false, false><<<dim3(C_ / 128, M_ / 128), 256, GEMM_SMEM>>>(
        (const __half*)p_h2, wh + OFF_PW2, b_pw2, x, p_x1, M_, C_, HID_);

    // 2) out = x1 + Attn(LN1(x1))
    ln_kernel<<<M_, 128>>>((const float*)p_x1, ln1_g, ln1_b, (__half*)p_ln1);
    mma_gemm_h<false, false, false, true, true><<<dim3(1152 / 128, M_ / 128), 256, GEMM_SMEM>>>(
        (const __half*)p_ln1, wh + OFF_QKV, nullptr, nullptr, p_qkvh, M_, 1152, C_);
    attn_mma_kernel<<<dim3(N_ / 128, H_, B_), 256>>>(
        (const __half*)p_qkvh, (__half*)p_atth);
    mma_gemm_h<false, true, true, false, false><<<dim3(C_ / 128, M_ / 128), 256, GEMM_SMEM>>>(
        (const __half*)p_atth, wh + OFF_PROJ, b_proj, (const float*)p_x1, out, M_, C_, C_);
}

// round 9
// speedup vs baseline: 5.3251x; 1.0205x over previous
#include <cuda_runtime.h>
#include <cuda_fp16.h>
#include <math.h>
#include <stdint.h>

// Problem constants
#define B_  8
#define N_  1024
#define C_  384
#define H_  12
#define HD_ 32
#define HID_ 768
#define M_  (B_ * N_)
#define NREL_ 3969
#define SCALE_ 0.17677669529663687f

// NOTE: harness PTX target is sm_103 (no 'a') -> tcgen05.* unavailable.
// All tensor work stays on mma.sync (HMMA).

__device__ __forceinline__ float gelu_f(float v) {
    return 0.5f * v * (1.0f + erff(v * 0.70710678118654752f));
}

__device__ __forceinline__ void mma_f16(float* c, const uint32_t* a, const uint32_t* b) {
    asm volatile(
        "mma.sync.aligned.m16n8k16.row.col.f32.f16.f16.f32 "
        "{%0,%1,%2,%3}, {%4,%5,%6,%7}, {%8,%9}, {%0,%1,%2,%3};"
        : "+f"(c[0]), "+f"(c[1]), "+f"(c[2]), "+f"(c[3])
        : "r"(a[0]), "r"(a[1]), "r"(a[2]), "r"(a[3]), "r"(b[0]), "r"(b[1]));
}

__device__ __forceinline__ void ldsm_x4(uint32_t* r, const __half* p) {
    uint32_t addr = (uint32_t)__cvta_generic_to_shared(p);
    asm volatile("ldmatrix.sync.aligned.m8n8.x4.shared.b16 {%0,%1,%2,%3}, [%4];"
                 : "=r"(r[0]), "=r"(r[1]), "=r"(r[2]), "=r"(r[3]) : "r"(addr));
}

__device__ __forceinline__ void ldsm_x2_t(uint32_t& r0, uint32_t& r1, const __half* p) {
    uint32_t addr = (uint32_t)__cvta_generic_to_shared(p);
    asm volatile("ldmatrix.sync.aligned.m8n8.x2.trans.shared.b16 {%0,%1}, [%2];"
                 : "=r"(r0), "=r"(r1) : "r"(addr));
}

// ---------------- scratch ----------------
__device__ __align__(16) __half g_ln2[M_ * C_];
__device__ __align__(16) __half g_h1 [M_ * HID_];
__device__ __align__(16) __half g_h2 [M_ * HID_];
__device__ float g_x1 [M_ * C_];
__device__ __align__(16) __half g_ln1[M_ * C_];
__device__ __align__(16) __half g_qkvh[M_ * 3 * C_];
__device__ __align__(16) __half g_atth[M_ * C_];
__device__ __align__(16) __half g_biash[H_ * N_ * N_];
__device__ __align__(16) __half g_wh[1179648];
#define OFF_QKV  0
#define OFF_PW1  442368
#define OFF_PW2  737280
#define OFF_PROJ 1032192
#define Q_QKV  110592
#define Q_PW1  184320
#define Q_PW2  258048
#define Q_END  294912

// ---------------- merged weight fp32 -> fp16 ----------------
__global__ __launch_bounds__(256) void w2h_all_kernel(
    const float* __restrict__ s_qkv, const float* __restrict__ s_pw1,
    const float* __restrict__ s_pw2, const float* __restrict__ s_proj,
    __half* __restrict__ dst)
{
    const int i = blockIdx.x * 256 + threadIdx.x;
    if (i >= Q_END) return;
    const float* src; int local;
    if (i < Q_QKV)      { src = s_qkv;  local = i; }
    else if (i < Q_PW1) { src = s_pw1;  local = i - Q_QKV; }
    else if (i < Q_PW2) { src = s_pw2;  local = i - Q_PW1; }
    else                { src = s_proj; local = i - Q_PW2; }
    const float4 v = ((const float4*)src)[local];
    __half2 h0 = __floats2half2_rn(v.x, v.y);
    __half2 h1 = __floats2half2_rn(v.z, v.w);
    uint2 u; u.x = *(uint32_t*)&h0; u.y = *(uint32_t*)&h1;
    *(uint2*)(dst + (size_t)i * 4) = u;
}

// ---------------- LayerNorm (half output) ----------------
__global__ __launch_bounds__(128) void ln_kernel(
    const float* __restrict__ in, const float* __restrict__ g,
    const float* __restrict__ bta, __half* __restrict__ out)
{
    const int row = blockIdx.x;
    const int t = threadIdx.x;
    const float* xr = in + (size_t)row * C_;
    float v0 = xr[t], v1 = xr[t + 128], v2 = xr[t + 256];
    float s = v0 + v1 + v2;
    __shared__ float red[4], red2[4];
    #pragma unroll
    for (int o = 16; o; o >>= 1) s += __shfl_xor_sync(0xffffffffu, s, o);
    if ((t & 31) == 0) red[t >> 5] = s;
    __syncthreads();
    const float mean = (red[0] + red[1] + red[2] + red[3]) * (1.0f / C_);
    const float d0 = v0 - mean, d1 = v1 - mean, d2 = v2 - mean;
    float q = d0 * d0 + d1 * d1 + d2 * d2;
    #pragma unroll
    for (int o = 16; o; o >>= 1) q += __shfl_xor_sync(0xffffffffu, q, o);
    if ((t & 31) == 0) red2[t >> 5] = q;
    __syncthreads();
    const float var = (red2[0] + red2[1] + red2[2] + red2[3]) * (1.0f / C_);
    const float inv = rsqrtf(var + 1e-5f);
    __half* orow = out + (size_t)row * C_;
    orow[t]       = __float2half_rn(d0 * inv * g[t]       + bta[t]);
    orow[t + 128] = __float2half_rn(d1 * inv * g[t + 128] + bta[t + 128]);
    orow[t + 256] = __float2half_rn(d2 * inv * g[t + 256] + bta[t + 256]);
}

// ---------------- fp16 GEMM: 4-stage cp.async, 1 barrier/iter ---------------
#define SMSH 40
#define GEMM_SMEM (4 * 128 * SMSH * 2 * 2)   // 81920 bytes
template<bool GELU, bool HASB, bool RES, bool OUTH, bool QSC>
__global__ __launch_bounds__(256, 2) void mma_gemm_h(
    const __half* __restrict__ A, const __half* __restrict__ W,
    const float* __restrict__ bias, const float* __restrict__ res,
    void* __restrict__ Cv, int M, int Nd, int K)
{
    extern __shared__ __half dsm[];
    __half* Asb = dsm;
    __half* Bsb = dsm + 4 * 128 * SMSH;
    const int tid  = threadIdx.x;
    const int lane = tid & 31, warp = tid >> 5;
    const int wm = warp >> 2, wn = warp & 3;
    const int lq = lane >> 2, lr = lane & 3;
    const int bm = blockIdx.y * 128, bn = blockIdx.x * 128;
    const int ntiles = K >> 5;

    const int lrow0 = tid >> 2, lc8 = (tid & 3) * 8;
    const int lrow1 = (tid + 256) >> 2;

    const int arow = ((lane >> 3) & 1) * 8 + (lane & 7);
    const int acol = (lane >> 4) * 8;
    const int brow = ((lane >> 4) << 3) + (lane & 7);
    const int bcol = ((lane >> 3) & 1) * 8;

    #define ISSUE(kt, buf)                                                       \
    {                                                                            \
        __half* asb = Asb + (buf) * 128 * SMSH;                                  \
        __half* bsb = Bsb + (buf) * 128 * SMSH;                                  \
        const __half* ag0 = A + (size_t)(bm + lrow0) * K + (kt) * 32 + lc8;      \
        const __half* wg0 = W + (size_t)(bn + lrow0) * K + (kt) * 32 + lc8;      \
        const __half* ag1 = A + (size_t)(bm + lrow1) * K + (kt) * 32 + lc8;      \
        const __half* wg1 = W + (size_t)(bn + lrow1) * K + (kt) * 32 + lc8;      \
        uint32_t sa0 = (uint32_t)__cvta_generic_to_shared(&asb[lrow0 * SMSH + lc8]); \
        uint32_t sb0 = (uint32_t)__cvta_generic_to_shared(&bsb[lrow0 * SMSH + lc8]); \
        uint32_t sa1 = (uint32_t)__cvta_generic_to_shared(&asb[lrow1 * SMSH + lc8]); \
        uint32_t sb1 = (uint32_t)__cvta_generic_to_shared(&bsb[lrow1 * SMSH + lc8]); \
        asm volatile("cp.async.cg.shared.global [%0], [%1], 16;" :: "r"(sa0), "l"(ag0)); \
        asm volatile("cp.async.cg.shared.global [%0], [%1], 16;" :: "r"(sb0), "l"(wg0)); \
        asm volatile("cp.async.cg.shared.global [%0], [%1], 16;" :: "r"(sa1), "l"(ag1)); \
        asm volatile("cp.async.cg.shared.global [%0], [%1], 16;" :: "r"(sb1), "l"(wg1)); \
        asm volatile("cp.async.commit_group;");                                  \
    }

    float acc[4][4][4] = {};
    ISSUE(0, 0);
    if (ntiles > 1) ISSUE(1, 1);
    if (ntiles > 2) ISSUE(2, 2);

    for (int kt = 0; kt < ntiles; kt++) {
        if (kt + 2 < ntiles)      asm volatile("cp.async.wait_group 2;");
        else if (kt + 1 < ntiles) asm volatile("cp.async.wait_group 1;");
        else                      asm volatile("cp.async.wait_group 0;");
        __syncthreads();
        if (kt + 3 < ntiles) ISSUE(kt + 3, (kt + 3) & 3);

        const __half* as = Asb + (kt & 3) * 128 * SMSH;
        const __half* bs = Bsb + (kt & 3) * 128 * SMSH;
        #pragma unroll
        for (int ks = 0; ks < 2; ks++) {
            const int c = ks * 16;
            uint32_t af[4][4], bf[4][2];
            #pragma unroll
            for (int mt = 0; mt < 4; mt++)
                ldsm_x4(af[mt], &as[(wm * 64 + mt * 16 + arow) * SMSH + c + acol]);
            #pragma unroll
            for (int np = 0; np < 2; np++) {
                uint32_t tmp[4];
                ldsm_x4(tmp, &bs[(wn * 32 + np * 16 + brow) * SMSH + c + bcol]);
                bf[np * 2][0] = tmp[0]; bf[np * 2][1] = tmp[1];
                bf[np * 2 + 1][0] = tmp[2]; bf[np * 2 + 1][1] = tmp[3];
            }
            #pragma unroll
            for (int mt = 0; mt < 4; mt++)
                #pragma unroll
                for (int nt = 0; nt < 4; nt++)
                    mma_f16(acc[mt][nt], af[mt], bf[nt]);
        }
    }
    #undef ISSUE

    #pragma unroll
    for (int mt = 0; mt < 4; mt++) {
        #pragma unroll
        for (int nt = 0; nt < 4; nt++) {
            const int row = bm + wm * 64 + mt * 16 + lq;
            const int col = bn + wn * 32 + nt * 8 + lr * 2;
            #pragma unroll
            for (int half = 0; half < 2; half++) {
                const int r = row + half * 8;
                float v0 = acc[mt][nt][half * 2 + 0];
                float v1 = acc[mt][nt][half * 2 + 1];
                if (HASB) { v0 += bias[col]; v1 += bias[col + 1]; }
                if (GELU) { v0 = gelu_f(v0); v1 = gelu_f(v1); }
                if (RES) {
                    const float* Rr = res + (size_t)r * Nd + col;
                    v0 += Rr[0]; v1 += Rr[1];
                }
                if (OUTH) {
                    if (QSC && col < 384) { v0 *= SCALE_; v1 *= SCALE_; }
                    __half2 hv = __floats2half2_rn(v0, v1);
                    *(__half2*)((__half*)Cv + (size_t)r * Nd + col) = hv;
                } else {
                    *(float2*)((float*)Cv + (size_t)r * Nd + col) = make_float2(v0, v1);
                }
            }
        }
    }
}

// ---------------- depthwise 3x3 dil-2 conv + GELU ---------------------------
__global__ __launch_bounds__(384) void dwconv_kernel(
    const __half* __restrict__ h1, __half* __restrict__ h2,
    const float* __restrict__ w, const float* __restrict__ bias)
{
    const int n = blockIdx.x;
    const int b = blockIdx.y;
    const int y = n >> 5, x = n & 31;
    const size_t base = (size_t)b * N_ * HID_;
    const int c0 = threadIdx.x * 2;

    float2 acc = make_float2(bias[c0], bias[c0 + 1]);
    const float* w0 = w + c0 * 9;
    const float* w1 = w + (c0 + 1) * 9;

    #pragma unroll
    for (int i = 0; i < 3; i++) {
        const int yy = y + 2 * i - 2;
        if (yy < 0 || yy > 31) continue;
        #pragma unroll
        for (int j = 0; j < 3; j++) {
            const int xx = x + 2 * j - 2;
            if (xx < 0 || xx > 31) continue;
            const float2 v = __half22float2(
                *(const __half2*)(h1 + base + (size_t)(yy * 32 + xx) * HID_ + c0));
            acc.x += w0[i * 3 + j] * v.x;
            acc.y += w1[i * 3 + j] * v.y;
        }
    }
    *(__half2*)(h2 + base + (size_t)n * HID_ + c0) =
        __floats2half2_rn(gelu_f(acc.x), gelu_f(acc.y));
}

// ---------------- bias precompute (half output) ----------------
__global__ __launch_bounds__(256) void bias_kernel(
    const int* __restrict__ rel_index, const float* __restrict__ rel_table,
    const float* __restrict__ gb)
{
    __shared__ float tab[NREL_];
    const int h = blockIdx.y;
    const int q0 = blockIdx.x * 32;
    for (int i = threadIdx.x; i < NREL_; i += 256) tab[i] = rel_table[i * H_ + h];
    __syncthreads();
    __half* out = g_biash + (size_t)h * (N_ * N_);
    for (int e = threadIdx.x; e < 32 * 512; e += 256) {
        const int q = q0 + (e >> 9);
        const int k = (e & 511) * 2;
        const size_t idx = (size_t)q * N_ + k;
        const __half2 v = __floats2half2_rn(
            tab[rel_index[idx]] + gb[idx],
            tab[rel_index[idx + 1]] + gb[idx + 1]);
        *(__half2*)&out[idx] = v;
    }
}

// ---------------- fp16 flash attention: P kept in registers -----------------
// S accumulator fragment (m16n8 C layout) == A-operand fragment (m16n8k16)
// after packing: a0=(c0,c1) row lq, a1=(c2,c3) row lq+8, a2/a3 = next 8-col frag.
__global__ __launch_bounds__(256) void attn_mma_kernel(
    const __half* __restrict__ qkv, __half* __restrict__ att)
{
    const int q0 = blockIdx.x * 128;
    const int h  = blockIdx.y;
    const int b  = blockIdx.z;
    const int tid = threadIdx.x;
    const int lane = tid & 31, w = tid >> 5;
    const int lq = lane >> 2;
    const int lr = lane & 3;

    __shared__ __half Ks[2][64][SMSH];
    __shared__ __half Vs[2][64][SMSH];

    const size_t qbase = (size_t)b * N_ * 1152;
    const int kl = tid >> 2, d8 = (tid & 3) * 8;

    #define AISSUE(kt, buf)                                                      \
    {                                                                            \
        const __half* src = qkv + qbase + (size_t)((kt) * 64 + kl) * 1152 + h * 32 + d8; \
        uint32_t sk = (uint32_t)__cvta_generic_to_shared(&Ks[buf][kl][d8]);      \
        uint32_t sv = (uint32_t)__cvta_generic_to_shared(&Vs[buf][kl][d8]);      \
        asm volatile("cp.async.cg.shared.global [%0], [%1], 16;" :: "r"(sk), "l"(src + 384)); \
        asm volatile("cp.async.cg.shared.global [%0], [%1], 16;" :: "r"(sv), "l"(src + 768)); \
        asm volatile("cp.async.commit_group;");                                  \
    }

    const int brow = ((lane >> 4) << 3) + (lane & 7);
    const int bcol = ((lane >> 3) & 1) * 8;

    uint32_t qa[2][4];
    const int br0 = q0 + w * 16 + lq;
    {
        const __half* qp  = qkv + qbase + (size_t)br0 * 1152 + h * 32;
        const __half* qp8 = qp + 8 * 1152;
        #pragma unroll
        for (int ks = 0; ks < 2; ks++) {
            const int c = ks * 16 + 2 * lr;
            qa[ks][0] = *(const uint32_t*)(qp  + c);
            qa[ks][1] = *(const uint32_t*)(qp8 + c);
            qa[ks][2] = *(const uint32_t*)(qp  + c + 8);
            qa[ks][3] = *(const uint32_t*)(qp8 + c + 8);
        }
    }

    float o[4][4] = {};
    float m0 = -1e30f, m1 = -1e30f, l0 = 0.0f, l1 = 0.0f;
    const __half* bh0 = g_biash + (size_t)h * N_ * N_ + (size_t)br0 * N_;
    const __half* bh1 = bh0 + (size_t)8 * N_;

    AISSUE(0, 0);
    for (int kt = 0; kt < 16; kt++) {
        asm volatile("cp.async.wait_group 0;");
        __syncthreads();
        if (kt < 15) AISSUE(kt + 1, (kt + 1) & 1);

        const int buf = kt & 1;
        const int k0 = kt * 64;

        // S = Q @ K^T
        float s[8][4];
        #pragma unroll
        for (int nf = 0; nf < 8; nf++)
            s[nf][0] = s[nf][1] = s[nf][2] = s[nf][3] = 0.0f;
        #pragma unroll
        for (int ks = 0; ks < 2; ks++) {
            const int c = ks * 16;
            uint32_t kf[8][2];
            #pragma unroll
            for (int np = 0; np < 4; np++) {
                uint32_t tmp[4];
                ldsm_x4(tmp, &Ks[buf][np * 16 + brow][c + bcol]);
                kf[np * 2][0] = tmp[0]; kf[np * 2][1] = tmp[1];
                kf[np * 2 + 1][0] = tmp[2]; kf[np * 2 + 1][1] = tmp[3];
            }
            #pragma unroll
            for (int nf = 0; nf < 8; nf++)
                mma_f16(s[nf], qa[ks], kf[nf]);
        }

        // + bias, row max
        float nm0 = m0, nm1 = m1;
        #pragma unroll
        for (int nf = 0; nf < 8; nf++) {
            const int col = k0 + nf * 8 + lr * 2;
            const float2 b0v = __half22float2(*(const __half2*)(bh0 + col));
            const float2 b1v = __half22float2(*(const __half2*)(bh1 + col));
            s[nf][0] += b0v.x; s[nf][1] += b0v.y;
            s[nf][2] += b1v.x; s[nf][3] += b1v.y;
            nm0 = fmaxf(nm0, fmaxf(s[nf][0], s[nf][1]));
            nm1 = fmaxf(nm1, fmaxf(s[nf][2], s[nf][3]));
        }
        nm0 = fmaxf(nm0, __shfl_xor_sync(0xffffffffu, nm0, 1));
        nm0 = fmaxf(nm0, __shfl_xor_sync(0xffffffffu, nm0, 2));
        nm1 = fmaxf(nm1, __shfl_xor_sync(0xffffffffu, nm1, 1));
        nm1 = fmaxf(nm1, __shfl_xor_sync(0xffffffffu, nm1, 2));

        const float c0 = __expf(m0 - nm0), c1 = __expf(m1 - nm1);
        m0 = nm0; m1 = nm1; l0 *= c0; l1 *= c1;
        #pragma unroll
        for (int nf = 0; nf < 4; nf++) {
            o[nf][0] *= c0; o[nf][1] *= c0;
            o[nf][2] *= c1; o[nf][3] *= c1;
        }

        // exp -> P packed straight into A-operand registers (no smem)
        uint32_t ph[8][2];
        float a0 = 0.0f, a1 = 0.0f;
        #pragma unroll
        for (int nf = 0; nf < 8; nf++) {
            const float p0 = __expf(s[nf][0] - nm0);
            const float p1 = __expf(s[nf][1] - nm0);
            const float p2 = __expf(s[nf][2] - nm1);
            const float p3 = __expf(s[nf][3] - nm1);
            a0 += p0 + p1; a1 += p2 + p3;
            __half2 h01 = __floats2half2_rn(p0, p1);
            __half2 h23 = __floats2half2_rn(p2, p3);
            ph[nf][0] = *(uint32_t*)&h01;   // row lq,   cols 2lr..+1
            ph[nf][1] = *(uint32_t*)&h23;   // row lq+8, cols 2lr..+1
        }
        a0 += __shfl_xor_sync(0xffffffffu, a0, 1);
        a0 += __shfl_xor_sync(0xffffffffu, a0, 2);
        a1 += __shfl_xor_sync(0xffffffffu, a1, 1);
        a1 += __shfl_xor_sync(0xffffffffu, a1, 2);
        l0 += a0; l1 += a1;

        // O += P @ V : P fragments from registers, V via ldmatrix.trans
        #pragma unroll
        for (int kf2 = 0; kf2 < 4; kf2++) {
            uint32_t pa[4];
            pa[0] = ph[2 * kf2][0];
            pa[1] = ph[2 * kf2][1];
            pa[2] = ph[2 * kf2 + 1][0];
            pa[3] = ph[2 * kf2 + 1][1];
            #pragma unroll
            for (int nf = 0; nf < 4; nf++) {
                uint32_t b0r, b1r;
                ldsm_x2_t(b0r, b1r, &Vs[buf][kf2 * 16 + (lane & 15)][nf * 8]);
                uint32_t bfr[2] = { b0r, b1r };
                mma_f16(o[nf], pa, bfr);
            }
        }
    }
    #undef AISSUE

    const float inv0 = 1.0f / l0, inv1 = 1.0f / l1;
    #pragma unroll
    for (int nf = 0; nf < 4; nf++) {
        const int col = h * 32 + nf * 8 + lr * 2;
        __half* o0 = att + ((size_t)b * N_ + br0) * C_ + col;
        __half* o1 = att + ((size_t)b * N_ + br0 + 8) * C_ + col;
        *(__half2*)o0 = __floats2half2_rn(o[nf][0] * inv0, o[nf][1] * inv0);
        *(__half2*)o1 = __floats2half2_rn(o[nf][2] * inv1, o[nf][3] * inv1);
    }
}

// ---------------- launch ----------------
extern "C" void kernel_launch(void* const* d_in, const int* in_sizes, int n_in,
                              void* d_out, int out_size)
{
    const int base = (n_in >= 19) ? 2 : 0;
    const float* x         = (const float*)d_in[0];
    const int*   rel_index = (const int*)  d_in[1 + base];
    const float* ln1_g     = (const float*)d_in[2 + base];
    const float* ln1_b     = (const float*)d_in[3 + base];
    const float* w_qkv     = (const float*)d_in[4 + base];
    const float* w_proj    = (const float*)d_in[5 + base];
    const float* b_proj    = (const float*)d_in[6 + base];
    const float* rel_table = (const float*)d_in[7 + base];
    const float* gbias     = (const float*)d_in[8 + base];
    const float* ln2_g     = (const float*)d_in[9 + base];
    const float* ln2_b     = (const float*)d_in[10 + base];
    const float* w_pw1     = (const float*)d_in[11 + base];
    const float* b_pw1     = (const float*)d_in[12 + base];
    const float* w_dw      = (const float*)d_in[13 + base];
    const float* b_dw      = (const float*)d_in[14 + base];
    const float* w_pw2     = (const float*)d_in[15 + base];
    const float* b_pw2     = (const float*)d_in[16 + base];
    float* out = (float*)d_out;

    void *p_ln2, *p_h1, *p_h2, *p_x1, *p_ln1, *p_qkvh, *p_atth, *p_wh;
    cudaGetSymbolAddress(&p_ln2, g_ln2);
    cudaGetSymbolAddress(&p_h1,  g_h1);
    cudaGetSymbolAddress(&p_h2,  g_h2);
    cudaGetSymbolAddress(&p_x1,  g_x1);
    cudaGetSymbolAddress(&p_ln1, g_ln1);
    cudaGetSymbolAddress(&p_qkvh, g_qkvh);
    cudaGetSymbolAddress(&p_atth, g_atth);
    cudaGetSymbolAddress(&p_wh,  g_wh);
    __half* wh = (__half*)p_wh;

    static bool attr_done = false;
    if (!attr_done) {
        cudaFuncSetAttribute(mma_gemm_h<true, true, false, true, false>,
                             cudaFuncAttributeMaxDynamicSharedMemorySize, GEMM_SMEM);
        cudaFuncSetAttribute(mma_gemm_h<false, true, true, false, false>,
                             cudaFuncAttributeMaxDynamicSharedMemorySize, GEMM_SMEM);
        cudaFuncSetAttribute(mma_gemm_h<false, false, false, true, true>,
                             cudaFuncAttributeMaxDynamicSharedMemorySize, GEMM_SMEM);
        attr_done = true;
    }

    w2h_all_kernel<<<(Q_END + 255) / 256, 256>>>(w_qkv, w_pw1, w_pw2, w_proj, wh);
    bias_kernel<<<dim3(32, 12), 256>>>(rel_index, rel_table, gbias);

    // 1) x1 = x + MLP(LN2(x))
    ln_kernel<<<M_, 128>>>(x, ln2_g, ln2_b, (__half*)p_ln2);
    mma_gemm_h<true, true, false, true, false><<<dim3(HID_ / 128, M_ / 128), 256, GEMM_SMEM>>>(
        (const __half*)p_ln2, wh + OFF_PW1, b_pw1, nullptr, p_h1, M_, HID_, C_);
    dwconv_kernel<<<dim3(N_, B_), 384>>>(
        (const __half*)p_h1, (__half*)p_h2, w_dw, b_dw);
    mma_gemm_h<false, true, true, false, false><<<dim3(C_ / 128, M_ / 128), 256, GEMM_SMEM>>>(
        (const __half*)p_h2, wh + OFF_PW2, b_pw2, x, p_x1, M_, C_, HID_);

    // 2) out = x1 + Attn(LN1(x1))
    ln_kernel<<<M_, 128>>>((const float*)p_x1, ln1_g, ln1_b, (__half*)p_ln1);
    mma_gemm_h<false, false, false, true, true><<<dim3(1152 / 128, M_ / 128), 256, GEMM_SMEM>>>(
        (const __half*)p_ln1, wh + OFF_QKV, nullptr, nullptr, p_qkvh, M_, 1152, C_);
    attn_mma_kernel<<<dim3(N_ / 128, H_, B_), 256>>>(
        (const __half*)p_qkvh, (__half*)p_atth);
    mma_gemm_h<false, true, true, false, false><<<dim3(C_ / 128, M_ / 128), 256, GEMM_SMEM>>>(
        (const __half*)p_atth, wh + OFF_PROJ, b_proj, (const float*)p_x1, out, M_, C_, C_);
}

// round 10
// speedup vs baseline: 5.4112x; 1.0162x over previous
#include <cuda_runtime.h>
#include <cuda_fp16.h>
#include <math.h>
#include <stdint.h>

// Problem constants
#define B_  8
#define N_  1024
#define C_  384
#define H_  12
#define HD_ 32
#define HID_ 768
#define M_  (B_ * N_)
#define NREL_ 3969
#define SCALE_ 0.17677669529663687f
#define LOG2E_ 1.4426950408889634f

// NOTE: harness PTX target is sm_103 (no 'a') -> tcgen05.* unavailable.
// All tensor work stays on mma.sync (HMMA).

__device__ __forceinline__ float gelu_f(float v) {
    return 0.5f * v * (1.0f + erff(v * 0.70710678118654752f));
}

__device__ __forceinline__ void mma_f16(float* c, const uint32_t* a, const uint32_t* b) {
    asm volatile(
        "mma.sync.aligned.m16n8k16.row.col.f32.f16.f16.f32 "
        "{%0,%1,%2,%3}, {%4,%5,%6,%7}, {%8,%9}, {%0,%1,%2,%3};"
        : "+f"(c[0]), "+f"(c[1]), "+f"(c[2]), "+f"(c[3])
        : "r"(a[0]), "r"(a[1]), "r"(a[2]), "r"(a[3]), "r"(b[0]), "r"(b[1]));
}

__device__ __forceinline__ void ldsm_x4(uint32_t* r, const __half* p) {
    uint32_t addr = (uint32_t)__cvta_generic_to_shared(p);
    asm volatile("ldmatrix.sync.aligned.m8n8.x4.shared.b16 {%0,%1,%2,%3}, [%4];"
                 : "=r"(r[0]), "=r"(r[1]), "=r"(r[2]), "=r"(r[3]) : "r"(addr));
}

__device__ __forceinline__ void ldsm_x2_t(uint32_t& r0, uint32_t& r1, const __half* p) {
    uint32_t addr = (uint32_t)__cvta_generic_to_shared(p);
    asm volatile("ldmatrix.sync.aligned.m8n8.x2.trans.shared.b16 {%0,%1}, [%2];"
                 : "=r"(r0), "=r"(r1) : "r"(addr));
}

// ---------------- scratch ----------------
__device__ __align__(16) __half g_ln2[M_ * C_];
__device__ __align__(16) __half g_h1 [M_ * HID_];
__device__ __align__(16) __half g_h2 [M_ * HID_];
__device__ float g_x1 [M_ * C_];
__device__ __align__(16) __half g_ln1[M_ * C_];
__device__ __align__(16) __half g_qkvh[M_ * 3 * C_];
__device__ __align__(16) __half g_atth[M_ * C_];
__device__ __align__(16) __half g_biash[H_ * N_ * N_];
__device__ __align__(16) __half g_wh[1179648];
#define OFF_QKV  0
#define OFF_PW1  442368
#define OFF_PW2  737280
#define OFF_PROJ 1032192
#define Q_QKV  110592
#define Q_PW1  184320
#define Q_PW2  258048
#define Q_END  294912

// ---------------- merged weight fp32 -> fp16 ----------------
__global__ __launch_bounds__(256) void w2h_all_kernel(
    const float* __restrict__ s_qkv, const float* __restrict__ s_pw1,
    const float* __restrict__ s_pw2, const float* __restrict__ s_proj,
    __half* __restrict__ dst)
{
    const int i = blockIdx.x * 256 + threadIdx.x;
    if (i >= Q_END) return;
    const float* src; int local;
    if (i < Q_QKV)      { src = s_qkv;  local = i; }
    else if (i < Q_PW1) { src = s_pw1;  local = i - Q_QKV; }
    else if (i < Q_PW2) { src = s_pw2;  local = i - Q_PW1; }
    else                { src = s_proj; local = i - Q_PW2; }
    const float4 v = ((const float4*)src)[local];
    __half2 h0 = __floats2half2_rn(v.x, v.y);
    __half2 h1 = __floats2half2_rn(v.z, v.w);
    uint2 u; u.x = *(uint32_t*)&h0; u.y = *(uint32_t*)&h1;
    *(uint2*)(dst + (size_t)i * 4) = u;
}

// ---------------- LayerNorm (half output) ----------------
__global__ __launch_bounds__(128) void ln_kernel(
    const float* __restrict__ in, const float* __restrict__ g,
    const float* __restrict__ bta, __half* __restrict__ out)
{
    const int row = blockIdx.x;
    const int t = threadIdx.x;
    const float* xr = in + (size_t)row * C_;
    float v0 = xr[t], v1 = xr[t + 128], v2 = xr[t + 256];
    float s = v0 + v1 + v2;
    __shared__ float red[4], red2[4];
    #pragma unroll
    for (int o = 16; o; o >>= 1) s += __shfl_xor_sync(0xffffffffu, s, o);
    if ((t & 31) == 0) red[t >> 5] = s;
    __syncthreads();
    const float mean = (red[0] + red[1] + red[2] + red[3]) * (1.0f / C_);
    const float d0 = v0 - mean, d1 = v1 - mean, d2 = v2 - mean;
    float q = d0 * d0 + d1 * d1 + d2 * d2;
    #pragma unroll
    for (int o = 16; o; o >>= 1) q += __shfl_xor_sync(0xffffffffu, q, o);
    if ((t & 31) == 0) red2[t >> 5] = q;
    __syncthreads();
    const float var = (red2[0] + red2[1] + red2[2] + red2[3]) * (1.0f / C_);
    const float inv = rsqrtf(var + 1e-5f);
    __half* orow = out + (size_t)row * C_;
    orow[t]       = __float2half_rn(d0 * inv * g[t]       + bta[t]);
    orow[t + 128] = __float2half_rn(d1 * inv * g[t + 128] + bta[t + 128]);
    orow[t + 256] = __float2half_rn(d2 * inv * g[t + 256] + bta[t + 256]);
}

// ---------------- fp16 GEMM: 4-stage cp.async, 1 barrier/iter ---------------
#define SMSH 40
#define GEMM_SMEM (4 * 128 * SMSH * 2 * 2)   // 81920 bytes
template<bool GELU, bool HASB, bool RES, bool OUTH, bool QSC>
__global__ __launch_bounds__(256, 2) void mma_gemm_h(
    const __half* __restrict__ A, const __half* __restrict__ W,
    const float* __restrict__ bias, const float* __restrict__ res,
    void* __restrict__ Cv, int M, int Nd, int K)
{
    extern __shared__ __half dsm[];
    __half* Asb = dsm;
    __half* Bsb = dsm + 4 * 128 * SMSH;
    const int tid  = threadIdx.x;
    const int lane = tid & 31, warp = tid >> 5;
    const int wm = warp >> 2, wn = warp & 3;
    const int lq = lane >> 2, lr = lane & 3;
    const int bm = blockIdx.y * 128, bn = blockIdx.x * 128;
    const int ntiles = K >> 5;

    const int lrow0 = tid >> 2, lc8 = (tid & 3) * 8;
    const int lrow1 = (tid + 256) >> 2;

    const int arow = ((lane >> 3) & 1) * 8 + (lane & 7);
    const int acol = (lane >> 4) * 8;
    const int brow = ((lane >> 4) << 3) + (lane & 7);
    const int bcol = ((lane >> 3) & 1) * 8;

    #define ISSUE(kt, buf)                                                       \
    {                                                                            \
        __half* asb = Asb + (buf) * 128 * SMSH;                                  \
        __half* bsb = Bsb + (buf) * 128 * SMSH;                                  \
        const __half* ag0 = A + (size_t)(bm + lrow0) * K + (kt) * 32 + lc8;      \
        const __half* wg0 = W + (size_t)(bn + lrow0) * K + (kt) * 32 + lc8;      \
        const __half* ag1 = A + (size_t)(bm + lrow1) * K + (kt) * 32 + lc8;      \
        const __half* wg1 = W + (size_t)(bn + lrow1) * K + (kt) * 32 + lc8;      \
        uint32_t sa0 = (uint32_t)__cvta_generic_to_shared(&asb[lrow0 * SMSH + lc8]); \
        uint32_t sb0 = (uint32_t)__cvta_generic_to_shared(&bsb[lrow0 * SMSH + lc8]); \
        uint32_t sa1 = (uint32_t)__cvta_generic_to_shared(&asb[lrow1 * SMSH + lc8]); \
        uint32_t sb1 = (uint32_t)__cvta_generic_to_shared(&bsb[lrow1 * SMSH + lc8]); \
        asm volatile("cp.async.cg.shared.global [%0], [%1], 16;" :: "r"(sa0), "l"(ag0)); \
        asm volatile("cp.async.cg.shared.global [%0], [%1], 16;" :: "r"(sb0), "l"(wg0)); \
        asm volatile("cp.async.cg.shared.global [%0], [%1], 16;" :: "r"(sa1), "l"(ag1)); \
        asm volatile("cp.async.cg.shared.global [%0], [%1], 16;" :: "r"(sb1), "l"(wg1)); \
        asm volatile("cp.async.commit_group;");                                  \
    }

    float acc[4][4][4] = {};
    ISSUE(0, 0);
    if (ntiles > 1) ISSUE(1, 1);
    if (ntiles > 2) ISSUE(2, 2);

    for (int kt = 0; kt < ntiles; kt++) {
        if (kt + 2 < ntiles)      asm volatile("cp.async.wait_group 2;");
        else if (kt + 1 < ntiles) asm volatile("cp.async.wait_group 1;");
        else                      asm volatile("cp.async.wait_group 0;");
        __syncthreads();
        if (kt + 3 < ntiles) ISSUE(kt + 3, (kt + 3) & 3);

        const __half* as = Asb + (kt & 3) * 128 * SMSH;
        const __half* bs = Bsb + (kt & 3) * 128 * SMSH;
        #pragma unroll
        for (int ks = 0; ks < 2; ks++) {
            const int c = ks * 16;
            uint32_t af[4][4], bf[4][2];
            #pragma unroll
            for (int mt = 0; mt < 4; mt++)
                ldsm_x4(af[mt], &as[(wm * 64 + mt * 16 + arow) * SMSH + c + acol]);
            #pragma unroll
            for (int np = 0; np < 2; np++) {
                uint32_t tmp[4];
                ldsm_x4(tmp, &bs[(wn * 32 + np * 16 + brow) * SMSH + c + bcol]);
                bf[np * 2][0] = tmp[0]; bf[np * 2][1] = tmp[1];
                bf[np * 2 + 1][0] = tmp[2]; bf[np * 2 + 1][1] = tmp[3];
            }
            #pragma unroll
            for (int mt = 0; mt < 4; mt++)
                #pragma unroll
                for (int nt = 0; nt < 4; nt++)
                    mma_f16(acc[mt][nt], af[mt], bf[nt]);
        }
    }
    #undef ISSUE

    #pragma unroll
    for (int mt = 0; mt < 4; mt++) {
        #pragma unroll
        for (int nt = 0; nt < 4; nt++) {
            const int row = bm + wm * 64 + mt * 16 + lq;
            const int col = bn + wn * 32 + nt * 8 + lr * 2;
            #pragma unroll
            for (int half = 0; half < 2; half++) {
                const int r = row + half * 8;
                float v0 = acc[mt][nt][half * 2 + 0];
                float v1 = acc[mt][nt][half * 2 + 1];
                if (HASB) { v0 += bias[col]; v1 += bias[col + 1]; }
                if (GELU) { v0 = gelu_f(v0); v1 = gelu_f(v1); }
                if (RES) {
                    const float* Rr = res + (size_t)r * Nd + col;
                    v0 += Rr[0]; v1 += Rr[1];
                }
                if (OUTH) {
                    if (QSC && col < 384) { v0 *= SCALE_; v1 *= SCALE_; }
                    __half2 hv = __floats2half2_rn(v0, v1);
                    *(__half2*)((__half*)Cv + (size_t)r * Nd + col) = hv;
                } else {
                    *(float2*)((float*)Cv + (size_t)r * Nd + col) = make_float2(v0, v1);
                }
            }
        }
    }
}

// ---------------- depthwise 3x3 dil-2 conv + GELU ---------------------------
__global__ __launch_bounds__(384) void dwconv_kernel(
    const __half* __restrict__ h1, __half* __restrict__ h2,
    const float* __restrict__ w, const float* __restrict__ bias)
{
    const int n = blockIdx.x;
    const int b = blockIdx.y;
    const int y = n >> 5, x = n & 31;
    const size_t base = (size_t)b * N_ * HID_;
    const int c0 = threadIdx.x * 2;

    float2 acc = make_float2(bias[c0], bias[c0 + 1]);
    const float* w0 = w + c0 * 9;
    const float* w1 = w + (c0 + 1) * 9;

    #pragma unroll
    for (int i = 0; i < 3; i++) {
        const int yy = y + 2 * i - 2;
        if (yy < 0 || yy > 31) continue;
        #pragma unroll
        for (int j = 0; j < 3; j++) {
            const int xx = x + 2 * j - 2;
            if (xx < 0 || xx > 31) continue;
            const float2 v = __half22float2(
                *(const __half2*)(h1 + base + (size_t)(yy * 32 + xx) * HID_ + c0));
            acc.x += w0[i * 3 + j] * v.x;
            acc.y += w1[i * 3 + j] * v.y;
        }
    }
    *(__half2*)(h2 + base + (size_t)n * HID_ + c0) =
        __floats2half2_rn(gelu_f(acc.x), gelu_f(acc.y));
}

// ---------------- bias precompute (half output) ----------------
__global__ __launch_bounds__(256) void bias_kernel(
    const int* __restrict__ rel_index, const float* __restrict__ rel_table,
    const float* __restrict__ gb)
{
    __shared__ float tab[NREL_];
    const int h = blockIdx.y;
    const int q0 = blockIdx.x * 32;
    for (int i = threadIdx.x; i < NREL_; i += 256) tab[i] = rel_table[i * H_ + h];
    __syncthreads();
    __half* out = g_biash + (size_t)h * (N_ * N_);
    for (int e = threadIdx.x; e < 32 * 512; e += 256) {
        const int q = q0 + (e >> 9);
        const int k = (e & 511) * 2;
        const size_t idx = (size_t)q * N_ + k;
        const __half2 v = __floats2half2_rn(
            tab[rel_index[idx]] + gb[idx],
            tab[rel_index[idx + 1]] + gb[idx + 1]);
        *(__half2*)&out[idx] = v;
    }
}

// ---------------- fp16 flash attention: reg-P + half2 exp -------------------
// exp path: x=(s-m)*log2e in fp32 FMA -> pack half2 -> one h2exp2 per PAIR
// (halves MUFU.EX2 issue count; P is half-precision anyway for the PV MMA).
__global__ __launch_bounds__(256) void attn_mma_kernel(
    const __half* __restrict__ qkv, __half* __restrict__ att)
{
    const int q0 = blockIdx.x * 128;
    const int h  = blockIdx.y;
    const int b  = blockIdx.z;
    const int tid = threadIdx.x;
    const int lane = tid & 31, w = tid >> 5;
    const int lq = lane >> 2;
    const int lr = lane & 3;

    __shared__ __half Ks[2][64][SMSH];
    __shared__ __half Vs[2][64][SMSH];

    const size_t qbase = (size_t)b * N_ * 1152;
    const int kl = tid >> 2, d8 = (tid & 3) * 8;

    #define AISSUE(kt, buf)                                                      \
    {                                                                            \
        const __half* src = qkv + qbase + (size_t)((kt) * 64 + kl) * 1152 + h * 32 + d8; \
        uint32_t sk = (uint32_t)__cvta_generic_to_shared(&Ks[buf][kl][d8]);      \
        uint32_t sv = (uint32_t)__cvta_generic_to_shared(&Vs[buf][kl][d8]);      \
        asm volatile("cp.async.cg.shared.global [%0], [%1], 16;" :: "r"(sk), "l"(src + 384)); \
        asm volatile("cp.async.cg.shared.global [%0], [%1], 16;" :: "r"(sv), "l"(src + 768)); \
        asm volatile("cp.async.commit_group;");                                  \
    }

    const int brow = ((lane >> 4) << 3) + (lane & 7);
    const int bcol = ((lane >> 3) & 1) * 8;

    uint32_t qa[2][4];
    const int br0 = q0 + w * 16 + lq;
    {
        const __half* qp  = qkv + qbase + (size_t)br0 * 1152 + h * 32;
        const __half* qp8 = qp + 8 * 1152;
        #pragma unroll
        for (int ks = 0; ks < 2; ks++) {
            const int c = ks * 16 + 2 * lr;
            qa[ks][0] = *(const uint32_t*)(qp  + c);
            qa[ks][1] = *(const uint32_t*)(qp8 + c);
            qa[ks][2] = *(const uint32_t*)(qp  + c + 8);
            qa[ks][3] = *(const uint32_t*)(qp8 + c + 8);
        }
    }

    float o[4][4] = {};
    float m0 = -1e30f, m1 = -1e30f, l0 = 0.0f, l1 = 0.0f;
    const __half* bh0 = g_biash + (size_t)h * N_ * N_ + (size_t)br0 * N_;
    const __half* bh1 = bh0 + (size_t)8 * N_;

    AISSUE(0, 0);
    for (int kt = 0; kt < 16; kt++) {
        asm volatile("cp.async.wait_group 0;");
        __syncthreads();
        if (kt < 15) AISSUE(kt + 1, (kt + 1) & 1);

        const int buf = kt & 1;
        const int k0 = kt * 64;

        // S = Q @ K^T
        float s[8][4];
        #pragma unroll
        for (int nf = 0; nf < 8; nf++)
            s[nf][0] = s[nf][1] = s[nf][2] = s[nf][3] = 0.0f;
        #pragma unroll
        for (int ks = 0; ks < 2; ks++) {
            const int c = ks * 16;
            uint32_t kf[8][2];
            #pragma unroll
            for (int np = 0; np < 4; np++) {
                uint32_t tmp[4];
                ldsm_x4(tmp, &Ks[buf][np * 16 + brow][c + bcol]);
                kf[np * 2][0] = tmp[0]; kf[np * 2][1] = tmp[1];
                kf[np * 2 + 1][0] = tmp[2]; kf[np * 2 + 1][1] = tmp[3];
            }
            #pragma unroll
            for (int nf = 0; nf < 8; nf++)
                mma_f16(s[nf], qa[ks], kf[nf]);
        }

        // + bias, row max
        float nm0 = m0, nm1 = m1;
        #pragma unroll
        for (int nf = 0; nf < 8; nf++) {
            const int col = k0 + nf * 8 + lr * 2;
            const float2 b0v = __half22float2(*(const __half2*)(bh0 + col));
            const float2 b1v = __half22float2(*(const __half2*)(bh1 + col));
            s[nf][0] += b0v.x; s[nf][1] += b0v.y;
            s[nf][2] += b1v.x; s[nf][3] += b1v.y;
            nm0 = fmaxf(nm0, fmaxf(s[nf][0], s[nf][1]));
            nm1 = fmaxf(nm1, fmaxf(s[nf][2], s[nf][3]));
        }
        nm0 = fmaxf(nm0, __shfl_xor_sync(0xffffffffu, nm0, 1));
        nm0 = fmaxf(nm0, __shfl_xor_sync(0xffffffffu, nm0, 2));
        nm1 = fmaxf(nm1, __shfl_xor_sync(0xffffffffu, nm1, 1));
        nm1 = fmaxf(nm1, __shfl_xor_sync(0xffffffffu, nm1, 2));

        const float c0 = __expf(m0 - nm0), c1 = __expf(m1 - nm1);
        m0 = nm0; m1 = nm1; l0 *= c0; l1 *= c1;
        #pragma unroll
        for (int nf = 0; nf < 4; nf++) {
            o[nf][0] *= c0; o[nf][1] *= c0;
            o[nf][2] *= c1; o[nf][3] *= c1;
        }

        // exp via half2 MUFU; P packed straight into A-operand registers
        uint32_t ph[8][2];
        float a0 = 0.0f, a1 = 0.0f;
        #pragma unroll
        for (int nf = 0; nf < 8; nf++) {
            const __half2 x01 = __floats2half2_rn((s[nf][0] - nm0) * LOG2E_,
                                                  (s[nf][1] - nm0) * LOG2E_);
            const __half2 x23 = __floats2half2_rn((s[nf][2] - nm1) * LOG2E_,
                                                  (s[nf][3] - nm1) * LOG2E_);
            const __half2 p01 = h2exp2(x01);
            const __half2 p23 = h2exp2(x23);
            const float2 f01 = __half22float2(p01);
            const float2 f23 = __half22float2(p23);
            a0 += f01.x + f01.y;
            a1 += f23.x + f23.y;
            ph[nf][0] = *(const uint32_t*)&p01;   // row lq,   cols 2lr..+1
            ph[nf][1] = *(const uint32_t*)&p23;   // row lq+8, cols 2lr..+1
        }
        a0 += __shfl_xor_sync(0xffffffffu, a0, 1);
        a0 += __shfl_xor_sync(0xffffffffu, a0, 2);
        a1 += __shfl_xor_sync(0xffffffffu, a1, 1);
        a1 += __shfl_xor_sync(0xffffffffu, a1, 2);
        l0 += a0; l1 += a1;

        // O += P @ V : P fragments from registers, V via ldmatrix.trans
        #pragma unroll
        for (int kf2 = 0; kf2 < 4; kf2++) {
            uint32_t pa[4];
            pa[0] = ph[2 * kf2][0];
            pa[1] = ph[2 * kf2][1];
            pa[2] = ph[2 * kf2 + 1][0];
            pa[3] = ph[2 * kf2 + 1][1];
            #pragma unroll
            for (int nf = 0; nf < 4; nf++) {
                uint32_t b0r, b1r;
                ldsm_x2_t(b0r, b1r, &Vs[buf][kf2 * 16 + (lane & 15)][nf * 8]);
                uint32_t bfr[2] = { b0r, b1r };
                mma_f16(o[nf], pa, bfr);
            }
        }
    }
    #undef AISSUE

    const float inv0 = 1.0f / l0, inv1 = 1.0f / l1;
    #pragma unroll
    for (int nf = 0; nf < 4; nf++) {
        const int col = h * 32 + nf * 8 + lr * 2;
        __half* o0 = att + ((size_t)b * N_ + br0) * C_ + col;
        __half* o1 = att + ((size_t)b * N_ + br0 + 8) * C_ + col;
        *(__half2*)o0 = __floats2half2_rn(o[nf][0] * inv0, o[nf][1] * inv0);
        *(__half2*)o1 = __floats2half2_rn(o[nf][2] * inv1, o[nf][3] * inv1);
    }
}

// ---------------- launch ----------------
extern "C" void kernel_launch(void* const* d_in, const int* in_sizes, int n_in,
                              void* d_out, int out_size)
{
    const int base = (n_in >= 19) ? 2 : 0;
    const float* x         = (const float*)d_in[0];
    const int*   rel_index = (const int*)  d_in[1 + base];
    const float* ln1_g     = (const float*)d_in[2 + base];
    const float* ln1_b     = (const float*)d_in[3 + base];
    const float* w_qkv     = (const float*)d_in[4 + base];
    const float* w_proj    = (const float*)d_in[5 + base];
    const float* b_proj    = (const float*)d_in[6 + base];
    const float* rel_table = (const float*)d_in[7 + base];
    const float* gbias     = (const float*)d_in[8 + base];
    const float* ln2_g     = (const float*)d_in[9 + base];
    const float* ln2_b     = (const float*)d_in[10 + base];
    const float* w_pw1     = (const float*)d_in[11 + base];
    const float* b_pw1     = (const float*)d_in[12 + base];
    const float* w_dw      = (const float*)d_in[13 + base];
    const float* b_dw      = (const float*)d_in[14 + base];
    const float* w_pw2     = (const float*)d_in[15 + base];
    const float* b_pw2     = (const float*)d_in[16 + base];
    float* out = (float*)d_out;

    void *p_ln2, *p_h1, *p_h2, *p_x1, *p_ln1, *p_qkvh, *p_atth, *p_wh;
    cudaGetSymbolAddress(&p_ln2, g_ln2);
    cudaGetSymbolAddress(&p_h1,  g_h1);
    cudaGetSymbolAddress(&p_h2,  g_h2);
    cudaGetSymbolAddress(&p_x1,  g_x1);
    cudaGetSymbolAddress(&p_ln1, g_ln1);
    cudaGetSymbolAddress(&p_qkvh, g_qkvh);
    cudaGetSymbolAddress(&p_atth, g_atth);
    cudaGetSymbolAddress(&p_wh,  g_wh);
    __half* wh = (__half*)p_wh;

    static bool attr_done = false;
    if (!attr_done) {
        cudaFuncSetAttribute(mma_gemm_h<true, true, false, true, false>,
                             cudaFuncAttributeMaxDynamicSharedMemorySize, GEMM_SMEM);
        cudaFuncSetAttribute(mma_gemm_h<false, true, true, false, false>,
                             cudaFuncAttributeMaxDynamicSharedMemorySize, GEMM_SMEM);
        cudaFuncSetAttribute(mma_gemm_h<false, false, false, true, true>,
                             cudaFuncAttributeMaxDynamicSharedMemorySize, GEMM_SMEM);
        attr_done = true;
    }

    w2h_all_kernel<<<(Q_END + 255) / 256, 256>>>(w_qkv, w_pw1, w_pw2, w_proj, wh);
    bias_kernel<<<dim3(32, 12), 256>>>(rel_index, rel_table, gbias);

    // 1) x1 = x + MLP(LN2(x))
    ln_kernel<<<M_, 128>>>(x, ln2_g, ln2_b, (__half*)p_ln2);
    mma_gemm_h<true, true, false, true, false><<<dim3(HID_ / 128, M_ / 128), 256, GEMM_SMEM>>>(
        (const __half*)p_ln2, wh + OFF_PW1, b_pw1, nullptr, p_h1, M_, HID_, C_);
    dwconv_kernel<<<dim3(N_, B_), 384>>>(
        (const __half*)p_h1, (__half*)p_h2, w_dw, b_dw);
    mma_gemm_h<false, true, true, false, false><<<dim3(C_ / 128, M_ / 128), 256, GEMM_SMEM>>>(
        (const __half*)p_h2, wh + OFF_PW2, b_pw2, x, p_x1, M_, C_, HID_);

    // 2) out = x1 + Attn(LN1(x1))
    ln_kernel<<<M_, 128>>>((const float*)p_x1, ln1_g, ln1_b, (__half*)p_ln1);
    mma_gemm_h<false, false, false, true, true><<<dim3(1152 / 128, M_ / 128), 256, GEMM_SMEM>>>(
        (const __half*)p_ln1, wh + OFF_QKV, nullptr, nullptr, p_qkvh, M_, 1152, C_);
    attn_mma_kernel<<<dim3(N_ / 128, H_, B_), 256>>>(
        (const __half*)p_qkvh, (__half*)p_atth);
    mma_gemm_h<false, true, true, false, false><<<dim3(C_ / 128, M_ / 128), 256, GEMM_SMEM>>>(
        (const __half*)p_atth, wh + OFF_PROJ, b_proj, (const float*)p_x1, out, M_, C_, C_);
}

// round 11
// speedup vs baseline: 5.6072x; 1.0362x over previous
#include <cuda_runtime.h>
#include <cuda_fp16.h>
#include <math.h>
#include <stdint.h>

// Problem constants
#define B_  8
#define N_  1024
#define C_  384
#define H_  12
#define HD_ 32
#define HID_ 768
#define M_  (B_ * N_)
#define NREL_ 3969
#define SCALE_ 0.17677669529663687f
#define LOG2E_ 1.4426950408889634f

// NOTE: harness PTX target is sm_103 (no 'a') -> tcgen05.* unavailable.

__device__ __forceinline__ float gelu_f(float v) {
    return 0.5f * v * (1.0f + erff(v * 0.70710678118654752f));
}

__device__ __forceinline__ void mma_f16(float* c, const uint32_t* a, const uint32_t* b) {
    asm volatile(
        "mma.sync.aligned.m16n8k16.row.col.f32.f16.f16.f32 "
        "{%0,%1,%2,%3}, {%4,%5,%6,%7}, {%8,%9}, {%0,%1,%2,%3};"
        : "+f"(c[0]), "+f"(c[1]), "+f"(c[2]), "+f"(c[3])
        : "r"(a[0]), "r"(a[1]), "r"(a[2]), "r"(a[3]), "r"(b[0]), "r"(b[1]));
}

__device__ __forceinline__ void ldsm_x4(uint32_t* r, const __half* p) {
    uint32_t addr = (uint32_t)__cvta_generic_to_shared(p);
    asm volatile("ldmatrix.sync.aligned.m8n8.x4.shared.b16 {%0,%1,%2,%3}, [%4];"
                 : "=r"(r[0]), "=r"(r[1]), "=r"(r[2]), "=r"(r[3]) : "r"(addr));
}

__device__ __forceinline__ void ldsm_x2_t(uint32_t& r0, uint32_t& r1, const __half* p) {
    uint32_t addr = (uint32_t)__cvta_generic_to_shared(p);
    asm volatile("ldmatrix.sync.aligned.m8n8.x2.trans.shared.b16 {%0,%1}, [%2];"
                 : "=r"(r0), "=r"(r1) : "r"(addr));
}

// ---------------- scratch ----------------
__device__ __align__(16) __half g_ln2[M_ * C_];
__device__ __align__(16) __half g_h1 [M_ * HID_];
__device__ __align__(16) __half g_h2 [M_ * HID_];
__device__ float g_x1 [M_ * C_];
__device__ __align__(16) __half g_ln1[M_ * C_];
__device__ __align__(16) __half g_qkvh[M_ * 3 * C_];
__device__ __align__(16) __half g_atth[M_ * C_];
__device__ __align__(16) __half g_biash[H_ * N_ * N_];
__device__ __align__(16) __half g_wh[1179648];
#define OFF_QKV  0
#define OFF_PW1  442368
#define OFF_PW2  737280
#define OFF_PROJ 1032192
#define Q_QKV  110592
#define Q_PW1  184320
#define Q_PW2  258048
#define Q_END  294912

// ---------------- merged weight fp32 -> fp16 ----------------
__global__ __launch_bounds__(256) void w2h_all_kernel(
    const float* __restrict__ s_qkv, const float* __restrict__ s_pw1,
    const float* __restrict__ s_pw2, const float* __restrict__ s_proj,
    __half* __restrict__ dst)
{
    const int i = blockIdx.x * 256 + threadIdx.x;
    if (i >= Q_END) return;
    const float* src; int local;
    if (i < Q_QKV)      { src = s_qkv;  local = i; }
    else if (i < Q_PW1) { src = s_pw1;  local = i - Q_QKV; }
    else if (i < Q_PW2) { src = s_pw2;  local = i - Q_PW1; }
    else                { src = s_proj; local = i - Q_PW2; }
    const float4 v = ((const float4*)src)[local];
    __half2 h0 = __floats2half2_rn(v.x, v.y);
    __half2 h1 = __floats2half2_rn(v.z, v.w);
    uint2 u; u.x = *(uint32_t*)&h0; u.y = *(uint32_t*)&h1;
    *(uint2*)(dst + (size_t)i * 4) = u;
}

// ---------------- LayerNorm (half output) ----------------
__global__ __launch_bounds__(128) void ln_kernel(
    const float* __restrict__ in, const float* __restrict__ g,
    const float* __restrict__ bta, __half* __restrict__ out)
{
    const int row = blockIdx.x;
    const int t = threadIdx.x;
    const float* xr = in + (size_t)row * C_;
    float v0 = xr[t], v1 = xr[t + 128], v2 = xr[t + 256];
    float s = v0 + v1 + v2;
    __shared__ float red[4], red2[4];
    #pragma unroll
    for (int o = 16; o; o >>= 1) s += __shfl_xor_sync(0xffffffffu, s, o);
    if ((t & 31) == 0) red[t >> 5] = s;
    __syncthreads();
    const float mean = (red[0] + red[1] + red[2] + red[3]) * (1.0f / C_);
    const float d0 = v0 - mean, d1 = v1 - mean, d2 = v2 - mean;
    float q = d0 * d0 + d1 * d1 + d2 * d2;
    #pragma unroll
    for (int o = 16; o; o >>= 1) q += __shfl_xor_sync(0xffffffffu, q, o);
    if ((t & 31) == 0) red2[t >> 5] = q;
    __syncthreads();
    const float var = (red2[0] + red2[1] + red2[2] + red2[3]) * (1.0f / C_);
    const float inv = rsqrtf(var + 1e-5f);
    __half* orow = out + (size_t)row * C_;
    orow[t]       = __float2half_rn(d0 * inv * g[t]       + bta[t]);
    orow[t + 128] = __float2half_rn(d1 * inv * g[t + 128] + bta[t + 128]);
    orow[t + 256] = __float2half_rn(d2 * inv * g[t + 256] + bta[t + 256]);
}

// ---------------- fp16 GEMM: 4-stage cp.async, 1 barrier/iter ---------------
#define SMSH 40
#define GEMM_SMEM (4 * 128 * SMSH * 2 * 2)   // 81920 bytes
template<bool GELU, bool HASB, bool RES, bool OUTH, bool QSC>
__global__ __launch_bounds__(256, 2) void mma_gemm_h(
    const __half* __restrict__ A, const __half* __restrict__ W,
    const float* __restrict__ bias, const float* __restrict__ res,
    void* __restrict__ Cv, int M, int Nd, int K)
{
    extern __shared__ __half dsm[];
    __half* Asb = dsm;
    __half* Bsb = dsm + 4 * 128 * SMSH;
    const int tid  = threadIdx.x;
    const int lane = tid & 31, warp = tid >> 5;
    const int wm = warp >> 2, wn = warp & 3;
    const int lq = lane >> 2, lr = lane & 3;
    const int bm = blockIdx.y * 128, bn = blockIdx.x * 128;
    const int ntiles = K >> 5;

    const int lrow0 = tid >> 2, lc8 = (tid & 3) * 8;
    const int lrow1 = (tid + 256) >> 2;

    const int arow = ((lane >> 3) & 1) * 8 + (lane & 7);
    const int acol = (lane >> 4) * 8;
    const int brow = ((lane >> 4) << 3) + (lane & 7);
    const int bcol = ((lane >> 3) & 1) * 8;

    #define ISSUE(kt, buf)                                                       \
    {                                                                            \
        __half* asb = Asb + (buf) * 128 * SMSH;                                  \
        __half* bsb = Bsb + (buf) * 128 * SMSH;                                  \
        const __half* ag0 = A + (size_t)(bm + lrow0) * K + (kt) * 32 + lc8;      \
        const __half* wg0 = W + (size_t)(bn + lrow0) * K + (kt) * 32 + lc8;      \
        const __half* ag1 = A + (size_t)(bm + lrow1) * K + (kt) * 32 + lc8;      \
        const __half* wg1 = W + (size_t)(bn + lrow1) * K + (kt) * 32 + lc8;      \
        uint32_t sa0 = (uint32_t)__cvta_generic_to_shared(&asb[lrow0 * SMSH + lc8]); \
        uint32_t sb0 = (uint32_t)__cvta_generic_to_shared(&bsb[lrow0 * SMSH + lc8]); \
        uint32_t sa1 = (uint32_t)__cvta_generic_to_shared(&asb[lrow1 * SMSH + lc8]); \
        uint32_t sb1 = (uint32_t)__cvta_generic_to_shared(&bsb[lrow1 * SMSH + lc8]); \
        asm volatile("cp.async.cg.shared.global [%0], [%1], 16;" :: "r"(sa0), "l"(ag0)); \
        asm volatile("cp.async.cg.shared.global [%0], [%1], 16;" :: "r"(sb0), "l"(wg0)); \
        asm volatile("cp.async.cg.shared.global [%0], [%1], 16;" :: "r"(sa1), "l"(ag1)); \
        asm volatile("cp.async.cg.shared.global [%0], [%1], 16;" :: "r"(sb1), "l"(wg1)); \
        asm volatile("cp.async.commit_group;");                                  \
    }

    float acc[4][4][4] = {};
    ISSUE(0, 0);
    if (ntiles > 1) ISSUE(1, 1);
    if (ntiles > 2) ISSUE(2, 2);

    for (int kt = 0; kt < ntiles; kt++) {
        if (kt + 2 < ntiles)      asm volatile("cp.async.wait_group 2;");
        else if (kt + 1 < ntiles) asm volatile("cp.async.wait_group 1;");
        else                      asm volatile("cp.async.wait_group 0;");
        __syncthreads();
        if (kt + 3 < ntiles) ISSUE(kt + 3, (kt + 3) & 3);

        const __half* as = Asb + (kt & 3) * 128 * SMSH;
        const __half* bs = Bsb + (kt & 3) * 128 * SMSH;
        #pragma unroll
        for (int ks = 0; ks < 2; ks++) {
            const int c = ks * 16;
            uint32_t af[4][4], bf[4][2];
            #pragma unroll
            for (int mt = 0; mt < 4; mt++)
                ldsm_x4(af[mt], &as[(wm * 64 + mt * 16 + arow) * SMSH + c + acol]);
            #pragma unroll
            for (int np = 0; np < 2; np++) {
                uint32_t tmp[4];
                ldsm_x4(tmp, &bs[(wn * 32 + np * 16 + brow) * SMSH + c + bcol]);
                bf[np * 2][0] = tmp[0]; bf[np * 2][1] = tmp[1];
                bf[np * 2 + 1][0] = tmp[2]; bf[np * 2 + 1][1] = tmp[3];
            }
            #pragma unroll
            for (int mt = 0; mt < 4; mt++)
                #pragma unroll
                for (int nt = 0; nt < 4; nt++)
                    mma_f16(acc[mt][nt], af[mt], bf[nt]);
        }
    }
    #undef ISSUE

    #pragma unroll
    for (int mt = 0; mt < 4; mt++) {
        #pragma unroll
        for (int nt = 0; nt < 4; nt++) {
            const int row = bm + wm * 64 + mt * 16 + lq;
            const int col = bn + wn * 32 + nt * 8 + lr * 2;
            #pragma unroll
            for (int half = 0; half < 2; half++) {
                const int r = row + half * 8;
                float v0 = acc[mt][nt][half * 2 + 0];
                float v1 = acc[mt][nt][half * 2 + 1];
                if (HASB) { v0 += bias[col]; v1 += bias[col + 1]; }
                if (GELU) { v0 = gelu_f(v0); v1 = gelu_f(v1); }
                if (RES) {
                    const float* Rr = res + (size_t)r * Nd + col;
                    v0 += Rr[0]; v1 += Rr[1];
                }
                if (OUTH) {
                    if (QSC && col < 384) { v0 *= SCALE_; v1 *= SCALE_; }
                    __half2 hv = __floats2half2_rn(v0, v1);
                    *(__half2*)((__half*)Cv + (size_t)r * Nd + col) = hv;
                } else {
                    *(float2*)((float*)Cv + (size_t)r * Nd + col) = make_float2(v0, v1);
                }
            }
        }
    }
}

// ---------------- depthwise 3x3 dil-2 conv + GELU ---------------------------
__global__ __launch_bounds__(384) void dwconv_kernel(
    const __half* __restrict__ h1, __half* __restrict__ h2,
    const float* __restrict__ w, const float* __restrict__ bias)
{
    const int n = blockIdx.x;
    const int b = blockIdx.y;
    const int y = n >> 5, x = n & 31;
    const size_t base = (size_t)b * N_ * HID_;
    const int c0 = threadIdx.x * 2;

    float2 acc = make_float2(bias[c0], bias[c0 + 1]);
    const float* w0 = w + c0 * 9;
    const float* w1 = w + (c0 + 1) * 9;

    #pragma unroll
    for (int i = 0; i < 3; i++) {
        const int yy = y + 2 * i - 2;
        if (yy < 0 || yy > 31) continue;
        #pragma unroll
        for (int j = 0; j < 3; j++) {
            const int xx = x + 2 * j - 2;
            if (xx < 0 || xx > 31) continue;
            const float2 v = __half22float2(
                *(const __half2*)(h1 + base + (size_t)(yy * 32 + xx) * HID_ + c0));
            acc.x += w0[i * 3 + j] * v.x;
            acc.y += w1[i * 3 + j] * v.y;
        }
    }
    *(__half2*)(h2 + base + (size_t)n * HID_ + c0) =
        __floats2half2_rn(gelu_f(acc.x), gelu_f(acc.y));
}

// ---------------- bias precompute (half output) ----------------
__global__ __launch_bounds__(256) void bias_kernel(
    const int* __restrict__ rel_index, const float* __restrict__ rel_table,
    const float* __restrict__ gb)
{
    __shared__ float tab[NREL_];
    const int h = blockIdx.y;
    const int q0 = blockIdx.x * 32;
    for (int i = threadIdx.x; i < NREL_; i += 256) tab[i] = rel_table[i * H_ + h];
    __syncthreads();
    __half* out = g_biash + (size_t)h * (N_ * N_);
    for (int e = threadIdx.x; e < 32 * 512; e += 256) {
        const int q = q0 + (e >> 9);
        const int k = (e & 511) * 2;
        const size_t idx = (size_t)q * N_ + k;
        const __half2 v = __floats2half2_rn(
            tab[rel_index[idx]] + gb[idx],
            tab[rel_index[idx + 1]] + gb[idx + 1]);
        *(__half2*)&out[idx] = v;
    }
}

// ---------------- fp16 flash attention: smem-staged bias --------------------
// K/V and the 128x64 bias tile are all cp.async double-buffered. Bias apply
// is conflict-free LDS (row stride 72 halves: bank = 4*lq + lr + 4*nf, all
// lanes distinct), replacing 16 scattered L2 LDG per thread per tile.
#define SMSH 40
#define ATT_K(buf)  ((buf) * 64 * SMSH)                  // 2 x 2560 half
#define ATT_V(buf)  (2 * 64 * SMSH + (buf) * 64 * SMSH)  // 2 x 2560 half
#define ATT_B(buf)  (4 * 64 * SMSH + (buf) * 128 * 72)   // 2 x 9216 half
#define ATT_SMEM  ((4 * 64 * SMSH + 2 * 128 * 72) * 2)   // 57344 bytes
__global__ __launch_bounds__(256) void attn_mma_kernel(
    const __half* __restrict__ qkv, __half* __restrict__ att)
{
    extern __shared__ __half asm_[];
    const int q0 = blockIdx.x * 128;
    const int h  = blockIdx.y;
    const int b  = blockIdx.z;
    const int tid = threadIdx.x;
    const int lane = tid & 31, w = tid >> 5;
    const int lq = lane >> 2;
    const int lr = lane & 3;

    const size_t qbase = (size_t)b * N_ * 1152;
    const int kl = tid >> 2, d8 = (tid & 3) * 8;
    const __half* bhg = g_biash + (size_t)h * N_ * N_;   // global bias, this head

    #define AISSUE(kt, buf)                                                      \
    {                                                                            \
        const __half* src = qkv + qbase + (size_t)((kt) * 64 + kl) * 1152 + h * 32 + d8; \
        uint32_t sk = (uint32_t)__cvta_generic_to_shared(&asm_[ATT_K(buf) + kl * SMSH + d8]); \
        uint32_t sv = (uint32_t)__cvta_generic_to_shared(&asm_[ATT_V(buf) + kl * SMSH + d8]); \
        asm volatile("cp.async.cg.shared.global [%0], [%1], 16;" :: "r"(sk), "l"(src + 384)); \
        asm volatile("cp.async.cg.shared.global [%0], [%1], 16;" :: "r"(sv), "l"(src + 768)); \
        _Pragma("unroll")                                                        \
        for (int j = 0; j < 4; j++) {                                            \
            const int cid = tid + j * 256;                                       \
            const int brw = cid >> 3, c8 = cid & 7;                              \
            const __half* bsrc = bhg + (size_t)(q0 + brw) * N_ + (kt) * 64 + c8 * 8; \
            uint32_t bdst = (uint32_t)__cvta_generic_to_shared(                  \
                &asm_[ATT_B(buf) + brw * 72 + c8 * 8]);                          \
            asm volatile("cp.async.cg.shared.global [%0], [%1], 16;" :: "r"(bdst), "l"(bsrc)); \
        }                                                                        \
        asm volatile("cp.async.commit_group;");                                  \
    }

    const int brow = ((lane >> 4) << 3) + (lane & 7);
    const int bcol = ((lane >> 3) & 1) * 8;

    uint32_t qa[2][4];
    const int br0 = q0 + w * 16 + lq;
    {
        const __half* qp  = qkv + qbase + (size_t)br0 * 1152 + h * 32;
        const __half* qp8 = qp + 8 * 1152;
        #pragma unroll
        for (int ks = 0; ks < 2; ks++) {
            const int c = ks * 16 + 2 * lr;
            qa[ks][0] = *(const uint32_t*)(qp  + c);
            qa[ks][1] = *(const uint32_t*)(qp8 + c);
            qa[ks][2] = *(const uint32_t*)(qp  + c + 8);
            qa[ks][3] = *(const uint32_t*)(qp8 + c + 8);
        }
    }

    float o[4][4] = {};
    float m0 = -1e30f, m1 = -1e30f, l0 = 0.0f, l1 = 0.0f;

    AISSUE(0, 0);
    for (int kt = 0; kt < 16; kt++) {
        asm volatile("cp.async.wait_group 0;");
        __syncthreads();
        if (kt < 15) AISSUE(kt + 1, (kt + 1) & 1);

        const int buf = kt & 1;

        // S = Q @ K^T
        float s[8][4];
        #pragma unroll
        for (int nf = 0; nf < 8; nf++)
            s[nf][0] = s[nf][1] = s[nf][2] = s[nf][3] = 0.0f;
        #pragma unroll
        for (int ks = 0; ks < 2; ks++) {
            const int c = ks * 16;
            uint32_t kf[8][2];
            #pragma unroll
            for (int np = 0; np < 4; np++) {
                uint32_t tmp[4];
                ldsm_x4(tmp, &asm_[ATT_K(buf) + (np * 16 + brow) * SMSH + c + bcol]);
                kf[np * 2][0] = tmp[0]; kf[np * 2][1] = tmp[1];
                kf[np * 2 + 1][0] = tmp[2]; kf[np * 2 + 1][1] = tmp[3];
            }
            #pragma unroll
            for (int nf = 0; nf < 8; nf++)
                mma_f16(s[nf], qa[ks], kf[nf]);
        }

        // + bias from smem (conflict-free), row max
        const __half* bs0 = &asm_[ATT_B(buf) + (w * 16 + lq) * 72];
        const __half* bs1 = bs0 + 8 * 72;
        float nm0 = m0, nm1 = m1;
        #pragma unroll
        for (int nf = 0; nf < 8; nf++) {
            const int col = nf * 8 + lr * 2;
            const float2 b0v = __half22float2(*(const __half2*)(bs0 + col));
            const float2 b1v = __half22float2(*(const __half2*)(bs1 + col));
            s[nf][0] += b0v.x; s[nf][1] += b0v.y;
            s[nf][2] += b1v.x; s[nf][3] += b1v.y;
            nm0 = fmaxf(nm0, fmaxf(s[nf][0], s[nf][1]));
            nm1 = fmaxf(nm1, fmaxf(s[nf][2], s[nf][3]));
        }
        nm0 = fmaxf(nm0, __shfl_xor_sync(0xffffffffu, nm0, 1));
        nm0 = fmaxf(nm0, __shfl_xor_sync(0xffffffffu, nm0, 2));
        nm1 = fmaxf(nm1, __shfl_xor_sync(0xffffffffu, nm1, 1));
        nm1 = fmaxf(nm1, __shfl_xor_sync(0xffffffffu, nm1, 2));

        const float c0 = __expf(m0 - nm0), c1 = __expf(m1 - nm1);
        m0 = nm0; m1 = nm1; l0 *= c0; l1 *= c1;
        #pragma unroll
        for (int nf = 0; nf < 4; nf++) {
            o[nf][0] *= c0; o[nf][1] *= c0;
            o[nf][2] *= c1; o[nf][3] *= c1;
        }

        // exp via half2 MUFU; P packed straight into A-operand registers
        uint32_t ph[8][2];
        float a0 = 0.0f, a1 = 0.0f;
        #pragma unroll
        for (int nf = 0; nf < 8; nf++) {
            const __half2 x01 = __floats2half2_rn((s[nf][0] - nm0) * LOG2E_,
                                                  (s[nf][1] - nm0) * LOG2E_);
            const __half2 x23 = __floats2half2_rn((s[nf][2] - nm1) * LOG2E_,
                                                  (s[nf][3] - nm1) * LOG2E_);
            const __half2 p01 = h2exp2(x01);
            const __half2 p23 = h2exp2(x23);
            const float2 f01 = __half22float2(p01);
            const float2 f23 = __half22float2(p23);
            a0 += f01.x + f01.y;
            a1 += f23.x + f23.y;
            ph[nf][0] = *(const uint32_t*)&p01;
            ph[nf][1] = *(const uint32_t*)&p23;
        }
        a0 += __shfl_xor_sync(0xffffffffu, a0, 1);
        a0 += __shfl_xor_sync(0xffffffffu, a0, 2);
        a1 += __shfl_xor_sync(0xffffffffu, a1, 1);
        a1 += __shfl_xor_sync(0xffffffffu, a1, 2);
        l0 += a0; l1 += a1;

        // O += P @ V
        #pragma unroll
        for (int kf2 = 0; kf2 < 4; kf2++) {
            uint32_t pa[4];
            pa[0] = ph[2 * kf2][0];
            pa[1] = ph[2 * kf2][1];
            pa[2] = ph[2 * kf2 + 1][0];
            pa[3] = ph[2 * kf2 + 1][1];
            #pragma unroll
            for (int nf = 0; nf < 4; nf++) {
                uint32_t b0r, b1r;
                ldsm_x2_t(b0r, b1r,
                          &asm_[ATT_V(buf) + (kf2 * 16 + (lane & 15)) * SMSH + nf * 8]);
                uint32_t bfr[2] = { b0r, b1r };
                mma_f16(o[nf], pa, bfr);
            }
        }
    }
    #undef AISSUE

    const float inv0 = 1.0f / l0, inv1 = 1.0f / l1;
    #pragma unroll
    for (int nf = 0; nf < 4; nf++) {
        const int col = h * 32 + nf * 8 + lr * 2;
        __half* o0 = att + ((size_t)b * N_ + br0) * C_ + col;
        __half* o1 = att + ((size_t)b * N_ + br0 + 8) * C_ + col;
        *(__half2*)o0 = __floats2half2_rn(o[nf][0] * inv0, o[nf][1] * inv0);
        *(__half2*)o1 = __floats2half2_rn(o[nf][2] * inv1, o[nf][3] * inv1);
    }
}

// ---------------- launch ----------------
extern "C" void kernel_launch(void* const* d_in, const int* in_sizes, int n_in,
                              void* d_out, int out_size)
{
    const int base = (n_in >= 19) ? 2 : 0;
    const float* x         = (const float*)d_in[0];
    const int*   rel_index = (const int*)  d_in[1 + base];
    const float* ln1_g     = (const float*)d_in[2 + base];
    const float* ln1_b     = (const float*)d_in[3 + base];
    const float* w_qkv     = (const float*)d_in[4 + base];
    const float* w_proj    = (const float*)d_in[5 + base];
    const float* b_proj    = (const float*)d_in[6 + base];
    const float* rel_table = (const float*)d_in[7 + base];
    const float* gbias     = (const float*)d_in[8 + base];
    const float* ln2_g     = (const float*)d_in[9 + base];
    const float* ln2_b     = (const float*)d_in[10 + base];
    const float* w_pw1     = (const float*)d_in[11 + base];
    const float* b_pw1     = (const float*)d_in[12 + base];
    const float* w_dw      = (const float*)d_in[13 + base];
    const float* b_dw      = (const float*)d_in[14 + base];
    const float* w_pw2     = (const float*)d_in[15 + base];
    const float* b_pw2     = (const float*)d_in[16 + base];
    float* out = (float*)d_out;

    void *p_ln2, *p_h1, *p_h2, *p_x1, *p_ln1, *p_qkvh, *p_atth, *p_wh;
    cudaGetSymbolAddress(&p_ln2, g_ln2);
    cudaGetSymbolAddress(&p_h1,  g_h1);
    cudaGetSymbolAddress(&p_h2,  g_h2);
    cudaGetSymbolAddress(&p_x1,  g_x1);
    cudaGetSymbolAddress(&p_ln1, g_ln1);
    cudaGetSymbolAddress(&p_qkvh, g_qkvh);
    cudaGetSymbolAddress(&p_atth, g_atth);
    cudaGetSymbolAddress(&p_wh,  g_wh);
    __half* wh = (__half*)p_wh;

    static bool attr_done = false;
    if (!attr_done) {
        cudaFuncSetAttribute(mma_gemm_h<true, true, false, true, false>,
                             cudaFuncAttributeMaxDynamicSharedMemorySize, GEMM_SMEM);
        cudaFuncSetAttribute(mma_gemm_h<false, true, true, false, false>,
                             cudaFuncAttributeMaxDynamicSharedMemorySize, GEMM_SMEM);
        cudaFuncSetAttribute(mma_gemm_h<false, false, false, true, true>,
                             cudaFuncAttributeMaxDynamicSharedMemorySize, GEMM_SMEM);
        cudaFuncSetAttribute(attn_mma_kernel,
                             cudaFuncAttributeMaxDynamicSharedMemorySize, ATT_SMEM);
        attr_done = true;
    }

    w2h_all_kernel<<<(Q_END + 255) / 256, 256>>>(w_qkv, w_pw1, w_pw2, w_proj, wh);
    bias_kernel<<<dim3(32, 12), 256>>>(rel_index, rel_table, gbias);

    // 1) x1 = x + MLP(LN2(x))
    ln_kernel<<<M_, 128>>>(x, ln2_g, ln2_b, (__half*)p_ln2);
    mma_gemm_h<true, true, false, true, false><<<dim3(HID_ / 128, M_ / 128), 256, GEMM_SMEM>>>(
        (const __half*)p_ln2, wh + OFF_PW1, b_pw1, nullptr, p_h1, M_, HID_, C_);
    dwconv_kernel<<<dim3(N_, B_), 384>>>(
        (const __half*)p_h1, (__half*)p_h2, w_dw, b_dw);
    mma_gemm_h<false, true, true, false, false><<<dim3(C_ / 128, M_ / 128), 256, GEMM_SMEM>>>(
        (const __half*)p_h2, wh + OFF_PW2, b_pw2, x, p_x1, M_, C_, HID_);

    // 2) out = x1 + Attn(LN1(x1))
    ln_kernel<<<M_, 128>>>((const float*)p_x1, ln1_g, ln1_b, (__half*)p_ln1);
    mma_gemm_h<false, false, false, true, true><<<dim3(1152 / 128, M_ / 128), 256, GEMM_SMEM>>>(
        (const __half*)p_ln1, wh + OFF_QKV, nullptr, nullptr, p_qkvh, M_, 1152, C_);
    attn_mma_kernel<<<dim3(N_ / 128, H_, B_), 256, ATT_SMEM>>>(
        (const __half*)p_qkvh, (__half*)p_atth);
    mma_gemm_h<false, true, true, false, false><<<dim3(C_ / 128, M_ / 128), 256, GEMM_SMEM>>>(
        (const __half*)p_atth, wh + OFF_PROJ, b_proj, (const float*)p_x1, out, M_, C_, C_);
}

// round 12
// speedup vs baseline: 5.8633x; 1.0457x over previous
#include <cuda_runtime.h>
#include <cuda_fp16.h>
#include <math.h>
#include <stdint.h>

// Problem constants
#define B_  8
#define N_  1024
#define C_  384
#define H_  12
#define HD_ 32
#define HID_ 768
#define M_  (B_ * N_)
#define NREL_ 3969
#define SCALE_ 0.17677669529663687f
#define LOG2E_ 1.4426950408889634f

// NOTE: harness PTX target is sm_103 (no 'a') -> tcgen05.* unavailable.

__device__ __forceinline__ float gelu_f(float v) {
    return 0.5f * v * (1.0f + erff(v * 0.70710678118654752f));
}

__device__ __forceinline__ void mma_f16(float* c, const uint32_t* a, const uint32_t* b) {
    asm volatile(
        "mma.sync.aligned.m16n8k16.row.col.f32.f16.f16.f32 "
        "{%0,%1,%2,%3}, {%4,%5,%6,%7}, {%8,%9}, {%0,%1,%2,%3};"
        : "+f"(c[0]), "+f"(c[1]), "+f"(c[2]), "+f"(c[3])
        : "r"(a[0]), "r"(a[1]), "r"(a[2]), "r"(a[3]), "r"(b[0]), "r"(b[1]));
}

__device__ __forceinline__ void ldsm_x4(uint32_t* r, const __half* p) {
    uint32_t addr = (uint32_t)__cvta_generic_to_shared(p);
    asm volatile("ldmatrix.sync.aligned.m8n8.x4.shared.b16 {%0,%1,%2,%3}, [%4];"
                 : "=r"(r[0]), "=r"(r[1]), "=r"(r[2]), "=r"(r[3]) : "r"(addr));
}

__device__ __forceinline__ void ldsm_x2_t(uint32_t& r0, uint32_t& r1, const __half* p) {
    uint32_t addr = (uint32_t)__cvta_generic_to_shared(p);
    asm volatile("ldmatrix.sync.aligned.m8n8.x2.trans.shared.b16 {%0,%1}, [%2];"
                 : "=r"(r0), "=r"(r1) : "r"(addr));
}

// ---------------- scratch ----------------
__device__ __align__(16) __half g_ln2[M_ * C_];
__device__ __align__(16) __half g_h1 [M_ * HID_];
__device__ __align__(16) __half g_h2 [M_ * HID_];
__device__ float g_x1 [M_ * C_];
__device__ __align__(16) __half g_ln1[M_ * C_];
__device__ __align__(16) __half g_qkvh[M_ * 3 * C_];
__device__ __align__(16) __half g_atth[M_ * C_];
__device__ __align__(16) __half g_biash[H_ * N_ * N_];
__device__ __align__(16) __half g_wh[1179648];
#define OFF_QKV  0
#define OFF_PW1  442368
#define OFF_PW2  737280
#define OFF_PROJ 1032192
#define Q_QKV  110592
#define Q_PW1  184320
#define Q_PW2  258048
#define Q_END  294912

// ---------------- merged weight fp32 -> fp16 ----------------
__global__ __launch_bounds__(256) void w2h_all_kernel(
    const float* __restrict__ s_qkv, const float* __restrict__ s_pw1,
    const float* __restrict__ s_pw2, const float* __restrict__ s_proj,
    __half* __restrict__ dst)
{
    const int i = blockIdx.x * 256 + threadIdx.x;
    if (i >= Q_END) return;
    const float* src; int local;
    if (i < Q_QKV)      { src = s_qkv;  local = i; }
    else if (i < Q_PW1) { src = s_pw1;  local = i - Q_QKV; }
    else if (i < Q_PW2) { src = s_pw2;  local = i - Q_PW1; }
    else                { src = s_proj; local = i - Q_PW2; }
    const float4 v = ((const float4*)src)[local];
    __half2 h0 = __floats2half2_rn(v.x, v.y);
    __half2 h1 = __floats2half2_rn(v.z, v.w);
    uint2 u; u.x = *(uint32_t*)&h0; u.y = *(uint32_t*)&h1;
    *(uint2*)(dst + (size_t)i * 4) = u;
}

// ---------------- LayerNorm (half output) ----------------
__global__ __launch_bounds__(128) void ln_kernel(
    const float* __restrict__ in, const float* __restrict__ g,
    const float* __restrict__ bta, __half* __restrict__ out)
{
    const int row = blockIdx.x;
    const int t = threadIdx.x;
    const float* xr = in + (size_t)row * C_;
    float v0 = xr[t], v1 = xr[t + 128], v2 = xr[t + 256];
    float s = v0 + v1 + v2;
    __shared__ float red[4], red2[4];
    #pragma unroll
    for (int o = 16; o; o >>= 1) s += __shfl_xor_sync(0xffffffffu, s, o);
    if ((t & 31) == 0) red[t >> 5] = s;
    __syncthreads();
    const float mean = (red[0] + red[1] + red[2] + red[3]) * (1.0f / C_);
    const float d0 = v0 - mean, d1 = v1 - mean, d2 = v2 - mean;
    float q = d0 * d0 + d1 * d1 + d2 * d2;
    #pragma unroll
    for (int o = 16; o; o >>= 1) q += __shfl_xor_sync(0xffffffffu, q, o);
    if ((t & 31) == 0) red2[t >> 5] = q;
    __syncthreads();
    const float var = (red2[0] + red2[1] + red2[2] + red2[3]) * (1.0f / C_);
    const float inv = rsqrtf(var + 1e-5f);
    __half* orow = out + (size_t)row * C_;
    orow[t]       = __float2half_rn(d0 * inv * g[t]       + bta[t]);
    orow[t + 128] = __float2half_rn(d1 * inv * g[t + 128] + bta[t + 128]);
    orow[t + 256] = __float2half_rn(d2 * inv * g[t + 256] + bta[t + 256]);
}

// ---------------- fp16 GEMM: 4-stage cp.async, 1 barrier/iter ---------------
#define SMSH 40
#define GEMM_SMEM (4 * 128 * SMSH * 2 * 2)   // 81920 bytes
template<bool GELU, bool HASB, bool RES, bool OUTH, bool QSC>
__global__ __launch_bounds__(256, 2) void mma_gemm_h(
    const __half* __restrict__ A, const __half* __restrict__ W,
    const float* __restrict__ bias, const float* __restrict__ res,
    void* __restrict__ Cv, int M, int Nd, int K)
{
    extern __shared__ __half dsm[];
    __half* Asb = dsm;
    __half* Bsb = dsm + 4 * 128 * SMSH;
    const int tid  = threadIdx.x;
    const int lane = tid & 31, warp = tid >> 5;
    const int wm = warp >> 2, wn = warp & 3;
    const int lq = lane >> 2, lr = lane & 3;
    const int bm = blockIdx.y * 128, bn = blockIdx.x * 128;
    const int ntiles = K >> 5;

    const int lrow0 = tid >> 2, lc8 = (tid & 3) * 8;
    const int lrow1 = (tid + 256) >> 2;

    const int arow = ((lane >> 3) & 1) * 8 + (lane & 7);
    const int acol = (lane >> 4) * 8;
    const int brow = ((lane >> 4) << 3) + (lane & 7);
    const int bcol = ((lane >> 3) & 1) * 8;

    #define ISSUE(kt, buf)                                                       \
    {                                                                            \
        __half* asb = Asb + (buf) * 128 * SMSH;                                  \
        __half* bsb = Bsb + (buf) * 128 * SMSH;                                  \
        const __half* ag0 = A + (size_t)(bm + lrow0) * K + (kt) * 32 + lc8;      \
        const __half* wg0 = W + (size_t)(bn + lrow0) * K + (kt) * 32 + lc8;      \
        const __half* ag1 = A + (size_t)(bm + lrow1) * K + (kt) * 32 + lc8;      \
        const __half* wg1 = W + (size_t)(bn + lrow1) * K + (kt) * 32 + lc8;      \
        uint32_t sa0 = (uint32_t)__cvta_generic_to_shared(&asb[lrow0 * SMSH + lc8]); \
        uint32_t sb0 = (uint32_t)__cvta_generic_to_shared(&bsb[lrow0 * SMSH + lc8]); \
        uint32_t sa1 = (uint32_t)__cvta_generic_to_shared(&asb[lrow1 * SMSH + lc8]); \
        uint32_t sb1 = (uint32_t)__cvta_generic_to_shared(&bsb[lrow1 * SMSH + lc8]); \
        asm volatile("cp.async.cg.shared.global [%0], [%1], 16;" :: "r"(sa0), "l"(ag0)); \
        asm volatile("cp.async.cg.shared.global [%0], [%1], 16;" :: "r"(sb0), "l"(wg0)); \
        asm volatile("cp.async.cg.shared.global [%0], [%1], 16;" :: "r"(sa1), "l"(ag1)); \
        asm volatile("cp.async.cg.shared.global [%0], [%1], 16;" :: "r"(sb1), "l"(wg1)); \
        asm volatile("cp.async.commit_group;");                                  \
    }

    float acc[4][4][4] = {};
    ISSUE(0, 0);
    if (ntiles > 1) ISSUE(1, 1);
    if (ntiles > 2) ISSUE(2, 2);

    for (int kt = 0; kt < ntiles; kt++) {
        if (kt + 2 < ntiles)      asm volatile("cp.async.wait_group 2;");
        else if (kt + 1 < ntiles) asm volatile("cp.async.wait_group 1;");
        else                      asm volatile("cp.async.wait_group 0;");
        __syncthreads();
        if (kt + 3 < ntiles) ISSUE(kt + 3, (kt + 3) & 3);

        const __half* as = Asb + (kt & 3) * 128 * SMSH;
        const __half* bs = Bsb + (kt & 3) * 128 * SMSH;
        #pragma unroll
        for (int ks = 0; ks < 2; ks++) {
            const int c = ks * 16;
            uint32_t af[4][4], bf[4][2];
            #pragma unroll
            for (int mt = 0; mt < 4; mt++)
                ldsm_x4(af[mt], &as[(wm * 64 + mt * 16 + arow) * SMSH + c + acol]);
            #pragma unroll
            for (int np = 0; np < 2; np++) {
                uint32_t tmp[4];
                ldsm_x4(tmp, &bs[(wn * 32 + np * 16 + brow) * SMSH + c + bcol]);
                bf[np * 2][0] = tmp[0]; bf[np * 2][1] = tmp[1];
                bf[np * 2 + 1][0] = tmp[2]; bf[np * 2 + 1][1] = tmp[3];
            }
            #pragma unroll
            for (int mt = 0; mt < 4; mt++)
                #pragma unroll
                for (int nt = 0; nt < 4; nt++)
                    mma_f16(acc[mt][nt], af[mt], bf[nt]);
        }
    }
    #undef ISSUE

    #pragma unroll
    for (int mt = 0; mt < 4; mt++) {
        #pragma unroll
        for (int nt = 0; nt < 4; nt++) {
            const int row = bm + wm * 64 + mt * 16 + lq;
            const int col = bn + wn * 32 + nt * 8 + lr * 2;
            #pragma unroll
            for (int half = 0; half < 2; half++) {
                const int r = row + half * 8;
                float v0 = acc[mt][nt][half * 2 + 0];
                float v1 = acc[mt][nt][half * 2 + 1];
                if (HASB) { v0 += bias[col]; v1 += bias[col + 1]; }
                if (GELU) { v0 = gelu_f(v0); v1 = gelu_f(v1); }
                if (RES) {
                    const float* Rr = res + (size_t)r * Nd + col;
                    v0 += Rr[0]; v1 += Rr[1];
                }
                if (OUTH) {
                    if (QSC && col < 384) { v0 *= SCALE_; v1 *= SCALE_; }
                    __half2 hv = __floats2half2_rn(v0, v1);
                    *(__half2*)((__half*)Cv + (size_t)r * Nd + col) = hv;
                } else {
                    *(float2*)((float*)Cv + (size_t)r * Nd + col) = make_float2(v0, v1);
                }
            }
        }
    }
}

// ---------------- depthwise 3x3 dil-2 conv + GELU ---------------------------
__global__ __launch_bounds__(384) void dwconv_kernel(
    const __half* __restrict__ h1, __half* __restrict__ h2,
    const float* __restrict__ w, const float* __restrict__ bias)
{
    const int n = blockIdx.x;
    const int b = blockIdx.y;
    const int y = n >> 5, x = n & 31;
    const size_t base = (size_t)b * N_ * HID_;
    const int c0 = threadIdx.x * 2;

    float2 acc = make_float2(bias[c0], bias[c0 + 1]);
    const float* w0 = w + c0 * 9;
    const float* w1 = w + (c0 + 1) * 9;

    #pragma unroll
    for (int i = 0; i < 3; i++) {
        const int yy = y + 2 * i - 2;
        if (yy < 0 || yy > 31) continue;
        #pragma unroll
        for (int j = 0; j < 3; j++) {
            const int xx = x + 2 * j - 2;
            if (xx < 0 || xx > 31) continue;
            const float2 v = __half22float2(
                *(const __half2*)(h1 + base + (size_t)(yy * 32 + xx) * HID_ + c0));
            acc.x += w0[i * 3 + j] * v.x;
            acc.y += w1[i * 3 + j] * v.y;
        }
    }
    *(__half2*)(h2 + base + (size_t)n * HID_ + c0) =
        __floats2half2_rn(gelu_f(acc.x), gelu_f(acc.y));
}

// ---------------- bias precompute v2: one pass over (q,k), all heads --------
// rel_table is [NREL][12] fp32: one 48B contiguous row covers all 12 heads.
// Reads rel_index/gb ONCE (vs 12x before); table gathers are L1/L2-resident.
__global__ __launch_bounds__(256) void bias2_kernel(
    const int* __restrict__ rel_index, const float* __restrict__ rel_table,
    const float* __restrict__ gb)
{
    const int q = blockIdx.x;
    const size_t rowi = (size_t)q * N_;
    #pragma unroll
    for (int it = 0; it < 2; it++) {
        const int k = (threadIdx.x + it * 256) * 2;
        const int2 ri = *(const int2*)(rel_index + rowi + k);
        const float2 g2 = *(const float2*)(gb + rowi + k);
        const float* t0 = rel_table + ri.x * H_;
        const float* t1 = rel_table + ri.y * H_;
        #pragma unroll
        for (int h = 0; h < H_; h++) {
            const __half2 v = __floats2half2_rn(t0[h] + g2.x, t1[h] + g2.y);
            *(__half2*)(g_biash + (size_t)h * (N_ * N_) + rowi + k) = v;
        }
    }
}

// ---------------- fp16 flash attention: smem-staged bias --------------------
#define SMSH 40
#define ATT_K(buf)  ((buf) * 64 * SMSH)
#define ATT_V(buf)  (2 * 64 * SMSH + (buf) * 64 * SMSH)
#define ATT_B(buf)  (4 * 64 * SMSH + (buf) * 128 * 72)
#define ATT_SMEM  ((4 * 64 * SMSH + 2 * 128 * 72) * 2)   // 57344 bytes
__global__ __launch_bounds__(256) void attn_mma_kernel(
    const __half* __restrict__ qkv, __half* __restrict__ att)
{
    extern __shared__ __half asm_[];
    const int q0 = blockIdx.x * 128;
    const int h  = blockIdx.y;
    const int b  = blockIdx.z;
    const int tid = threadIdx.x;
    const int lane = tid & 31, w = tid >> 5;
    const int lq = lane >> 2;
    const int lr = lane & 3;

    const size_t qbase = (size_t)b * N_ * 1152;
    const int kl = tid >> 2, d8 = (tid & 3) * 8;
    const __half* bhg = g_biash + (size_t)h * N_ * N_;

    #define AISSUE(kt, buf)                                                      \
    {                                                                            \
        const __half* src = qkv + qbase + (size_t)((kt) * 64 + kl) * 1152 + h * 32 + d8; \
        uint32_t sk = (uint32_t)__cvta_generic_to_shared(&asm_[ATT_K(buf) + kl * SMSH + d8]); \
        uint32_t sv = (uint32_t)__cvta_generic_to_shared(&asm_[ATT_V(buf) + kl * SMSH + d8]); \
        asm volatile("cp.async.cg.shared.global [%0], [%1], 16;" :: "r"(sk), "l"(src + 384)); \
        asm volatile("cp.async.cg.shared.global [%0], [%1], 16;" :: "r"(sv), "l"(src + 768)); \
        _Pragma("unroll")                                                        \
        for (int j = 0; j < 4; j++) {                                            \
            const int cid = tid + j * 256;                                       \
            const int brw = cid >> 3, c8 = cid & 7;                              \
            const __half* bsrc = bhg + (size_t)(q0 + brw) * N_ + (kt) * 64 + c8 * 8; \
            uint32_t bdst = (uint32_t)__cvta_generic_to_shared(                  \
                &asm_[ATT_B(buf) + brw * 72 + c8 * 8]);                          \
            asm volatile("cp.async.cg.shared.global [%0], [%1], 16;" :: "r"(bdst), "l"(bsrc)); \
        }                                                                        \
        asm volatile("cp.async.commit_group;");                                  \
    }

    const int brow = ((lane >> 4) << 3) + (lane & 7);
    const int bcol = ((lane >> 3) & 1) * 8;

    uint32_t qa[2][4];
    const int br0 = q0 + w * 16 + lq;
    {
        const __half* qp  = qkv + qbase + (size_t)br0 * 1152 + h * 32;
        const __half* qp8 = qp + 8 * 1152;
        #pragma unroll
        for (int ks = 0; ks < 2; ks++) {
            const int c = ks * 16 + 2 * lr;
            qa[ks][0] = *(const uint32_t*)(qp  + c);
            qa[ks][1] = *(const uint32_t*)(qp8 + c);
            qa[ks][2] = *(const uint32_t*)(qp  + c + 8);
            qa[ks][3] = *(const uint32_t*)(qp8 + c + 8);
        }
    }

    float o[4][4] = {};
    float m0 = -1e30f, m1 = -1e30f, l0 = 0.0f, l1 = 0.0f;

    AISSUE(0, 0);
    for (int kt = 0; kt < 16; kt++) {
        asm volatile("cp.async.wait_group 0;");
        __syncthreads();
        if (kt < 15) AISSUE(kt + 1, (kt + 1) & 1);

        const int buf = kt & 1;

        float s[8][4];
        #pragma unroll
        for (int nf = 0; nf < 8; nf++)
            s[nf][0] = s[nf][1] = s[nf][2] = s[nf][3] = 0.0f;
        #pragma unroll
        for (int ks = 0; ks < 2; ks++) {
            const int c = ks * 16;
            uint32_t kf[8][2];
            #pragma unroll
            for (int np = 0; np < 4; np++) {
                uint32_t tmp[4];
                ldsm_x4(tmp, &asm_[ATT_K(buf) + (np * 16 + brow) * SMSH + c + bcol]);
                kf[np * 2][0] = tmp[0]; kf[np * 2][1] = tmp[1];
                kf[np * 2 + 1][0] = tmp[2]; kf[np * 2 + 1][1] = tmp[3];
            }
            #pragma unroll
            for (int nf = 0; nf < 8; nf++)
                mma_f16(s[nf], qa[ks], kf[nf]);
        }

        const __half* bs0 = &asm_[ATT_B(buf) + (w * 16 + lq) * 72];
        const __half* bs1 = bs0 + 8 * 72;
        float nm0 = m0, nm1 = m1;
        #pragma unroll
        for (int nf = 0; nf < 8; nf++) {
            const int col = nf * 8 + lr * 2;
            const float2 b0v = __half22float2(*(const __half2*)(bs0 + col));
            const float2 b1v = __half22float2(*(const __half2*)(bs1 + col));
            s[nf][0] += b0v.x; s[nf][1] += b0v.y;
            s[nf][2] += b1v.x; s[nf][3] += b1v.y;
            nm0 = fmaxf(nm0, fmaxf(s[nf][0], s[nf][1]));
            nm1 = fmaxf(nm1, fmaxf(s[nf][2], s[nf][3]));
        }
        nm0 = fmaxf(nm0, __shfl_xor_sync(0xffffffffu, nm0, 1));
        nm0 = fmaxf(nm0, __shfl_xor_sync(0xffffffffu, nm0, 2));
        nm1 = fmaxf(nm1, __shfl_xor_sync(0xffffffffu, nm1, 1));
        nm1 = fmaxf(nm1, __shfl_xor_sync(0xffffffffu, nm1, 2));

        const float c0 = __expf(m0 - nm0), c1 = __expf(m1 - nm1);
        m0 = nm0; m1 = nm1; l0 *= c0; l1 *= c1;
        #pragma unroll
        for (int nf = 0; nf < 4; nf++) {
            o[nf][0] *= c0; o[nf][1] *= c0;
            o[nf][2] *= c1; o[nf][3] *= c1;
        }

        uint32_t ph[8][2];
        float a0 = 0.0f, a1 = 0.0f;
        #pragma unroll
        for (int nf = 0; nf < 8; nf++) {
            const __half2 x01 = __floats2half2_rn((s[nf][0] - nm0) * LOG2E_,
                                                  (s[nf][1] - nm0) * LOG2E_);
            const __half2 x23 = __floats2half2_rn((s[nf][2] - nm1) * LOG2E_,
                                                  (s[nf][3] - nm1) * LOG2E_);
            const __half2 p01 = h2exp2(x01);
            const __half2 p23 = h2exp2(x23);
            const float2 f01 = __half22float2(p01);
            const float2 f23 = __half22float2(p23);
            a0 += f01.x + f01.y;
            a1 += f23.x + f23.y;
            ph[nf][0] = *(const uint32_t*)&p01;
            ph[nf][1] = *(const uint32_t*)&p23;
        }
        a0 += __shfl_xor_sync(0xffffffffu, a0, 1);
        a0 += __shfl_xor_sync(0xffffffffu, a0, 2);
        a1 += __shfl_xor_sync(0xffffffffu, a1, 1);
        a1 += __shfl_xor_sync(0xffffffffu, a1, 2);
        l0 += a0; l1 += a1;

        #pragma unroll
        for (int kf2 = 0; kf2 < 4; kf2++) {
            uint32_t pa[4];
            pa[0] = ph[2 * kf2][0];
            pa[1] = ph[2 * kf2][1];
            pa[2] = ph[2 * kf2 + 1][0];
            pa[3] = ph[2 * kf2 + 1][1];
            #pragma unroll
            for (int nf = 0; nf < 4; nf++) {
                uint32_t b0r, b1r;
                ldsm_x2_t(b0r, b1r,
                          &asm_[ATT_V(buf) + (kf2 * 16 + (lane & 15)) * SMSH + nf * 8]);
                uint32_t bfr[2] = { b0r, b1r };
                mma_f16(o[nf], pa, bfr);
            }
        }
    }
    #undef AISSUE

    const float inv0 = 1.0f / l0, inv1 = 1.0f / l1;
    #pragma unroll
    for (int nf = 0; nf < 4; nf++) {
        const int col = h * 32 + nf * 8 + lr * 2;
        __half* o0 = att + ((size_t)b * N_ + br0) * C_ + col;
        __half* o1 = att + ((size_t)b * N_ + br0 + 8) * C_ + col;
        *(__half2*)o0 = __floats2half2_rn(o[nf][0] * inv0, o[nf][1] * inv0);
        *(__half2*)o1 = __floats2half2_rn(o[nf][2] * inv1, o[nf][3] * inv1);
    }
}

// ---------------- launch ----------------
extern "C" void kernel_launch(void* const* d_in, const int* in_sizes, int n_in,
                              void* d_out, int out_size)
{
    const int base = (n_in >= 19) ? 2 : 0;
    const float* x         = (const float*)d_in[0];
    const int*   rel_index = (const int*)  d_in[1 + base];
    const float* ln1_g     = (const float*)d_in[2 + base];
    const float* ln1_b     = (const float*)d_in[3 + base];
    const float* w_qkv     = (const float*)d_in[4 + base];
    const float* w_proj    = (const float*)d_in[5 + base];
    const float* b_proj    = (const float*)d_in[6 + base];
    const float* rel_table = (const float*)d_in[7 + base];
    const float* gbias     = (const float*)d_in[8 + base];
    const float* ln2_g     = (const float*)d_in[9 + base];
    const float* ln2_b     = (const float*)d_in[10 + base];
    const float* w_pw1     = (const float*)d_in[11 + base];
    const float* b_pw1     = (const float*)d_in[12 + base];
    const float* w_dw      = (const float*)d_in[13 + base];
    const float* b_dw      = (const float*)d_in[14 + base];
    const float* w_pw2     = (const float*)d_in[15 + base];
    const float* b_pw2     = (const float*)d_in[16 + base];
    float* out = (float*)d_out;

    void *p_ln2, *p_h1, *p_h2, *p_x1, *p_ln1, *p_qkvh, *p_atth, *p_wh;
    cudaGetSymbolAddress(&p_ln2, g_ln2);
    cudaGetSymbolAddress(&p_h1,  g_h1);
    cudaGetSymbolAddress(&p_h2,  g_h2);
    cudaGetSymbolAddress(&p_x1,  g_x1);
    cudaGetSymbolAddress(&p_ln1, g_ln1);
    cudaGetSymbolAddress(&p_qkvh, g_qkvh);
    cudaGetSymbolAddress(&p_atth, g_atth);
    cudaGetSymbolAddress(&p_wh,  g_wh);
    __half* wh = (__half*)p_wh;

    static bool attr_done = false;
    if (!attr_done) {
        cudaFuncSetAttribute(mma_gemm_h<true, true, false, true, false>,
                             cudaFuncAttributeMaxDynamicSharedMemorySize, GEMM_SMEM);
        cudaFuncSetAttribute(mma_gemm_h<false, true, true, false, false>,
                             cudaFuncAttributeMaxDynamicSharedMemorySize, GEMM_SMEM);
        cudaFuncSetAttribute(mma_gemm_h<false, false, false, true, true>,
                             cudaFuncAttributeMaxDynamicSharedMemorySize, GEMM_SMEM);
        cudaFuncSetAttribute(attn_mma_kernel,
                             cudaFuncAttributeMaxDynamicSharedMemorySize, ATT_SMEM);
        attr_done = true;
    }

    w2h_all_kernel<<<(Q_END + 255) / 256, 256>>>(w_qkv, w_pw1, w_pw2, w_proj, wh);
    bias2_kernel<<<N_, 256>>>(rel_index, rel_table, gbias);

    // 1) x1 = x + MLP(LN2(x))
    ln_kernel<<<M_, 128>>>(x, ln2_g, ln2_b, (__half*)p_ln2);
    mma_gemm_h<true, true, false, true, false><<<dim3(HID_ / 128, M_ / 128), 256, GEMM_SMEM>>>(
        (const __half*)p_ln2, wh + OFF_PW1, b_pw1, nullptr, p_h1, M_, HID_, C_);
    dwconv_kernel<<<dim3(N_, B_), 384>>>(
        (const __half*)p_h1, (__half*)p_h2, w_dw, b_dw);
    mma_gemm_h<false, true, true, false, false><<<dim3(C_ / 128, M_ / 128), 256, GEMM_SMEM>>>(
        (const __half*)p_h2, wh + OFF_PW2, b_pw2, x, p_x1, M_, C_, HID_);

    // 2) out = x1 + Attn(LN1(x1))
    ln_kernel<<<M_, 128>>>((const float*)p_x1, ln1_g, ln1_b, (__half*)p_ln1);
    mma_gemm_h<false, false, false, true, true><<<dim3(1152 / 128, M_ / 128), 256, GEMM_SMEM>>>(
        (const __half*)p_ln1, wh + OFF_QKV, nullptr, nullptr, p_qkvh, M_, 1152, C_);
    attn_mma_kernel<<<dim3(N_ / 128, H_, B_), 256, ATT_SMEM>>>(
        (const __half*)p_qkvh, (__half*)p_atth);
    mma_gemm_h<false, true, true, false, false><<<dim3(C_ / 128, M_ / 128), 256, GEMM_SMEM>>>(
        (const __half*)p_atth, wh + OFF_PROJ, b_proj, (const float*)p_x1, out, M_, C_, C_);
}

// round 13
// speedup vs baseline: 5.9492x; 1.0146x over previous
#include <cuda_runtime.h>
#include <cuda_fp16.h>
#include <math.h>
#include <stdint.h>

// Problem constants
#define B_  8
#define N_  1024
#define C_  384
#define H_  12
#define HD_ 32
#define HID_ 768
#define M_  (B_ * N_)
#define NREL_ 3969
#define SCALE_ 0.17677669529663687f
#define LOG2E_ 1.4426950408889634f

// NOTE: harness PTX target is sm_103 (no 'a') -> tcgen05.* unavailable.

__device__ __forceinline__ float gelu_f(float v) {
    return 0.5f * v * (1.0f + erff(v * 0.70710678118654752f));
}

__device__ __forceinline__ void mma_f16(float* c, const uint32_t* a, const uint32_t* b) {
    asm volatile(
        "mma.sync.aligned.m16n8k16.row.col.f32.f16.f16.f32 "
        "{%0,%1,%2,%3}, {%4,%5,%6,%7}, {%8,%9}, {%0,%1,%2,%3};"
        : "+f"(c[0]), "+f"(c[1]), "+f"(c[2]), "+f"(c[3])
        : "r"(a[0]), "r"(a[1]), "r"(a[2]), "r"(a[3]), "r"(b[0]), "r"(b[1]));
}

__device__ __forceinline__ void ldsm_x4(uint32_t* r, const __half* p) {
    uint32_t addr = (uint32_t)__cvta_generic_to_shared(p);
    asm volatile("ldmatrix.sync.aligned.m8n8.x4.shared.b16 {%0,%1,%2,%3}, [%4];"
                 : "=r"(r[0]), "=r"(r[1]), "=r"(r[2]), "=r"(r[3]) : "r"(addr));
}

__device__ __forceinline__ void ldsm_x2_t(uint32_t& r0, uint32_t& r1, const __half* p) {
    uint32_t addr = (uint32_t)__cvta_generic_to_shared(p);
    asm volatile("ldmatrix.sync.aligned.m8n8.x2.trans.shared.b16 {%0,%1}, [%2];"
                 : "=r"(r0), "=r"(r1) : "r"(addr));
}

// ---------------- scratch ----------------
__device__ __align__(16) __half g_ln2[M_ * C_];
__device__ __align__(16) __half g_h1 [M_ * HID_];
__device__ __align__(16) __half g_h2 [M_ * HID_];
__device__ float g_x1 [M_ * C_];
__device__ __align__(16) __half g_ln1[M_ * C_];
__device__ __align__(16) __half g_qkvh[M_ * 3 * C_];
__device__ __align__(16) __half g_atth[M_ * C_];
__device__ __align__(16) __half g_biash[H_ * N_ * N_];
__device__ __align__(16) __half g_wh[1179648];
#define OFF_QKV  0
#define OFF_PW1  442368
#define OFF_PW2  737280
#define OFF_PROJ 1032192
#define Q_QKV  110592
#define Q_PW1  184320
#define Q_PW2  258048
#define Q_END  294912

// ---------------- merged weight fp32 -> fp16 ----------------
__global__ __launch_bounds__(256) void w2h_all_kernel(
    const float* __restrict__ s_qkv, const float* __restrict__ s_pw1,
    const float* __restrict__ s_pw2, const float* __restrict__ s_proj,
    __half* __restrict__ dst)
{
    const int i = blockIdx.x * 256 + threadIdx.x;
    if (i >= Q_END) return;
    const float* src; int local;
    if (i < Q_QKV)      { src = s_qkv;  local = i; }
    else if (i < Q_PW1) { src = s_pw1;  local = i - Q_QKV; }
    else if (i < Q_PW2) { src = s_pw2;  local = i - Q_PW1; }
    else                { src = s_proj; local = i - Q_PW2; }
    const float4 v = ((const float4*)src)[local];
    __half2 h0 = __floats2half2_rn(v.x, v.y);
    __half2 h1 = __floats2half2_rn(v.z, v.w);
    uint2 u; u.x = *(uint32_t*)&h0; u.y = *(uint32_t*)&h1;
    *(uint2*)(dst + (size_t)i * 4) = u;
}

// ---------------- LayerNorm: warp-per-row, shfl-only --------------------------
__global__ __launch_bounds__(256) void ln_kernel(
    const float* __restrict__ in, const float* __restrict__ g,
    const float* __restrict__ bta, __half* __restrict__ out)
{
    const int lane = threadIdx.x & 31;
    const int row  = blockIdx.x * 8 + (threadIdx.x >> 5);
    const float4* xr = (const float4*)(in + (size_t)row * C_);
    const float4 a = xr[lane], b = xr[lane + 32], c = xr[lane + 64];

    float s = (a.x + a.y) + (a.z + a.w) + (b.x + b.y) + (b.z + b.w)
            + (c.x + c.y) + (c.z + c.w);
    #pragma unroll
    for (int o = 16; o; o >>= 1) s += __shfl_xor_sync(0xffffffffu, s, o);
    const float mean = s * (1.0f / C_);

    const float dx[12] = { a.x - mean, a.y - mean, a.z - mean, a.w - mean,
                           b.x - mean, b.y - mean, b.z - mean, b.w - mean,
                           c.x - mean, c.y - mean, c.z - mean, c.w - mean };
    float q = 0.0f;
    #pragma unroll
    for (int i = 0; i < 12; i++) q += dx[i] * dx[i];
    #pragma unroll
    for (int o = 16; o; o >>= 1) q += __shfl_xor_sync(0xffffffffu, q, o);
    const float inv = rsqrtf(q * (1.0f / C_) + 1e-5f);

    const float4* g4 = (const float4*)g;
    const float4* t4 = (const float4*)bta;
    __half* orow = out + (size_t)row * C_;
    #pragma unroll
    for (int seg = 0; seg < 3; seg++) {
        const float4 gv = g4[lane + seg * 32];
        const float4 tv = t4[lane + seg * 32];
        const float* d = &dx[seg * 4];
        __half2 h0 = __floats2half2_rn(d[0] * inv * gv.x + tv.x,
                                       d[1] * inv * gv.y + tv.y);
        __half2 h1 = __floats2half2_rn(d[2] * inv * gv.z + tv.z,
                                       d[3] * inv * gv.w + tv.w);
        uint2 u; u.x = *(uint32_t*)&h0; u.y = *(uint32_t*)&h1;
        *(uint2*)(orow + lane * 4 + seg * 128) = u;
    }
}

// ---------------- fp16 GEMM: 4-stage cp.async, 1 barrier/iter ---------------
#define SMSH 40
#define GEMM_SMEM (4 * 128 * SMSH * 2 * 2)   // 81920 bytes
template<bool GELU, bool HASB, bool RES, bool OUTH, bool QSC>
__global__ __launch_bounds__(256, 2) void mma_gemm_h(
    const __half* __restrict__ A, const __half* __restrict__ W,
    const float* __restrict__ bias, const float* __restrict__ res,
    void* __restrict__ Cv, int M, int Nd, int K)
{
    extern __shared__ __half dsm[];
    __half* Asb = dsm;
    __half* Bsb = dsm + 4 * 128 * SMSH;
    const int tid  = threadIdx.x;
    const int lane = tid & 31, warp = tid >> 5;
    const int wm = warp >> 2, wn = warp & 3;
    const int lq = lane >> 2, lr = lane & 3;
    const int bm = blockIdx.y * 128, bn = blockIdx.x * 128;
    const int ntiles = K >> 5;

    const int lrow0 = tid >> 2, lc8 = (tid & 3) * 8;
    const int lrow1 = (tid + 256) >> 2;

    const int arow = ((lane >> 3) & 1) * 8 + (lane & 7);
    const int acol = (lane >> 4) * 8;
    const int brow = ((lane >> 4) << 3) + (lane & 7);
    const int bcol = ((lane >> 3) & 1) * 8;

    #define ISSUE(kt, buf)                                                       \
    {                                                                            \
        __half* asb = Asb + (buf) * 128 * SMSH;                                  \
        __half* bsb = Bsb + (buf) * 128 * SMSH;                                  \
        const __half* ag0 = A + (size_t)(bm + lrow0) * K + (kt) * 32 + lc8;      \
        const __half* wg0 = W + (size_t)(bn + lrow0) * K + (kt) * 32 + lc8;      \
        const __half* ag1 = A + (size_t)(bm + lrow1) * K + (kt) * 32 + lc8;      \
        const __half* wg1 = W + (size_t)(bn + lrow1) * K + (kt) * 32 + lc8;      \
        uint32_t sa0 = (uint32_t)__cvta_generic_to_shared(&asb[lrow0 * SMSH + lc8]); \
        uint32_t sb0 = (uint32_t)__cvta_generic_to_shared(&bsb[lrow0 * SMSH + lc8]); \
        uint32_t sa1 = (uint32_t)__cvta_generic_to_shared(&asb[lrow1 * SMSH + lc8]); \
        uint32_t sb1 = (uint32_t)__cvta_generic_to_shared(&bsb[lrow1 * SMSH + lc8]); \
        asm volatile("cp.async.cg.shared.global [%0], [%1], 16;" :: "r"(sa0), "l"(ag0)); \
        asm volatile("cp.async.cg.shared.global [%0], [%1], 16;" :: "r"(sb0), "l"(wg0)); \
        asm volatile("cp.async.cg.shared.global [%0], [%1], 16;" :: "r"(sa1), "l"(ag1)); \
        asm volatile("cp.async.cg.shared.global [%0], [%1], 16;" :: "r"(sb1), "l"(wg1)); \
        asm volatile("cp.async.commit_group;");                                  \
    }

    float acc[4][4][4] = {};
    ISSUE(0, 0);
    if (ntiles > 1) ISSUE(1, 1);
    if (ntiles > 2) ISSUE(2, 2);

    for (int kt = 0; kt < ntiles; kt++) {
        if (kt + 2 < ntiles)      asm volatile("cp.async.wait_group 2;");
        else if (kt + 1 < ntiles) asm volatile("cp.async.wait_group 1;");
        else                      asm volatile("cp.async.wait_group 0;");
        __syncthreads();
        if (kt + 3 < ntiles) ISSUE(kt + 3, (kt + 3) & 3);

        const __half* as = Asb + (kt & 3) * 128 * SMSH;
        const __half* bs = Bsb + (kt & 3) * 128 * SMSH;
        #pragma unroll
        for (int ks = 0; ks < 2; ks++) {
            const int c = ks * 16;
            uint32_t af[4][4], bf[4][2];
            #pragma unroll
            for (int mt = 0; mt < 4; mt++)
                ldsm_x4(af[mt], &as[(wm * 64 + mt * 16 + arow) * SMSH + c + acol]);
            #pragma unroll
            for (int np = 0; np < 2; np++) {
                uint32_t tmp[4];
                ldsm_x4(tmp, &bs[(wn * 32 + np * 16 + brow) * SMSH + c + bcol]);
                bf[np * 2][0] = tmp[0]; bf[np * 2][1] = tmp[1];
                bf[np * 2 + 1][0] = tmp[2]; bf[np * 2 + 1][1] = tmp[3];
            }
            #pragma unroll
            for (int mt = 0; mt < 4; mt++)
                #pragma unroll
                for (int nt = 0; nt < 4; nt++)
                    mma_f16(acc[mt][nt], af[mt], bf[nt]);
        }
    }
    #undef ISSUE

    #pragma unroll
    for (int mt = 0; mt < 4; mt++) {
        #pragma unroll
        for (int nt = 0; nt < 4; nt++) {
            const int row = bm + wm * 64 + mt * 16 + lq;
            const int col = bn + wn * 32 + nt * 8 + lr * 2;
            #pragma unroll
            for (int half = 0; half < 2; half++) {
                const int r = row + half * 8;
                float v0 = acc[mt][nt][half * 2 + 0];
                float v1 = acc[mt][nt][half * 2 + 1];
                if (HASB) { v0 += bias[col]; v1 += bias[col + 1]; }
                if (GELU) { v0 = gelu_f(v0); v1 = gelu_f(v1); }
                if (RES) {
                    const float* Rr = res + (size_t)r * Nd + col;
                    v0 += Rr[0]; v1 += Rr[1];
                }
                if (OUTH) {
                    if (QSC && col < 384) { v0 *= SCALE_; v1 *= SCALE_; }
                    __half2 hv = __floats2half2_rn(v0, v1);
                    *(__half2*)((__half*)Cv + (size_t)r * Nd + col) = hv;
                } else {
                    *(float2*)((float*)Cv + (size_t)r * Nd + col) = make_float2(v0, v1);
                }
            }
        }
    }
}

// ---------------- dwconv + fused bias-precompute (extra gridDim.y slice) ----
// Blocks with blockIdx.y < B_: depthwise 3x3 dil-2 conv + GELU (unchanged).
// Blocks with blockIdx.y == B_: bias precompute for q = blockIdx.x (runs
// concurrently; its output is consumed only by attn, launched later).
__global__ __launch_bounds__(384) void dwconv_bias_kernel(
    const __half* __restrict__ h1, __half* __restrict__ h2,
    const float* __restrict__ w, const float* __restrict__ bias,
    const int* __restrict__ rel_index, const float* __restrict__ rel_table,
    const float* __restrict__ gb)
{
    const int n = blockIdx.x;
    const int b = blockIdx.y;

    if (b == B_) {
        // bias plane: one q row, all 12 heads; rel_index/gb read once
        const size_t rowi = (size_t)n * N_;
        for (int e = threadIdx.x; e < 512; e += 384) {
            const int k = e * 2;
            const int2 ri = *(const int2*)(rel_index + rowi + k);
            const float2 g2 = *(const float2*)(gb + rowi + k);
            const float* t0 = rel_table + ri.x * H_;
            const float* t1 = rel_table + ri.y * H_;
            #pragma unroll
            for (int h = 0; h < H_; h++) {
                const __half2 v = __floats2half2_rn(t0[h] + g2.x, t1[h] + g2.y);
                *(__half2*)(g_biash + (size_t)h * (N_ * N_) + rowi + k) = v;
            }
        }
        return;
    }

    const int y = n >> 5, x = n & 31;
    const size_t base = (size_t)b * N_ * HID_;
    const int c0 = threadIdx.x * 2;

    float2 acc = make_float2(bias[c0], bias[c0 + 1]);
    const float* w0 = w + c0 * 9;
    const float* w1 = w + (c0 + 1) * 9;

    #pragma unroll
    for (int i = 0; i < 3; i++) {
        const int yy = y + 2 * i - 2;
        if (yy < 0 || yy > 31) continue;
        #pragma unroll
        for (int j = 0; j < 3; j++) {
            const int xx = x + 2 * j - 2;
            if (xx < 0 || xx > 31) continue;
            const float2 v = __half22float2(
                *(const __half2*)(h1 + base + (size_t)(yy * 32 + xx) * HID_ + c0));
            acc.x += w0[i * 3 + j] * v.x;
            acc.y += w1[i * 3 + j] * v.y;
        }
    }
    *(__half2*)(h2 + base + (size_t)n * HID_ + c0) =
        __floats2half2_rn(gelu_f(acc.x), gelu_f(acc.y));
}

// ---------------- fp16 flash attention: smem-staged bias --------------------
#define SMSH 40
#define ATT_K(buf)  ((buf) * 64 * SMSH)
#define ATT_V(buf)  (2 * 64 * SMSH + (buf) * 64 * SMSH)
#define ATT_B(buf)  (4 * 64 * SMSH + (buf) * 128 * 72)
#define ATT_SMEM  ((4 * 64 * SMSH + 2 * 128 * 72) * 2)   // 57344 bytes
__global__ __launch_bounds__(256) void attn_mma_kernel(
    const __half* __restrict__ qkv, __half* __restrict__ att)
{
    extern __shared__ __half asm_[];
    const int q0 = blockIdx.x * 128;
    const int h  = blockIdx.y;
    const int b  = blockIdx.z;
    const int tid = threadIdx.x;
    const int lane = tid & 31, w = tid >> 5;
    const int lq = lane >> 2;
    const int lr = lane & 3;

    const size_t qbase = (size_t)b * N_ * 1152;
    const int kl = tid >> 2, d8 = (tid & 3) * 8;
    const __half* bhg = g_biash + (size_t)h * N_ * N_;

    #define AISSUE(kt, buf)                                                      \
    {                                                                            \
        const __half* src = qkv + qbase + (size_t)((kt) * 64 + kl) * 1152 + h * 32 + d8; \
        uint32_t sk = (uint32_t)__cvta_generic_to_shared(&asm_[ATT_K(buf) + kl * SMSH + d8]); \
        uint32_t sv = (uint32_t)__cvta_generic_to_shared(&asm_[ATT_V(buf) + kl * SMSH + d8]); \
        asm volatile("cp.async.cg.shared.global [%0], [%1], 16;" :: "r"(sk), "l"(src + 384)); \
        asm volatile("cp.async.cg.shared.global [%0], [%1], 16;" :: "r"(sv), "l"(src + 768)); \
        _Pragma("unroll")                                                        \
        for (int j = 0; j < 4; j++) {                                            \
            const int cid = tid + j * 256;                                       \
            const int brw = cid >> 3, c8 = cid & 7;                              \
            const __half* bsrc = bhg + (size_t)(q0 + brw) * N_ + (kt) * 64 + c8 * 8; \
            uint32_t bdst = (uint32_t)__cvta_generic_to_shared(                  \
                &asm_[ATT_B(buf) + brw * 72 + c8 * 8]);                          \
            asm volatile("cp.async.cg.shared.global [%0], [%1], 16;" :: "r"(bdst), "l"(bsrc)); \
        }                                                                        \
        asm volatile("cp.async.commit_group;");                                  \
    }

    const int brow = ((lane >> 4) << 3) + (lane & 7);
    const int bcol = ((lane >> 3) & 1) * 8;

    uint32_t qa[2][4];
    const int br0 = q0 + w * 16 + lq;
    {
        const __half* qp  = qkv + qbase + (size_t)br0 * 1152 + h * 32;
        const __half* qp8 = qp + 8 * 1152;
        #pragma unroll
        for (int ks = 0; ks < 2; ks++) {
            const int c = ks * 16 + 2 * lr;
            qa[ks][0] = *(const uint32_t*)(qp  + c);
            qa[ks][1] = *(const uint32_t*)(qp8 + c);
            qa[ks][2] = *(const uint32_t*)(qp  + c + 8);
            qa[ks][3] = *(const uint32_t*)(qp8 + c + 8);
        }
    }

    float o[4][4] = {};
    float m0 = -1e30f, m1 = -1e30f, l0 = 0.0f, l1 = 0.0f;

    AISSUE(0, 0);
    for (int kt = 0; kt < 16; kt++) {
        asm volatile("cp.async.wait_group 0;");
        __syncthreads();
        if (kt < 15) AISSUE(kt + 1, (kt + 1) & 1);

        const int buf = kt & 1;

        float s[8][4];
        #pragma unroll
        for (int nf = 0; nf < 8; nf++)
            s[nf][0] = s[nf][1] = s[nf][2] = s[nf][3] = 0.0f;
        #pragma unroll
        for (int ks = 0; ks < 2; ks++) {
            const int c = ks * 16;
            uint32_t kf[8][2];
            #pragma unroll
            for (int np = 0; np < 4; np++) {
                uint32_t tmp[4];
                ldsm_x4(tmp, &asm_[ATT_K(buf) + (np * 16 + brow) * SMSH + c + bcol]);
                kf[np * 2][0] = tmp[0]; kf[np * 2][1] = tmp[1];
                kf[np * 2 + 1][0] = tmp[2]; kf[np * 2 + 1][1] = tmp[3];
            }
            #pragma unroll
            for (int nf = 0; nf < 8; nf++)
                mma_f16(s[nf], qa[ks], kf[nf]);
        }

        const __half* bs0 = &asm_[ATT_B(buf) + (w * 16 + lq) * 72];
        const __half* bs1 = bs0 + 8 * 72;
        float nm0 = m0, nm1 = m1;
        #pragma unroll
        for (int nf = 0; nf < 8; nf++) {
            const int col = nf * 8 + lr * 2;
            const float2 b0v = __half22float2(*(const __half2*)(bs0 + col));
            const float2 b1v = __half22float2(*(const __half2*)(bs1 + col));
            s[nf][0] += b0v.x; s[nf][1] += b0v.y;
            s[nf][2] += b1v.x; s[nf][3] += b1v.y;
            nm0 = fmaxf(nm0, fmaxf(s[nf][0], s[nf][1]));
            nm1 = fmaxf(nm1, fmaxf(s[nf][2], s[nf][3]));
        }
        nm0 = fmaxf(nm0, __shfl_xor_sync(0xffffffffu, nm0, 1));
        nm0 = fmaxf(nm0, __shfl_xor_sync(0xffffffffu, nm0, 2));
        nm1 = fmaxf(nm1, __shfl_xor_sync(0xffffffffu, nm1, 1));
        nm1 = fmaxf(nm1, __shfl_xor_sync(0xffffffffu, nm1, 2));

        const float c0 = __expf(m0 - nm0), c1 = __expf(m1 - nm1);
        m0 = nm0; m1 = nm1; l0 *= c0; l1 *= c1;
        #pragma unroll
        for (int nf = 0; nf < 4; nf++) {
            o[nf][0] *= c0; o[nf][1] *= c0;
            o[nf][2] *= c1; o[nf][3] *= c1;
        }

        uint32_t ph[8][2];
        float a0 = 0.0f, a1 = 0.0f;
        #pragma unroll
        for (int nf = 0; nf < 8; nf++) {
            const __half2 x01 = __floats2half2_rn((s[nf][0] - nm0) * LOG2E_,
                                                  (s[nf][1] - nm0) * LOG2E_);
            const __half2 x23 = __floats2half2_rn((s[nf][2] - nm1) * LOG2E_,
                                                  (s[nf][3] - nm1) * LOG2E_);
            const __half2 p01 = h2exp2(x01);
            const __half2 p23 = h2exp2(x23);
            const float2 f01 = __half22float2(p01);
            const float2 f23 = __half22float2(p23);
            a0 += f01.x + f01.y;
            a1 += f23.x + f23.y;
            ph[nf][0] = *(const uint32_t*)&p01;
            ph[nf][1] = *(const uint32_t*)&p23;
        }
        a0 += __shfl_xor_sync(0xffffffffu, a0, 1);
        a0 += __shfl_xor_sync(0xffffffffu, a0, 2);
        a1 += __shfl_xor_sync(0xffffffffu, a1, 1);
        a1 += __shfl_xor_sync(0xffffffffu, a1, 2);
        l0 += a0; l1 += a1;

        #pragma unroll
        for (int kf2 = 0; kf2 < 4; kf2++) {
            uint32_t pa[4];
            pa[0] = ph[2 * kf2][0];
            pa[1] = ph[2 * kf2][1];
            pa[2] = ph[2 * kf2 + 1][0];
            pa[3] = ph[2 * kf2 + 1][1];
            #pragma unroll
            for (int nf = 0; nf < 4; nf++) {
                uint32_t b0r, b1r;
                ldsm_x2_t(b0r, b1r,
                          &asm_[ATT_V(buf) + (kf2 * 16 + (lane & 15)) * SMSH + nf * 8]);
                uint32_t bfr[2] = { b0r, b1r };
                mma_f16(o[nf], pa, bfr);
            }
        }
    }
    #undef AISSUE

    const float inv0 = 1.0f / l0, inv1 = 1.0f / l1;
    #pragma unroll
    for (int nf = 0; nf < 4; nf++) {
        const int col = h * 32 + nf * 8 + lr * 2;
        __half* o0 = att + ((size_t)b * N_ + br0) * C_ + col;
        __half* o1 = att + ((size_t)b * N_ + br0 + 8) * C_ + col;
        *(__half2*)o0 = __floats2half2_rn(o[nf][0] * inv0, o[nf][1] * inv0);
        *(__half2*)o1 = __floats2half2_rn(o[nf][2] * inv1, o[nf][3] * inv1);
    }
}

// ---------------- launch ----------------
extern "C" void kernel_launch(void* const* d_in, const int* in_sizes, int n_in,
                              void* d_out, int out_size)
{
    const int base = (n_in >= 19) ? 2 : 0;
    const float* x         = (const float*)d_in[0];
    const int*   rel_index = (const int*)  d_in[1 + base];
    const float* ln1_g     = (const float*)d_in[2 + base];
    const float* ln1_b     = (const float*)d_in[3 + base];
    const float* w_qkv     = (const float*)d_in[4 + base];
    const float* w_proj    = (const float*)d_in[5 + base];
    const float* b_proj    = (const float*)d_in[6 + base];
    const float* rel_table = (const float*)d_in[7 + base];
    const float* gbias     = (const float*)d_in[8 + base];
    const float* ln2_g     = (const float*)d_in[9 + base];
    const float* ln2_b     = (const float*)d_in[10 + base];
    const float* w_pw1     = (const float*)d_in[11 + base];
    const float* b_pw1     = (const float*)d_in[12 + base];
    const float* w_dw      = (const float*)d_in[13 + base];
    const float* b_dw      = (const float*)d_in[14 + base];
    const float* w_pw2     = (const float*)d_in[15 + base];
    const float* b_pw2     = (const float*)d_in[16 + base];
    float* out = (float*)d_out;

    void *p_ln2, *p_h1, *p_h2, *p_x1, *p_ln1, *p_qkvh, *p_atth, *p_wh;
    cudaGetSymbolAddress(&p_ln2, g_ln2);
    cudaGetSymbolAddress(&p_h1,  g_h1);
    cudaGetSymbolAddress(&p_h2,  g_h2);
    cudaGetSymbolAddress(&p_x1,  g_x1);
    cudaGetSymbolAddress(&p_ln1, g_ln1);
    cudaGetSymbolAddress(&p_qkvh, g_qkvh);
    cudaGetSymbolAddress(&p_atth, g_atth);
    cudaGetSymbolAddress(&p_wh,  g_wh);
    __half* wh = (__half*)p_wh;

    static bool attr_done = false;
    if (!attr_done) {
        cudaFuncSetAttribute(mma_gemm_h<true, true, false, true, false>,
                             cudaFuncAttributeMaxDynamicSharedMemorySize, GEMM_SMEM);
        cudaFuncSetAttribute(mma_gemm_h<false, true, true, false, false>,
                             cudaFuncAttributeMaxDynamicSharedMemorySize, GEMM_SMEM);
        cudaFuncSetAttribute(mma_gemm_h<false, false, false, true, true>,
                             cudaFuncAttributeMaxDynamicSharedMemorySize, GEMM_SMEM);
        cudaFuncSetAttribute(attn_mma_kernel,
                             cudaFuncAttributeMaxDynamicSharedMemorySize, ATT_SMEM);
        attr_done = true;
    }

    w2h_all_kernel<<<(Q_END + 255) / 256, 256>>>(w_qkv, w_pw1, w_pw2, w_proj, wh);

    // 1) x1 = x + MLP(LN2(x))   (bias precompute rides in the dwconv grid)
    ln_kernel<<<M_ / 8, 256>>>(x, ln2_g, ln2_b, (__half*)p_ln2);
    mma_gemm_h<true, true, false, true, false><<<dim3(HID_ / 128, M_ / 128), 256, GEMM_SMEM>>>(
        (const __half*)p_ln2, wh + OFF_PW1, b_pw1, nullptr, p_h1, M_, HID_, C_);
    dwconv_bias_kernel<<<dim3(N_, B_ + 1), 384>>>(
        (const __half*)p_h1, (__half*)p_h2, w_dw, b_dw,
        rel_index, rel_table, gbias);
    mma_gemm_h<false, true, true, false, false><<<dim3(C_ / 128, M_ / 128), 256, GEMM_SMEM>>>(
        (const __half*)p_h2, wh + OFF_PW2, b_pw2, x, p_x1, M_, C_, HID_);

    // 2) out = x1 + Attn(LN1(x1))
    ln_kernel<<<M_ / 8, 256>>>((const float*)p_x1, ln1_g, ln1_b, (__half*)p_ln1);
    mma_gemm_h<false, false, false, true, true><<<dim3(1152 / 128, M_ / 128), 256, GEMM_SMEM>>>(
        (const __half*)p_ln1, wh + OFF_QKV, nullptr, nullptr, p_qkvh, M_, 1152, C_);
    attn_mma_kernel<<<dim3(N_ / 128, H_, B_), 256, ATT_SMEM>>>(
        (const __half*)p_qkvh, (__half*)p_atth);
    mma_gemm_h<false, true, true, false, false><<<dim3(C_ / 128, M_ / 128), 256, GEMM_SMEM>>>(
        (const __half*)p_atth, wh + OFF_PROJ, b_proj, (const float*)p_x1, out, M_, C_, C_);
}